// round 1
// baseline (speedup 1.0000x reference)
#include <cuda_runtime.h>
#include <cuda_bf16.h>
#include <math.h>

// Problem constants
#define BB   4
#define SS   2048
#define DD   1024
#define HH   16
#define DKK  64
#define FFN  4096
#define NTOK (BB*SS)            // 8192 rows
#define NELT (NTOK*DD)          // 8,388,608
#define ASZ  ((long long)BB*HH*SS*SS) // 268,435,456

// GEMM tile config
#define BM 128
#define BN 128
#define BK 8

// ---------------- scratch (device globals; no allocations allowed) ----------------
__device__ float g_h  [NELT];
__device__ float g_Q  [NELT];
__device__ float g_K  [NELT];
__device__ float g_V  [NELT];
__device__ float g_Qg [NELT];
__device__ float g_ctx[NELT];
__device__ float g_x1 [NELT];
__device__ float g_h2 [NELT];
__device__ float g_x2 [NELT];
__device__ float g_t1 [NTOK*2*DD];
__device__ float g_ff1[NTOK*FFN];
__device__ float g_cwgt[NTOK];
__device__ float g_attn_fb[(size_t)ASZ];   // fallback if out lacks attn region

// ---------------- helpers ----------------
__device__ __forceinline__ float geluf(float x) {
    return 0.5f * x * (1.0f + erff(x * 0.70710678118654752f));
}

__device__ __forceinline__ float brsum(float v, float* sh) {
    int t = threadIdx.x;
    sh[t] = v; __syncthreads();
    #pragma unroll
    for (int s = 128; s > 0; s >>= 1) { if (t < s) sh[t] += sh[t + s]; __syncthreads(); }
    float r = sh[0]; __syncthreads();
    return r;
}
__device__ __forceinline__ float brmax(float v, float* sh) {
    int t = threadIdx.x;
    sh[t] = v; __syncthreads();
    #pragma unroll
    for (int s = 128; s > 0; s >>= 1) { if (t < s) sh[t] = fmaxf(sh[t], sh[t + s]); __syncthreads(); }
    float r = sh[0]; __syncthreads();
    return r;
}

// ---------------- layernorm (one block per row of D=1024) ----------------
__global__ void __launch_bounds__(256) ln_kernel(
    const float* __restrict__ x, float* __restrict__ y,
    const float* __restrict__ g, const float* __restrict__ b,
    float* __restrict__ cwgt, const float* __restrict__ alpha_ptr)
{
    long long base = (long long)blockIdx.x * DD;
    int t = threadIdx.x;
    __shared__ float sh[256];
    float xv[4];
    float s = 0.f;
    #pragma unroll
    for (int i = 0; i < 4; i++) { xv[i] = x[base + t + i*256]; s += xv[i]; }
    s = brsum(s, sh);
    float mu = s * (1.0f / DD);
    float vs = 0.f;
    #pragma unroll
    for (int i = 0; i < 4; i++) { float d = xv[i] - mu; vs += d * d; }
    vs = brsum(vs, sh);
    float inv = rsqrtf(vs * (1.0f / DD) + 1e-5f);
    float ss = 0.f;
    #pragma unroll
    for (int i = 0; i < 4; i++) {
        int c = t + i*256;
        float yv = (xv[i] - mu) * inv * g[c] + b[c];
        y[base + c] = yv;
        ss += yv * yv;
    }
    if (cwgt) {
        ss = brsum(ss, sh);
        if (t == 0) cwgt[blockIdx.x] = expf(-alpha_ptr[0] * sqrtf(ss));
    }
}

// ---------------- gauge-modified query: Qg = Q*cos(ph[h]) - V*sin(ph[h]) ----------------
__global__ void __launch_bounds__(256) qg_kernel(
    const float* __restrict__ Q, const float* __restrict__ V,
    const float* __restrict__ phase, float* __restrict__ Qg)
{
    int i = blockIdx.x * 256 + threadIdx.x;
    if (i >= NELT) return;
    int h = (i & (DD - 1)) >> 6;     // (i % 1024) / 64
    float p = phase[h];
    Qg[i] = Q[i] * cosf(p) - V[i] * sinf(p);
}

// ---------------- softmax over rows of length 2048 (in place) ----------------
__global__ void __launch_bounds__(256) softmax_kernel(float* __restrict__ attn)
{
    float* r = attn + (long long)blockIdx.x * SS;
    int t = threadIdx.x;
    __shared__ float sh[256];
    float v[8];
    float mx = -3.4e38f;
    #pragma unroll
    for (int i = 0; i < 8; i++) { v[i] = r[t + i*256]; mx = fmaxf(mx, v[i]); }
    mx = brmax(mx, sh);
    float s = 0.f;
    #pragma unroll
    for (int i = 0; i < 8; i++) { v[i] = expf(v[i] - mx); s += v[i]; }
    s = brsum(s, sh);
    float inv = 1.0f / s;
    #pragma unroll
    for (int i = 0; i < 8; i++) r[t + i*256] = v[i] * inv;
}

// ---------------- generic tiled fp32 GEMM with fused epilogues ----------------
// mode: 0 = scale*acc    1 = acc     2 = gelu(acc+bias)
//       3 = res + acc (+bias)        4 = res + beta*h2 + cwgt[m]*(acc+bias)
__global__ void __launch_bounds__(256) gemm_kernel(
    const float* __restrict__ A, const float* __restrict__ B, float* __restrict__ C,
    int M, int N, int K, int lda, int ldb, int ldc,
    int batchH, long long sAb, long long sAh, long long sBb, long long sBh,
    long long sCb, long long sCh,
    float scale, const float* __restrict__ bias, const float* __restrict__ res,
    const float* __restrict__ h2p, const float* __restrict__ cwgt,
    const float* __restrict__ beta_ptr, int mode, int transB)
{
    __shared__ float As[BK][BM];
    __shared__ float Bs[BK][BN];

    int z = blockIdx.z;
    int zb = z / batchH, zh = z - zb * batchH;
    A += (long long)zb * sAb + (long long)zh * sAh;
    B += (long long)zb * sBb + (long long)zh * sBh;
    C += (long long)zb * sCb + (long long)zh * sCh;

    int tid = threadIdx.x;
    int m0 = blockIdx.y * BM, n0 = blockIdx.x * BN;
    int ty = tid >> 4, tx = tid & 15;

    float acc[8][8];
    #pragma unroll
    for (int i = 0; i < 8; i++)
        #pragma unroll
        for (int j = 0; j < 8; j++) acc[i][j] = 0.f;

    int arow = tid >> 1, akq = (tid & 1) * 4;     // A loader: 1 float4/thread
    int bkk  = tid >> 5, bnq = (tid & 31) * 4;    // B non-trans loader
    int tbn  = tid >> 1, tbkq = (tid & 1) * 4;    // B trans loader

    for (int k0 = 0; k0 < K; k0 += BK) {
        float4 av = *reinterpret_cast<const float4*>(
            A + (long long)(m0 + arow) * lda + (k0 + akq));
        As[akq + 0][arow] = av.x; As[akq + 1][arow] = av.y;
        As[akq + 2][arow] = av.z; As[akq + 3][arow] = av.w;

        if (!transB) {
            float4 bv = make_float4(0.f, 0.f, 0.f, 0.f);
            if (n0 + bnq < N)
                bv = *reinterpret_cast<const float4*>(
                    B + (long long)(k0 + bkk) * ldb + (n0 + bnq));
            *reinterpret_cast<float4*>(&Bs[bkk][bnq]) = bv;
        } else {
            float4 bv = make_float4(0.f, 0.f, 0.f, 0.f);
            if (n0 + tbn < N)
                bv = *reinterpret_cast<const float4*>(
                    B + (long long)(n0 + tbn) * ldb + (k0 + tbkq));
            Bs[tbkq + 0][tbn] = bv.x; Bs[tbkq + 1][tbn] = bv.y;
            Bs[tbkq + 2][tbn] = bv.z; Bs[tbkq + 3][tbn] = bv.w;
        }
        __syncthreads();

        #pragma unroll
        for (int kk = 0; kk < BK; kk++) {
            float ar[8], br[8];
            *reinterpret_cast<float4*>(&ar[0]) = *reinterpret_cast<float4*>(&As[kk][ty*8]);
            *reinterpret_cast<float4*>(&ar[4]) = *reinterpret_cast<float4*>(&As[kk][ty*8+4]);
            *reinterpret_cast<float4*>(&br[0]) = *reinterpret_cast<float4*>(&Bs[kk][tx*8]);
            *reinterpret_cast<float4*>(&br[4]) = *reinterpret_cast<float4*>(&Bs[kk][tx*8+4]);
            #pragma unroll
            for (int i = 0; i < 8; i++)
                #pragma unroll
                for (int j = 0; j < 8; j++)
                    acc[i][j] = fmaf(ar[i], br[j], acc[i][j]);
        }
        __syncthreads();
    }

    float betav = beta_ptr ? beta_ptr[0] : 0.f;
    #pragma unroll
    for (int i = 0; i < 8; i++) {
        int m = m0 + ty * 8 + i;
        long long crow = (long long)m * ldc;
        float cw = (mode == 4) ? cwgt[m] : 0.f;
        #pragma unroll
        for (int j = 0; j < 8; j++) {
            int n = n0 + tx * 8 + j;
            if (n >= N) continue;
            float v = acc[i][j];
            float o;
            if (mode == 0)      o = v * scale;
            else if (mode == 1) o = v;
            else if (mode == 2) o = geluf(v + bias[n]);
            else if (mode == 3) o = res[crow + n] + v + (bias ? bias[n] : 0.f);
            else                o = res[crow + n] + betav * h2p[crow + n]
                                     + cw * (v + bias[n]);
            C[crow + n] = o;
        }
    }
}

// ---------------- host-side launch helpers ----------------
static void launch_gemm(const float* A, const float* B, float* C,
    int M, int N, int K, int lda, int ldb, int ldc,
    int batch, int batchH,
    long long sAb, long long sAh, long long sBb, long long sBh,
    long long sCb, long long sCh,
    float scale, const float* bias, const float* res,
    const float* h2p, const float* cwgt, const float* betap,
    int mode, int transB)
{
    dim3 grid((N + BN - 1) / BN, (M + BM - 1) / BM, batch);
    gemm_kernel<<<grid, 256>>>(A, B, C, M, N, K, lda, ldb, ldc,
        batchH, sAb, sAh, sBb, sBh, sCb, sCh,
        scale, bias, res, h2p, cwgt, betap, mode, transB);
}

extern "C" void kernel_launch(void* const* d_in, const int* in_sizes, int n_in,
                              void* d_out, int out_size)
{
    const float* x     = (const float*)d_in[0];
    const float* wq    = (const float*)d_in[1];
    const float* wk    = (const float*)d_in[2];
    const float* wv    = (const float*)d_in[3];
    const float* wo    = (const float*)d_in[4];
    const float* phase = (const float*)d_in[5];
    const float* cw1   = (const float*)d_in[6];
    const float* cb1   = (const float*)d_in[7];
    const float* cw2   = (const float*)d_in[8];
    const float* cb2   = (const float*)d_in[9];
    const float* alpha = (const float*)d_in[10];
    const float* beta  = (const float*)d_in[11];
    const float* fw1   = (const float*)d_in[12];
    const float* fb1   = (const float*)d_in[13];
    const float* fw2   = (const float*)d_in[14];
    const float* fb2   = (const float*)d_in[15];
    const float* ln1g  = (const float*)d_in[16];
    const float* ln1b  = (const float*)d_in[17];
    const float* ln2g  = (const float*)d_in[18];
    const float* ln2b  = (const float*)d_in[19];
    const float* ln3g  = (const float*)d_in[20];
    const float* ln3b  = (const float*)d_in[21];

    static float *p_h=0,*p_Q=0,*p_K=0,*p_V=0,*p_Qg=0,*p_ctx=0,*p_x1=0,*p_h2=0,
                 *p_x2=0,*p_t1=0,*p_ff1=0,*p_cwgt=0,*p_attn_fb=0;
    if (!p_h) {
        cudaGetSymbolAddress((void**)&p_h,   g_h);
        cudaGetSymbolAddress((void**)&p_Q,   g_Q);
        cudaGetSymbolAddress((void**)&p_K,   g_K);
        cudaGetSymbolAddress((void**)&p_V,   g_V);
        cudaGetSymbolAddress((void**)&p_Qg,  g_Qg);
        cudaGetSymbolAddress((void**)&p_ctx, g_ctx);
        cudaGetSymbolAddress((void**)&p_x1,  g_x1);
        cudaGetSymbolAddress((void**)&p_h2,  g_h2);
        cudaGetSymbolAddress((void**)&p_x2,  g_x2);
        cudaGetSymbolAddress((void**)&p_t1,  g_t1);
        cudaGetSymbolAddress((void**)&p_ff1, g_ff1);
        cudaGetSymbolAddress((void**)&p_cwgt,g_cwgt);
        cudaGetSymbolAddress((void**)&p_attn_fb, g_attn_fb);
    }

    float* out_x = (float*)d_out;
    long long need = (long long)NELT + ASZ;
    float* attn = ((long long)out_size >= need) ? (out_x + NELT) : p_attn_fb;

    // 1) h = LN1(x)
    ln_kernel<<<NTOK, 256>>>(x, p_h, ln1g, ln1b, nullptr, nullptr);

    // 2) Q,K,V = h @ {wq,wk,wv}
    launch_gemm(p_h, wq, p_Q, NTOK, DD, DD, DD, DD, DD, 1, 1, 0,0,0,0,0,0,
                1.f, 0, 0, 0, 0, 0, 1, 0);
    launch_gemm(p_h, wk, p_K, NTOK, DD, DD, DD, DD, DD, 1, 1, 0,0,0,0,0,0,
                1.f, 0, 0, 0, 0, 0, 1, 0);
    launch_gemm(p_h, wv, p_V, NTOK, DD, DD, DD, DD, DD, 1, 1, 0,0,0,0,0,0,
                1.f, 0, 0, 0, 0, 0, 1, 0);

    // 3) Qg = Q*cos - V*sin (per head)
    qg_kernel<<<(NELT + 255) / 256, 256>>>(p_Q, p_V, phase, p_Qg);

    // 4) scores[b,h] = Qg_bh @ K_bh^T / sqrt(64)   (batched over b*h)
    launch_gemm(p_Qg, p_K, attn, SS, SS, DKK, DD, DD, SS,
                BB*HH, HH,
                (long long)SS*DD, DKK,
                (long long)SS*DD, DKK,
                (long long)HH*SS*SS, (long long)SS*SS,
                0.125f, 0, 0, 0, 0, 0, 0, 1);

    // 5) softmax rows (in place -> final attn_weights output)
    softmax_kernel<<<BB*HH*SS, 256>>>(attn);

    // 6) ctx[b,h] = attn_bh @ V_bh
    launch_gemm(attn, p_V, p_ctx, SS, DKK, SS, SS, DD, DD,
                BB*HH, HH,
                (long long)HH*SS*SS, (long long)SS*SS,
                (long long)SS*DD, DKK,
                (long long)SS*DD, DKK,
                1.f, 0, 0, 0, 0, 0, 1, 0);

    // 7) x1 = x + ctx @ wo
    launch_gemm(p_ctx, wo, p_x1, NTOK, DD, DD, DD, DD, DD, 1, 1, 0,0,0,0,0,0,
                1.f, 0, x, 0, 0, 0, 3, 0);

    // 8) h2 = LN2(x1), cwgt = exp(-alpha*||h2||)
    ln_kernel<<<NTOK, 256>>>(p_x1, p_h2, ln2g, ln2b, p_cwgt, alpha);

    // 9) t1 = gelu(h2 @ cw1 + cb1)
    launch_gemm(p_h2, cw1, p_t1, NTOK, 2*DD, DD, DD, 2*DD, 2*DD, 1, 1, 0,0,0,0,0,0,
                1.f, cb1, 0, 0, 0, 0, 2, 0);

    // 10) x2 = x1 + beta*h2 + cwgt*(t1 @ cw2 + cb2)
    launch_gemm(p_t1, cw2, p_x2, NTOK, DD, 2*DD, 2*DD, DD, DD, 1, 1, 0,0,0,0,0,0,
                1.f, cb2, p_x1, p_h2, p_cwgt, beta, 4, 0);

    // 11) h3 = LN3(x2)
    ln_kernel<<<NTOK, 256>>>(p_x2, p_h, ln3g, ln3b, nullptr, nullptr);

    // 12) ff1 = gelu(h3 @ fw1 + fb1)
    launch_gemm(p_h, fw1, p_ff1, NTOK, FFN, DD, DD, FFN, FFN, 1, 1, 0,0,0,0,0,0,
                1.f, fb1, 0, 0, 0, 0, 2, 0);

    // 13) out = x2 + ff1 @ fw2 + fb2
    launch_gemm(p_ff1, fw2, out_x, NTOK, DD, FFN, FFN, DD, DD, 1, 1, 0,0,0,0,0,0,
                1.f, fb2, p_x2, 0, 0, 0, 3, 0);
}

// round 6
// speedup vs baseline: 3.0345x; 3.0345x over previous
#include <cuda_runtime.h>
#include <math.h>
#include <stdint.h>

// ---------------- problem constants ----------------
#define BB   4
#define SS   2048
#define DD   1024
#define HH   16
#define DKK  64
#define FFN  4096
#define NTOK (BB*SS)
#define NELT (NTOK*DD)
#define ASZ  ((long long)BB*HH*SS*SS)

// ---------------- scratch (device globals) ----------------
__device__ float g_h  [NELT];
__device__ float g_Q  [NELT];
__device__ float g_K  [NELT];
__device__ float g_V  [NELT];
__device__ float g_Qg [NELT];
__device__ float g_VT [NELT];
__device__ float g_ctx[NELT];
__device__ float g_x1 [NELT];
__device__ float g_h2 [NELT];
__device__ float g_x2 [NELT];
__device__ float g_t1 [NTOK*2*DD];
__device__ float g_ff1[NTOK*FFN];
__device__ float g_cwgt[NTOK];
__device__ float g_wqT [DD*DD];
__device__ float g_wkT [DD*DD];
__device__ float g_wvT [DD*DD];
__device__ float g_woT [DD*DD];
__device__ float g_cw1T[DD*2*DD];
__device__ float g_cw2T[2*DD*DD];
__device__ float g_fw1T[DD*FFN];
__device__ float g_fw2T[DD*FFN];
__device__ float g_attn_fb[(size_t)ASZ];

// ---------------- helpers ----------------
__device__ __forceinline__ uint32_t f2tf32(float x) {
    uint32_t u;
    asm("cvt.rna.tf32.f32 %0, %1;" : "=r"(u) : "f"(x));
    return u;
}
__device__ __forceinline__ float geluf(float x) {
    return 0.5f * x * (1.0f + erff(x * 0.70710678118654752f));
}
__device__ __forceinline__ void mma_tf32(float* d, const uint32_t* a, const uint32_t* b) {
    asm volatile(
        "mma.sync.aligned.m16n8k8.row.col.f32.tf32.tf32.f32 "
        "{%0,%1,%2,%3}, {%4,%5,%6,%7}, {%8,%9}, {%0,%1,%2,%3};"
        : "+f"(d[0]), "+f"(d[1]), "+f"(d[2]), "+f"(d[3])
        : "r"(a[0]), "r"(a[1]), "r"(a[2]), "r"(a[3]), "r"(b[0]), "r"(b[1]));
}

// ---------------- tensor-core tf32 GEMM: C = A[M,K] @ B[N,K]^T, fused epilogues ----------------
// Block 128x128xBK16, 8 warps (4 M x 2 N), warp tile 32x64.
// mode: 0 = scale*acc   1 = acc   2 = gelu(acc+bias)
//       3 = res + acc (+bias)     4 = res + beta*h2 + cwgt[m]*(acc+bias)
#define BKC 16
#define SPAD 20   // row stride in floats (16 + 4 pad) -> conflict-free frags, 16B-aligned rows

__global__ void __launch_bounds__(256) tc_gemm(
    const float* __restrict__ A, const float* __restrict__ B, float* __restrict__ C,
    int M, int N, int K, int lda, int ldb, int ldc,
    int batchH, long long sAb, long long sAh, long long sBb, long long sBh,
    long long sCb, long long sCh,
    float scale, const float* __restrict__ bias, const float* __restrict__ res,
    const float* __restrict__ h2p, const float* __restrict__ cwgt,
    const float* __restrict__ beta_ptr, int mode)
{
    __shared__ uint32_t As[2][128][SPAD];
    __shared__ uint32_t Bs[2][128][SPAD];

    int z = blockIdx.z;
    int zb = z / batchH, zh = z - zb * batchH;
    A += (long long)zb * sAb + (long long)zh * sAh;
    B += (long long)zb * sBb + (long long)zh * sBh;
    C += (long long)zb * sCb + (long long)zh * sCh;

    int tid = threadIdx.x;
    int wid = tid >> 5, lane = tid & 31;
    int wm = wid >> 1, wn = wid & 1;          // warp grid 4 (M) x 2 (N)
    int g = lane >> 2, t = lane & 3;          // fragment group / thread-in-group

    int m0 = blockIdx.y * 128, n0 = blockIdx.x * 128;
    int ntile = N - n0; if (ntile > 128) ntile = 128;

    float acc[2][8][4];
    #pragma unroll
    for (int i = 0; i < 2; i++)
        #pragma unroll
        for (int j = 0; j < 8; j++)
            #pragma unroll
            for (int q = 0; q < 4; q++) acc[i][j][q] = 0.f;

    // global loaders: 512 float4 per tile / 256 thr = 2 each
    int lr0 = tid >> 2, lc0 = (tid & 3) * 4;          // element i: row = lr0 + i*64
    int NC = K / BKC;

    float4 ra[2], rb[2];
    #pragma unroll
    for (int i = 0; i < 2; i++) {
        int r = lr0 + i * 64;
        ra[i] = *reinterpret_cast<const float4*>(A + (long long)(m0 + r) * lda + lc0);
        rb[i] = (r < ntile)
            ? *reinterpret_cast<const float4*>(B + (long long)(n0 + r) * ldb + lc0)
            : make_float4(0.f, 0.f, 0.f, 0.f);
    }

    for (int c = 0; c < NC; c++) {
        int buf = c & 1;
        #pragma unroll
        for (int i = 0; i < 2; i++) {
            int r = lr0 + i * 64;
            As[buf][r][lc0+0] = f2tf32(ra[i].x); As[buf][r][lc0+1] = f2tf32(ra[i].y);
            As[buf][r][lc0+2] = f2tf32(ra[i].z); As[buf][r][lc0+3] = f2tf32(ra[i].w);
            Bs[buf][r][lc0+0] = f2tf32(rb[i].x); Bs[buf][r][lc0+1] = f2tf32(rb[i].y);
            Bs[buf][r][lc0+2] = f2tf32(rb[i].z); Bs[buf][r][lc0+3] = f2tf32(rb[i].w);
        }
        __syncthreads();

        if (c + 1 < NC) {
            int k0 = (c + 1) * BKC;
            #pragma unroll
            for (int i = 0; i < 2; i++) {
                int r = lr0 + i * 64;
                ra[i] = *reinterpret_cast<const float4*>(A + (long long)(m0 + r) * lda + k0 + lc0);
                rb[i] = (r < ntile)
                    ? *reinterpret_cast<const float4*>(B + (long long)(n0 + r) * ldb + k0 + lc0)
                    : make_float4(0.f, 0.f, 0.f, 0.f);
            }
        }

        #pragma unroll
        for (int ks = 0; ks < 2; ks++) {
            int kk = ks * 8;
            uint32_t af[2][4], bf[8][2];
            #pragma unroll
            for (int mt = 0; mt < 2; mt++) {
                int row = wm * 32 + mt * 16 + g;
                af[mt][0] = As[buf][row    ][kk + t];
                af[mt][1] = As[buf][row + 8][kk + t];
                af[mt][2] = As[buf][row    ][kk + t + 4];
                af[mt][3] = As[buf][row + 8][kk + t + 4];
            }
            #pragma unroll
            for (int nt = 0; nt < 8; nt++) {
                int col = wn * 64 + nt * 8 + g;
                bf[nt][0] = Bs[buf][col][kk + t];
                bf[nt][1] = Bs[buf][col][kk + t + 4];
            }
            #pragma unroll
            for (int mt = 0; mt < 2; mt++)
                #pragma unroll
                for (int nt = 0; nt < 8; nt++)
                    mma_tf32(acc[mt][nt], af[mt], bf[nt]);
        }
        __syncthreads();
    }

    // ---------------- epilogue ----------------
    float betav = (mode == 4 && beta_ptr) ? beta_ptr[0] : 0.f;
    #pragma unroll
    for (int mt = 0; mt < 2; mt++) {
        int r0 = m0 + wm * 32 + mt * 16 + g;
        int r1 = r0 + 8;
        float cw0 = 0.f, cw1 = 0.f;
        if (mode == 4) { cw0 = cwgt[r0]; cw1 = cwgt[r1]; }
        #pragma unroll
        for (int nt = 0; nt < 8; nt++) {
            int crel = wn * 64 + nt * 8 + 2 * t;
            if (crel >= ntile) continue;
            int n = n0 + crel;
            long long co0 = (long long)r0 * ldc + n;
            long long co1 = (long long)r1 * ldc + n;
            float v00 = acc[mt][nt][0], v01 = acc[mt][nt][1];
            float v10 = acc[mt][nt][2], v11 = acc[mt][nt][3];
            float2 o0, o1;
            if (mode == 0) {
                o0 = make_float2(v00 * scale, v01 * scale);
                o1 = make_float2(v10 * scale, v11 * scale);
            } else if (mode == 1) {
                o0 = make_float2(v00, v01);
                o1 = make_float2(v10, v11);
            } else if (mode == 2) {
                float b0 = bias[n], b1 = bias[n + 1];
                o0 = make_float2(geluf(v00 + b0), geluf(v01 + b1));
                o1 = make_float2(geluf(v10 + b0), geluf(v11 + b1));
            } else if (mode == 3) {
                float b0 = bias ? bias[n] : 0.f, b1 = bias ? bias[n + 1] : 0.f;
                float2 q0 = *reinterpret_cast<const float2*>(res + co0);
                float2 q1 = *reinterpret_cast<const float2*>(res + co1);
                o0 = make_float2(q0.x + v00 + b0, q0.y + v01 + b1);
                o1 = make_float2(q1.x + v10 + b0, q1.y + v11 + b1);
            } else {
                float b0 = bias[n], b1 = bias[n + 1];
                float2 q0 = *reinterpret_cast<const float2*>(res + co0);
                float2 q1 = *reinterpret_cast<const float2*>(res + co1);
                float2 h0 = *reinterpret_cast<const float2*>(h2p + co0);
                float2 h1 = *reinterpret_cast<const float2*>(h2p + co1);
                o0 = make_float2(q0.x + betav * h0.x + cw0 * (v00 + b0),
                                 q0.y + betav * h0.y + cw0 * (v01 + b1));
                o1 = make_float2(q1.x + betav * h1.x + cw1 * (v10 + b0),
                                 q1.y + betav * h1.y + cw1 * (v11 + b1));
            }
            *reinterpret_cast<float2*>(C + co0) = o0;
            *reinterpret_cast<float2*>(C + co1) = o1;
        }
    }
}

// ---------------- transpose: out[c][r] = in[r][c], batched ----------------
__global__ void __launch_bounds__(256) transpose_kernel(
    const float* __restrict__ in, float* __restrict__ out,
    int R, int C, int ldi, int ldo,
    int batchH, long long sIb, long long sIh, long long sOb, long long sOh)
{
    __shared__ float tile[32][33];
    int z = blockIdx.z;
    int zb = z / batchH, zh = z - zb * batchH;
    in  += (long long)zb * sIb + (long long)zh * sIh;
    out += (long long)zb * sOb + (long long)zh * sOh;
    int r0 = blockIdx.y * 32, c0 = blockIdx.x * 32;
    int tx = threadIdx.x & 31, ty = threadIdx.x >> 5;
    #pragma unroll
    for (int i = 0; i < 4; i++) {
        int r = r0 + ty + i * 8, c = c0 + tx;
        if (r < R && c < C) tile[ty + i * 8][tx] = in[(long long)r * ldi + c];
    }
    __syncthreads();
    #pragma unroll
    for (int i = 0; i < 4; i++) {
        int c = c0 + ty + i * 8, r = r0 + tx;
        if (r < R && c < C) out[(long long)c * ldo + r] = tile[tx][ty + i * 8];
    }
}

// ---------------- layernorm ----------------
__device__ __forceinline__ float brsum(float v, float* sh) {
    int t = threadIdx.x;
    sh[t] = v; __syncthreads();
    #pragma unroll
    for (int s = 128; s > 0; s >>= 1) { if (t < s) sh[t] += sh[t + s]; __syncthreads(); }
    float r = sh[0]; __syncthreads();
    return r;
}
__device__ __forceinline__ float brmax(float v, float* sh) {
    int t = threadIdx.x;
    sh[t] = v; __syncthreads();
    #pragma unroll
    for (int s = 128; s > 0; s >>= 1) { if (t < s) sh[t] = fmaxf(sh[t], sh[t + s]); __syncthreads(); }
    float r = sh[0]; __syncthreads();
    return r;
}

__global__ void __launch_bounds__(256) ln_kernel(
    const float* __restrict__ x, float* __restrict__ y,
    const float* __restrict__ g, const float* __restrict__ b,
    float* __restrict__ cwgt, const float* __restrict__ alpha_ptr)
{
    long long base = (long long)blockIdx.x * DD;
    int t = threadIdx.x;
    __shared__ float sh[256];
    float xv[4];
    float s = 0.f;
    #pragma unroll
    for (int i = 0; i < 4; i++) { xv[i] = x[base + t + i * 256]; s += xv[i]; }
    s = brsum(s, sh);
    float mu = s * (1.0f / DD);
    float vs = 0.f;
    #pragma unroll
    for (int i = 0; i < 4; i++) { float d = xv[i] - mu; vs += d * d; }
    vs = brsum(vs, sh);
    float inv = rsqrtf(vs * (1.0f / DD) + 1e-5f);
    float ss = 0.f;
    #pragma unroll
    for (int i = 0; i < 4; i++) {
        int c = t + i * 256;
        float yv = (xv[i] - mu) * inv * g[c] + b[c];
        y[base + c] = yv;
        ss += yv * yv;
    }
    if (cwgt) {
        ss = brsum(ss, sh);
        if (t == 0) cwgt[blockIdx.x] = expf(-alpha_ptr[0] * sqrtf(ss));
    }
}

// ---------------- Qg = Q*cos(ph[h]) - V*sin(ph[h]) ----------------
__global__ void __launch_bounds__(256) qg_kernel(
    const float* __restrict__ Q, const float* __restrict__ V,
    const float* __restrict__ phase, float* __restrict__ Qg)
{
    int i = blockIdx.x * 256 + threadIdx.x;
    if (i >= NELT) return;
    int h = (i & (DD - 1)) >> 6;
    float p = phase[h];
    Qg[i] = Q[i] * cosf(p) - V[i] * sinf(p);
}

// ---------------- softmax (rows of 2048, in place) ----------------
__global__ void __launch_bounds__(256) softmax_kernel(float* __restrict__ attn)
{
    float* r = attn + (long long)blockIdx.x * SS;
    int t = threadIdx.x;
    __shared__ float sh[256];
    float v[8];
    float mx = -3.4e38f;
    #pragma unroll
    for (int i = 0; i < 8; i++) { v[i] = r[t + i * 256]; mx = fmaxf(mx, v[i]); }
    mx = brmax(mx, sh);
    float s = 0.f;
    #pragma unroll
    for (int i = 0; i < 8; i++) { v[i] = expf(v[i] - mx); s += v[i]; }
    s = brsum(s, sh);
    float inv = 1.0f / s;
    #pragma unroll
    for (int i = 0; i < 8; i++) r[t + i * 256] = v[i] * inv;
}

// ---------------- host helpers ----------------
static void launch_tc(const float* A, const float* B, float* C,
    int M, int N, int K, int lda, int ldb, int ldc,
    int batch, int batchH,
    long long sAb, long long sAh, long long sBb, long long sBh,
    long long sCb, long long sCh,
    float scale, const float* bias, const float* res,
    const float* h2p, const float* cwgt, const float* betap, int mode)
{
    dim3 grid((N + 127) / 128, M / 128, batch);
    tc_gemm<<<grid, 256>>>(A, B, C, M, N, K, lda, ldb, ldc,
        batchH, sAb, sAh, sBb, sBh, sCb, sCh,
        scale, bias, res, h2p, cwgt, betap, mode);
}

static void launch_tr(const float* in, float* out, int R, int C, int ldi, int ldo,
    int batch, int batchH, long long sIb, long long sIh, long long sOb, long long sOh)
{
    dim3 grid((C + 31) / 32, (R + 31) / 32, batch);
    transpose_kernel<<<grid, 256>>>(in, out, R, C, ldi, ldo, batchH, sIb, sIh, sOb, sOh);
}

extern "C" void kernel_launch(void* const* d_in, const int* in_sizes, int n_in,
                              void* d_out, int out_size)
{
    const float* x     = (const float*)d_in[0];
    const float* wq    = (const float*)d_in[1];
    const float* wk    = (const float*)d_in[2];
    const float* wv    = (const float*)d_in[3];
    const float* wo    = (const float*)d_in[4];
    const float* phase = (const float*)d_in[5];
    const float* cw1   = (const float*)d_in[6];
    const float* cb1   = (const float*)d_in[7];
    const float* cw2   = (const float*)d_in[8];
    const float* cb2   = (const float*)d_in[9];
    const float* alpha = (const float*)d_in[10];
    const float* beta  = (const float*)d_in[11];
    const float* fw1   = (const float*)d_in[12];
    const float* fb1   = (const float*)d_in[13];
    const float* fw2   = (const float*)d_in[14];
    const float* fb2   = (const float*)d_in[15];
    const float* ln1g  = (const float*)d_in[16];
    const float* ln1b  = (const float*)d_in[17];
    const float* ln2g  = (const float*)d_in[18];
    const float* ln2b  = (const float*)d_in[19];
    const float* ln3g  = (const float*)d_in[20];
    const float* ln3b  = (const float*)d_in[21];

    static float *p_h=0,*p_Q=0,*p_K=0,*p_V=0,*p_Qg=0,*p_VT=0,*p_ctx=0,*p_x1=0,
                 *p_h2=0,*p_x2=0,*p_t1=0,*p_ff1=0,*p_cwgt=0,*p_attn_fb=0,
                 *p_wqT=0,*p_wkT=0,*p_wvT=0,*p_woT=0,*p_cw1T=0,*p_cw2T=0,
                 *p_fw1T=0,*p_fw2T=0;
    if (!p_h) {
        cudaGetSymbolAddress((void**)&p_h,    g_h);
        cudaGetSymbolAddress((void**)&p_Q,    g_Q);
        cudaGetSymbolAddress((void**)&p_K,    g_K);
        cudaGetSymbolAddress((void**)&p_V,    g_V);
        cudaGetSymbolAddress((void**)&p_Qg,   g_Qg);
        cudaGetSymbolAddress((void**)&p_VT,   g_VT);
        cudaGetSymbolAddress((void**)&p_ctx,  g_ctx);
        cudaGetSymbolAddress((void**)&p_x1,   g_x1);
        cudaGetSymbolAddress((void**)&p_h2,   g_h2);
        cudaGetSymbolAddress((void**)&p_x2,   g_x2);
        cudaGetSymbolAddress((void**)&p_t1,   g_t1);
        cudaGetSymbolAddress((void**)&p_ff1,  g_ff1);
        cudaGetSymbolAddress((void**)&p_cwgt, g_cwgt);
        cudaGetSymbolAddress((void**)&p_attn_fb, g_attn_fb);
        cudaGetSymbolAddress((void**)&p_wqT,  g_wqT);
        cudaGetSymbolAddress((void**)&p_wkT,  g_wkT);
        cudaGetSymbolAddress((void**)&p_wvT,  g_wvT);
        cudaGetSymbolAddress((void**)&p_woT,  g_woT);
        cudaGetSymbolAddress((void**)&p_cw1T, g_cw1T);
        cudaGetSymbolAddress((void**)&p_cw2T, g_cw2T);
        cudaGetSymbolAddress((void**)&p_fw1T, g_fw1T);
        cudaGetSymbolAddress((void**)&p_fw2T, g_fw2T);
    }

    float* out_x = (float*)d_out;
    long long need = (long long)NELT + ASZ;
    float* attn = ((long long)out_size >= need) ? (out_x + NELT) : p_attn_fb;

    // weight transposes (W[K,N] -> WT[N,K])
    launch_tr(wq,  p_wqT,  DD,   DD,  DD,   DD,   1, 1, 0,0,0,0);
    launch_tr(wk,  p_wkT,  DD,   DD,  DD,   DD,   1, 1, 0,0,0,0);
    launch_tr(wv,  p_wvT,  DD,   DD,  DD,   DD,   1, 1, 0,0,0,0);
    launch_tr(wo,  p_woT,  DD,   DD,  DD,   DD,   1, 1, 0,0,0,0);
    launch_tr(cw1, p_cw1T, DD,   2*DD, 2*DD, DD,  1, 1, 0,0,0,0);
    launch_tr(cw2, p_cw2T, 2*DD, DD,  DD,   2*DD, 1, 1, 0,0,0,0);
    launch_tr(fw1, p_fw1T, DD,   FFN, FFN,  DD,   1, 1, 0,0,0,0);
    launch_tr(fw2, p_fw2T, FFN,  DD,  DD,   FFN,  1, 1, 0,0,0,0);

    // 1) h = LN1(x)
    ln_kernel<<<NTOK, 256>>>(x, p_h, ln1g, ln1b, nullptr, nullptr);

    // 2) Q,K,V
    launch_tc(p_h, p_wqT, p_Q, NTOK, DD, DD, DD, DD, DD, 1,1, 0,0,0,0,0,0,
              1.f, 0,0,0,0,0, 1);
    launch_tc(p_h, p_wkT, p_K, NTOK, DD, DD, DD, DD, DD, 1,1, 0,0,0,0,0,0,
              1.f, 0,0,0,0,0, 1);
    launch_tc(p_h, p_wvT, p_V, NTOK, DD, DD, DD, DD, DD, 1,1, 0,0,0,0,0,0,
              1.f, 0,0,0,0,0, 1);

    // 3) Qg
    qg_kernel<<<(NELT + 255) / 256, 256>>>(p_Q, p_V, phase, p_Qg);

    // 3b) VT[b,h,d,s] = V[b,s,h,d]
    launch_tr(p_V, p_VT, SS, DKK, DD, SS,
              BB * HH, HH,
              (long long)SS * DD, DKK,
              (long long)HH * DKK * SS, (long long)DKK * SS);

    // 4) scores = Qg @ K^T / 8
    launch_tc(p_Qg, p_K, attn, SS, SS, DKK, DD, DD, SS,
              BB * HH, HH,
              (long long)SS * DD, DKK,
              (long long)SS * DD, DKK,
              (long long)HH * SS * SS, (long long)SS * SS,
              0.125f, 0,0,0,0,0, 0);

    // 5) softmax
    softmax_kernel<<<BB * HH * SS, 256>>>(attn);

    // 6) ctx = attn @ V   (B = VT[b,h] is [64, 2048] K-major)
    launch_tc(attn, p_VT, p_ctx, SS, DKK, SS, SS, SS, DD,
              BB * HH, HH,
              (long long)HH * SS * SS, (long long)SS * SS,
              (long long)HH * DKK * SS, (long long)DKK * SS,
              (long long)SS * DD, DKK,
              1.f, 0,0,0,0,0, 1);

    // 7) x1 = x + ctx @ wo
    launch_tc(p_ctx, p_woT, p_x1, NTOK, DD, DD, DD, DD, DD, 1,1, 0,0,0,0,0,0,
              1.f, 0, x, 0,0,0, 3);

    // 8) h2 = LN2(x1) + cwgt
    ln_kernel<<<NTOK, 256>>>(p_x1, p_h2, ln2g, ln2b, p_cwgt, alpha);

    // 9) t1 = gelu(h2 @ cw1 + cb1)
    launch_tc(p_h2, p_cw1T, p_t1, NTOK, 2*DD, DD, DD, DD, 2*DD, 1,1, 0,0,0,0,0,0,
              1.f, cb1, 0,0,0,0, 2);

    // 10) x2 = x1 + beta*h2 + cwgt*(t1 @ cw2 + cb2)
    launch_tc(p_t1, p_cw2T, p_x2, NTOK, DD, 2*DD, 2*DD, 2*DD, DD, 1,1, 0,0,0,0,0,0,
              1.f, cb2, p_x1, p_h2, p_cwgt, beta, 4);

    // 11) h3 = LN3(x2)
    ln_kernel<<<NTOK, 256>>>(p_x2, p_h, ln3g, ln3b, nullptr, nullptr);

    // 12) ff1 = gelu(h3 @ fw1 + fb1)
    launch_tc(p_h, p_fw1T, p_ff1, NTOK, FFN, DD, DD, DD, FFN, 1,1, 0,0,0,0,0,0,
              1.f, fb1, 0,0,0,0, 2);

    // 13) out = x2 + ff1 @ fw2 + fb2
    launch_tc(p_ff1, p_fw2T, out_x, NTOK, DD, FFN, FFN, FFN, DD, 1,1, 0,0,0,0,0,0,
              1.f, fb2, p_x2, 0,0,0, 3);
}

// round 7
// speedup vs baseline: 3.4158x; 1.1257x over previous
#include <cuda_runtime.h>
#include <math.h>
#include <stdint.h>

// ---------------- problem constants ----------------
#define BB   4
#define SS   2048
#define DD   1024
#define HH   16
#define DKK  64
#define FFN  4096
#define NTOK (BB*SS)
#define NELT (NTOK*DD)
#define ASZ  ((long long)BB*HH*SS*SS)
#define NROWS (BB*HH*SS)

#define SPAD 20   // smem row stride (floats): conflict-free frags, rows 16B-aligned

// ---------------- scratch (device globals) ----------------
__device__ float g_h  [NELT];
__device__ float g_Q  [NELT];
__device__ float g_K  [NELT];
__device__ float g_V  [NELT];
__device__ float g_Qg [NELT];
__device__ float g_VT [NELT];
__device__ float g_ctx[NELT];
__device__ float g_x1 [NELT];
__device__ float g_h2 [NELT];
__device__ float g_x2 [NELT];
__device__ float g_t1 [NTOK*2*DD];
__device__ float g_ff1[NTOK*FFN];
__device__ float g_cwgt[NTOK];
__device__ float g_rowsum[NROWS];
__device__ float g_wqT [DD*DD];
__device__ float g_wkT [DD*DD];
__device__ float g_wvT [DD*DD];
__device__ float g_woT [DD*DD];
__device__ float g_cw1T[DD*2*DD];
__device__ float g_cw2T[2*DD*DD];
__device__ float g_fw1T[DD*FFN];
__device__ float g_fw2T[DD*FFN];
__device__ float g_attn_fb[(size_t)ASZ];   // holds unnormalized exp(scores)

// ---------------- helpers ----------------
__device__ __forceinline__ uint32_t smem_u32(const void* p) {
    uint32_t a;
    asm("{ .reg .u64 t; cvta.to.shared.u64 t, %1; cvt.u32.u64 %0, t; }"
        : "=r"(a) : "l"(p));
    return a;
}
__device__ __forceinline__ uint32_t f2tf32(float x) {
    uint32_t u;
    asm("cvt.rna.tf32.f32 %0, %1;" : "=r"(u) : "f"(x));
    return u;
}
__device__ __forceinline__ float geluf(float x) {
    return 0.5f * x * (1.0f + erff(x * 0.70710678118654752f));
}
__device__ __forceinline__ void mma_tf32(float* d, const uint32_t* a, const uint32_t* b) {
    asm volatile(
        "mma.sync.aligned.m16n8k8.row.col.f32.tf32.tf32.f32 "
        "{%0,%1,%2,%3}, {%4,%5,%6,%7}, {%8,%9}, {%0,%1,%2,%3};"
        : "+f"(d[0]), "+f"(d[1]), "+f"(d[2]), "+f"(d[3])
        : "r"(a[0]), "r"(a[1]), "r"(a[2]), "r"(a[3]), "r"(b[0]), "r"(b[1]));
}
__device__ __forceinline__ void cp16(uint32_t dst, const void* src) {
    asm volatile("cp.async.cg.shared.global [%0], [%1], 16;"
                 :: "r"(dst), "l"(src) : "memory");
}
#define CP_COMMIT() asm volatile("cp.async.commit_group;" ::: "memory")
#define CP_WAIT1()  asm volatile("cp.async.wait_group 1;" ::: "memory")

// ---------------- templated tensor-core tf32 GEMM ----------------
// C = A[M,K] @ B[N,K]^T; BM=128, BKC=16, 3-stage cp.async pipeline; 8 warps.
// BN=128: warps 4x2 (warp tile 32x64, MT=2). BN=64: warps 8x1 (16x64, MT=1).
// MODE: 1 = acc                    2 = gelu(acc+bias)
//       3 = res + acc (+bias)      4 = res + beta*h2 + cwgt[m]*(acc+bias)
//       5 = e=exp(acc*scale), write e, atomic row sums
//       6 = acc * inv_rowsum[m]  (ctx; ATTN=true also streams normalized attn)
template<int BN, bool ATTN, int MODE>
__global__ void __launch_bounds__(256) tc_gemm(
    const float* __restrict__ A, const float* __restrict__ B,
    float* __restrict__ C, float* __restrict__ Aout, float* __restrict__ rowsum,
    int M, int K, int lda, int ldb, int ldc,
    int batchH, long long sAb, long long sAh, long long sBb, long long sBh,
    long long sCb, long long sCh,
    float scale, const float* __restrict__ bias, const float* __restrict__ res,
    const float* __restrict__ h2p, const float* __restrict__ cwgt,
    const float* __restrict__ beta_ptr)
{
    constexpr int WN  = (BN == 128) ? 2 : 1;
    constexpr int MT  = (BN == 128) ? 2 : 1;
    constexpr int STG = (128 + BN) * SPAD;   // uint32s per stage

    extern __shared__ uint32_t sm[];
    uint32_t sbase = smem_u32(sm);

    int z = blockIdx.z;
    int zb = z / batchH, zh = z - zb * batchH;
    A += (long long)zb * sAb + (long long)zh * sAh;
    B += (long long)zb * sBb + (long long)zh * sBh;
    C += (long long)zb * sCb + (long long)zh * sCh;

    int tid = threadIdx.x;
    int wid = tid >> 5, lane = tid & 31;
    int wm = wid / WN, wn = wid % WN;
    int g = lane >> 2, t = lane & 3;
    int m0 = blockIdx.y * 128, n0 = blockIdx.x * BN;

    float acc[MT][8][4];
    #pragma unroll
    for (int i = 0; i < MT; i++)
        #pragma unroll
        for (int j = 0; j < 8; j++)
            #pragma unroll
            for (int q = 0; q < 4; q++) acc[i][j][q] = 0.f;

    int lr0 = tid >> 2, lc0 = (tid & 3) * 4;
    const float* Ag = A + (long long)(m0 + lr0) * lda + lc0;
    const float* Bg = B + (long long)(n0 + lr0) * ldb + lc0;
    int NC = K >> 4;

    float invL0 = 0.f, invL1 = 0.f;
    float* AoutB = nullptr;
    if (ATTN) {
        const float* rs = rowsum + (long long)z * M;
        invL0 = 1.f / rs[m0 + lr0];
        invL1 = 1.f / rs[m0 + lr0 + 64];
        AoutB = Aout + (long long)zb * sAb + (long long)zh * sAh;
    }

    auto issue = [&](int c) {
        int s = c % 3;
        uint32_t ab = sbase + (uint32_t)(s * STG) * 4u;
        uint32_t bb = ab + 128u * SPAD * 4u;
        const float* Ap = Ag + c * 16;
        cp16(ab + (uint32_t)(lr0 * SPAD + lc0) * 4u, Ap);
        cp16(ab + (uint32_t)((lr0 + 64) * SPAD + lc0) * 4u, Ap + (long long)64 * lda);
        const float* Bp = Bg + c * 16;
        cp16(bb + (uint32_t)(lr0 * SPAD + lc0) * 4u, Bp);
        if (BN == 128)
            cp16(bb + (uint32_t)((lr0 + 64) * SPAD + lc0) * 4u, Bp + (long long)64 * ldb);
    };

    issue(0); CP_COMMIT();
    issue(1); CP_COMMIT();

    for (int c = 0; c < NC; c++) {
        int s = c % 3;
        uint32_t* stA = sm + s * STG;
        uint32_t* stB = stA + 128 * SPAD;

        CP_WAIT1();
        __syncthreads();          // stage c visible to all; all warps done with stage (c-1)%3

        if (ATTN) {               // stream normalized attention weights out of smem
            float4 e0 = *reinterpret_cast<float4*>(&stA[lr0 * SPAD + lc0]);
            float4 e1 = *reinterpret_cast<float4*>(&stA[(lr0 + 64) * SPAD + lc0]);
            e0.x *= invL0; e0.y *= invL0; e0.z *= invL0; e0.w *= invL0;
            e1.x *= invL1; e1.y *= invL1; e1.z *= invL1; e1.w *= invL1;
            *reinterpret_cast<float4*>(AoutB + (long long)(m0 + lr0) * lda + c * 16 + lc0) = e0;
            *reinterpret_cast<float4*>(AoutB + (long long)(m0 + lr0 + 64) * lda + c * 16 + lc0) = e1;
        }

        if (c + 2 < NC) issue(c + 2);
        CP_COMMIT();              // always commit (possibly empty) to keep group counting uniform

        #pragma unroll
        for (int ks = 0; ks < 2; ks++) {
            int kk = ks * 8;
            uint32_t af[MT][4], bf[8][2];
            #pragma unroll
            for (int mt = 0; mt < MT; mt++) {
                int row = wm * (MT * 16) + mt * 16 + g;
                af[mt][0] = f2tf32(__uint_as_float(stA[row * SPAD + kk + t]));
                af[mt][1] = f2tf32(__uint_as_float(stA[(row + 8) * SPAD + kk + t]));
                af[mt][2] = f2tf32(__uint_as_float(stA[row * SPAD + kk + t + 4]));
                af[mt][3] = f2tf32(__uint_as_float(stA[(row + 8) * SPAD + kk + t + 4]));
            }
            #pragma unroll
            for (int nt = 0; nt < 8; nt++) {
                int col = wn * 64 + nt * 8 + g;
                bf[nt][0] = f2tf32(__uint_as_float(stB[col * SPAD + kk + t]));
                bf[nt][1] = f2tf32(__uint_as_float(stB[col * SPAD + kk + t + 4]));
            }
            #pragma unroll
            for (int mt = 0; mt < MT; mt++)
                #pragma unroll
                for (int nt = 0; nt < 8; nt++)
                    mma_tf32(acc[mt][nt], af[mt], bf[nt]);
        }
    }

    // ---------------- epilogue ----------------
    float betav = (MODE == 4) ? beta_ptr[0] : 0.f;
    const float* rsE = (MODE == 6) ? rowsum + (long long)z * M : nullptr;
    float* rsA = (MODE == 5) ? rowsum + (long long)z * M : nullptr;

    #pragma unroll
    for (int mt = 0; mt < MT; mt++) {
        int r0 = m0 + wm * (MT * 16) + mt * 16 + g;
        int r1 = r0 + 8;
        float cw0 = 0.f, cw1 = 0.f, inv0 = 0.f, inv1 = 0.f;
        if (MODE == 4) { cw0 = cwgt[r0]; cw1 = cwgt[r1]; }
        if (MODE == 6) { inv0 = 1.f / rsE[r0]; inv1 = 1.f / rsE[r1]; }
        float s0 = 0.f, s1 = 0.f;
        #pragma unroll
        for (int nt = 0; nt < 8; nt++) {
            int n = n0 + wn * 64 + nt * 8 + 2 * t;
            long long co0 = (long long)r0 * ldc + n;
            long long co1 = (long long)r1 * ldc + n;
            float v00 = acc[mt][nt][0], v01 = acc[mt][nt][1];
            float v10 = acc[mt][nt][2], v11 = acc[mt][nt][3];
            float2 o0, o1;
            if (MODE == 1) {
                o0 = make_float2(v00, v01);
                o1 = make_float2(v10, v11);
            } else if (MODE == 2) {
                float b0 = bias[n], b1 = bias[n + 1];
                o0 = make_float2(geluf(v00 + b0), geluf(v01 + b1));
                o1 = make_float2(geluf(v10 + b0), geluf(v11 + b1));
            } else if (MODE == 3) {
                float b0 = bias ? bias[n] : 0.f, b1 = bias ? bias[n + 1] : 0.f;
                float2 q0 = *reinterpret_cast<const float2*>(res + co0);
                float2 q1 = *reinterpret_cast<const float2*>(res + co1);
                o0 = make_float2(q0.x + v00 + b0, q0.y + v01 + b1);
                o1 = make_float2(q1.x + v10 + b0, q1.y + v11 + b1);
            } else if (MODE == 4) {
                float b0 = bias[n], b1 = bias[n + 1];
                float2 q0 = *reinterpret_cast<const float2*>(res + co0);
                float2 q1 = *reinterpret_cast<const float2*>(res + co1);
                float2 h0 = *reinterpret_cast<const float2*>(h2p + co0);
                float2 h1 = *reinterpret_cast<const float2*>(h2p + co1);
                o0 = make_float2(q0.x + betav * h0.x + cw0 * (v00 + b0),
                                 q0.y + betav * h0.y + cw0 * (v01 + b1));
                o1 = make_float2(q1.x + betav * h1.x + cw1 * (v10 + b0),
                                 q1.y + betav * h1.y + cw1 * (v11 + b1));
            } else if (MODE == 5) {
                float e00 = __expf(v00 * scale), e01 = __expf(v01 * scale);
                float e10 = __expf(v10 * scale), e11 = __expf(v11 * scale);
                o0 = make_float2(e00, e01);
                o1 = make_float2(e10, e11);
                s0 += e00 + e01; s1 += e10 + e11;
            } else { // MODE == 6
                o0 = make_float2(v00 * inv0, v01 * inv0);
                o1 = make_float2(v10 * inv1, v11 * inv1);
            }
            *reinterpret_cast<float2*>(C + co0) = o0;
            *reinterpret_cast<float2*>(C + co1) = o1;
        }
        if (MODE == 5) {
            s0 += __shfl_xor_sync(0xffffffffu, s0, 1);
            s0 += __shfl_xor_sync(0xffffffffu, s0, 2);
            s1 += __shfl_xor_sync(0xffffffffu, s1, 1);
            s1 += __shfl_xor_sync(0xffffffffu, s1, 2);
            if (t == 0) {
                atomicAdd(rsA + r0, s0);
                atomicAdd(rsA + r1, s1);
            }
        }
    }
}

// ---------------- zero kernel (row sums) ----------------
__global__ void __launch_bounds__(256) zero_kernel(float* p, int n) {
    int i = blockIdx.x * 256 + threadIdx.x;
    if (i < n) p[i] = 0.f;
}

// ---------------- transpose ----------------
__global__ void __launch_bounds__(256) transpose_kernel(
    const float* __restrict__ in, float* __restrict__ out,
    int R, int C, int ldi, int ldo,
    int batchH, long long sIb, long long sIh, long long sOb, long long sOh)
{
    __shared__ float tile[32][33];
    int z = blockIdx.z;
    int zb = z / batchH, zh = z - zb * batchH;
    in  += (long long)zb * sIb + (long long)zh * sIh;
    out += (long long)zb * sOb + (long long)zh * sOh;
    int r0 = blockIdx.y * 32, c0 = blockIdx.x * 32;
    int tx = threadIdx.x & 31, ty = threadIdx.x >> 5;
    #pragma unroll
    for (int i = 0; i < 4; i++) {
        int r = r0 + ty + i * 8, c = c0 + tx;
        if (r < R && c < C) tile[ty + i * 8][tx] = in[(long long)r * ldi + c];
    }
    __syncthreads();
    #pragma unroll
    for (int i = 0; i < 4; i++) {
        int c = c0 + ty + i * 8, r = r0 + tx;
        if (r < R && c < C) out[(long long)c * ldo + r] = tile[tx][ty + i * 8];
    }
}

// ---------------- layernorm ----------------
__device__ __forceinline__ float brsum(float v, float* sh) {
    int t = threadIdx.x;
    sh[t] = v; __syncthreads();
    #pragma unroll
    for (int s = 128; s > 0; s >>= 1) { if (t < s) sh[t] += sh[t + s]; __syncthreads(); }
    float r = sh[0]; __syncthreads();
    return r;
}

__global__ void __launch_bounds__(256) ln_kernel(
    const float* __restrict__ x, float* __restrict__ y,
    const float* __restrict__ g, const float* __restrict__ b,
    float* __restrict__ cwgt, const float* __restrict__ alpha_ptr)
{
    long long base = (long long)blockIdx.x * DD;
    int t = threadIdx.x;
    __shared__ float sh[256];
    float xv[4];
    float s = 0.f;
    #pragma unroll
    for (int i = 0; i < 4; i++) { xv[i] = x[base + t + i * 256]; s += xv[i]; }
    s = brsum(s, sh);
    float mu = s * (1.0f / DD);
    float vs = 0.f;
    #pragma unroll
    for (int i = 0; i < 4; i++) { float d = xv[i] - mu; vs += d * d; }
    vs = brsum(vs, sh);
    float inv = rsqrtf(vs * (1.0f / DD) + 1e-5f);
    float ss = 0.f;
    #pragma unroll
    for (int i = 0; i < 4; i++) {
        int c = t + i * 256;
        float yv = (xv[i] - mu) * inv * g[c] + b[c];
        y[base + c] = yv;
        ss += yv * yv;
    }
    if (cwgt) {
        ss = brsum(ss, sh);
        if (t == 0) cwgt[blockIdx.x] = expf(-alpha_ptr[0] * sqrtf(ss));
    }
}

// ---------------- Qg = Q*cos(ph[h]) - V*sin(ph[h]) ----------------
__global__ void __launch_bounds__(256) qg_kernel(
    const float* __restrict__ Q, const float* __restrict__ V,
    const float* __restrict__ phase, float* __restrict__ Qg)
{
    int i = blockIdx.x * 256 + threadIdx.x;
    if (i >= NELT) return;
    int h = (i & (DD - 1)) >> 6;
    float p = phase[h];
    Qg[i] = Q[i] * cosf(p) - V[i] * sinf(p);
}

// ---------------- host helpers ----------------
template<int BN, bool ATTN, int MODE>
static void run_gemm(const float* A, const float* B, float* C, float* Aout, float* rowsum,
    int M, int N, int K, int lda, int ldb, int ldc,
    int batch, int batchH,
    long long sAb, long long sAh, long long sBb, long long sBh,
    long long sCb, long long sCh,
    float scale, const float* bias, const float* res,
    const float* h2p, const float* cwgt, const float* betap)
{
    int smem = 3 * (128 + BN) * SPAD * 4;
    cudaFuncSetAttribute(tc_gemm<BN, ATTN, MODE>,
                         cudaFuncAttributeMaxDynamicSharedMemorySize, smem);
    dim3 grid(N / BN, M / 128, batch);
    tc_gemm<BN, ATTN, MODE><<<grid, 256, smem>>>(
        A, B, C, Aout, rowsum, M, K, lda, ldb, ldc,
        batchH, sAb, sAh, sBb, sBh, sCb, sCh,
        scale, bias, res, h2p, cwgt, betap);
}

static void launch_tr(const float* in, float* out, int R, int C, int ldi, int ldo,
    int batch, int batchH, long long sIb, long long sIh, long long sOb, long long sOh)
{
    dim3 grid((C + 31) / 32, (R + 31) / 32, batch);
    transpose_kernel<<<grid, 256>>>(in, out, R, C, ldi, ldo, batchH, sIb, sIh, sOb, sOh);
}

extern "C" void kernel_launch(void* const* d_in, const int* in_sizes, int n_in,
                              void* d_out, int out_size)
{
    const float* x     = (const float*)d_in[0];
    const float* wq    = (const float*)d_in[1];
    const float* wk    = (const float*)d_in[2];
    const float* wv    = (const float*)d_in[3];
    const float* wo    = (const float*)d_in[4];
    const float* phase = (const float*)d_in[5];
    const float* cw1   = (const float*)d_in[6];
    const float* cb1   = (const float*)d_in[7];
    const float* cw2   = (const float*)d_in[8];
    const float* cb2   = (const float*)d_in[9];
    const float* alpha = (const float*)d_in[10];
    const float* beta  = (const float*)d_in[11];
    const float* fw1   = (const float*)d_in[12];
    const float* fb1   = (const float*)d_in[13];
    const float* fw2   = (const float*)d_in[14];
    const float* fb2   = (const float*)d_in[15];
    const float* ln1g  = (const float*)d_in[16];
    const float* ln1b  = (const float*)d_in[17];
    const float* ln2g  = (const float*)d_in[18];
    const float* ln2b  = (const float*)d_in[19];
    const float* ln3g  = (const float*)d_in[20];
    const float* ln3b  = (const float*)d_in[21];

    static float *p_h=0,*p_Q=0,*p_K=0,*p_V=0,*p_Qg=0,*p_VT=0,*p_ctx=0,*p_x1=0,
                 *p_h2=0,*p_x2=0,*p_t1=0,*p_ff1=0,*p_cwgt=0,*p_rowsum=0,*p_attn_fb=0,
                 *p_wqT=0,*p_wkT=0,*p_wvT=0,*p_woT=0,*p_cw1T=0,*p_cw2T=0,
                 *p_fw1T=0,*p_fw2T=0;
    if (!p_h) {
        cudaGetSymbolAddress((void**)&p_h,    g_h);
        cudaGetSymbolAddress((void**)&p_Q,    g_Q);
        cudaGetSymbolAddress((void**)&p_K,    g_K);
        cudaGetSymbolAddress((void**)&p_V,    g_V);
        cudaGetSymbolAddress((void**)&p_Qg,   g_Qg);
        cudaGetSymbolAddress((void**)&p_VT,   g_VT);
        cudaGetSymbolAddress((void**)&p_ctx,  g_ctx);
        cudaGetSymbolAddress((void**)&p_x1,   g_x1);
        cudaGetSymbolAddress((void**)&p_h2,   g_h2);
        cudaGetSymbolAddress((void**)&p_x2,   g_x2);
        cudaGetSymbolAddress((void**)&p_t1,   g_t1);
        cudaGetSymbolAddress((void**)&p_ff1,  g_ff1);
        cudaGetSymbolAddress((void**)&p_cwgt, g_cwgt);
        cudaGetSymbolAddress((void**)&p_rowsum, g_rowsum);
        cudaGetSymbolAddress((void**)&p_attn_fb, g_attn_fb);
        cudaGetSymbolAddress((void**)&p_wqT,  g_wqT);
        cudaGetSymbolAddress((void**)&p_wkT,  g_wkT);
        cudaGetSymbolAddress((void**)&p_wvT,  g_wvT);
        cudaGetSymbolAddress((void**)&p_woT,  g_woT);
        cudaGetSymbolAddress((void**)&p_cw1T, g_cw1T);
        cudaGetSymbolAddress((void**)&p_cw2T, g_cw2T);
        cudaGetSymbolAddress((void**)&p_fw1T, g_fw1T);
        cudaGetSymbolAddress((void**)&p_fw2T, g_fw2T);
    }

    float* out_x = (float*)d_out;
    long long need = (long long)NELT + ASZ;
    float* attn = ((long long)out_size >= need) ? (out_x + NELT) : p_attn_fb;

    // weight transposes (W[K,N] -> WT[N,K])
    launch_tr(wq,  p_wqT,  DD,   DD,  DD,   DD,   1, 1, 0,0,0,0);
    launch_tr(wk,  p_wkT,  DD,   DD,  DD,   DD,   1, 1, 0,0,0,0);
    launch_tr(wv,  p_wvT,  DD,   DD,  DD,   DD,   1, 1, 0,0,0,0);
    launch_tr(wo,  p_woT,  DD,   DD,  DD,   DD,   1, 1, 0,0,0,0);
    launch_tr(cw1, p_cw1T, DD,   2*DD, 2*DD, DD,  1, 1, 0,0,0,0);
    launch_tr(cw2, p_cw2T, 2*DD, DD,  DD,   2*DD, 1, 1, 0,0,0,0);
    launch_tr(fw1, p_fw1T, DD,   FFN, FFN,  DD,   1, 1, 0,0,0,0);
    launch_tr(fw2, p_fw2T, FFN,  DD,  DD,   FFN,  1, 1, 0,0,0,0);

    // 0) zero row sums
    zero_kernel<<<(NROWS + 255) / 256, 256>>>(p_rowsum, NROWS);

    // 1) h = LN1(x)
    ln_kernel<<<NTOK, 256>>>(x, p_h, ln1g, ln1b, nullptr, nullptr);

    // 2) Q,K,V
    run_gemm<128,false,1>(p_h, p_wqT, p_Q, 0, 0, NTOK, DD, DD, DD, DD, DD,
                          1,1, 0,0,0,0,0,0, 1.f, 0,0,0,0,0);
    run_gemm<128,false,1>(p_h, p_wkT, p_K, 0, 0, NTOK, DD, DD, DD, DD, DD,
                          1,1, 0,0,0,0,0,0, 1.f, 0,0,0,0,0);
    run_gemm<128,false,1>(p_h, p_wvT, p_V, 0, 0, NTOK, DD, DD, DD, DD, DD,
                          1,1, 0,0,0,0,0,0, 1.f, 0,0,0,0,0);

    // 3) Qg
    qg_kernel<<<(NELT + 255) / 256, 256>>>(p_Q, p_V, phase, p_Qg);

    // 3b) VT[b,h,d,s] = V[b,s,h,d]
    launch_tr(p_V, p_VT, SS, DKK, DD, SS,
              BB * HH, HH,
              (long long)SS * DD, DKK,
              (long long)HH * DKK * SS, (long long)DKK * SS);

    // 4) e = exp(Qg @ K^T / 8)  + row sums (unnormalized, into scratch)
    run_gemm<128,false,5>(p_Qg, p_K, p_attn_fb, 0, p_rowsum,
                          SS, SS, DKK, DD, DD, SS,
                          BB * HH, HH,
                          (long long)SS * DD, DKK,
                          (long long)SS * DD, DKK,
                          (long long)HH * SS * SS, (long long)SS * SS,
                          0.125f, 0,0,0,0,0);

    // 5+6) ctx = (e/rowsum) @ V  — also streams normalized attn_weights to output
    run_gemm<64,true,6>(p_attn_fb, p_VT, p_ctx, attn, p_rowsum,
                        SS, DKK, SS, SS, SS, DD,
                        BB * HH, HH,
                        (long long)HH * SS * SS, (long long)SS * SS,
                        (long long)HH * DKK * SS, (long long)DKK * SS,
                        (long long)SS * DD, DKK,
                        1.f, 0,0,0,0,0);

    // 7) x1 = x + ctx @ wo
    run_gemm<128,false,3>(p_ctx, p_woT, p_x1, 0, 0, NTOK, DD, DD, DD, DD, DD,
                          1,1, 0,0,0,0,0,0, 1.f, 0, x, 0,0,0);

    // 8) h2 = LN2(x1) + cwgt
    ln_kernel<<<NTOK, 256>>>(p_x1, p_h2, ln2g, ln2b, p_cwgt, alpha);

    // 9) t1 = gelu(h2 @ cw1 + cb1)
    run_gemm<128,false,2>(p_h2, p_cw1T, p_t1, 0, 0, NTOK, 2*DD, DD, DD, DD, 2*DD,
                          1,1, 0,0,0,0,0,0, 1.f, cb1, 0,0,0,0);

    // 10) x2 = x1 + beta*h2 + cwgt*(t1 @ cw2 + cb2)
    run_gemm<128,false,4>(p_t1, p_cw2T, p_x2, 0, 0, NTOK, DD, 2*DD, 2*DD, 2*DD, DD,
                          1,1, 0,0,0,0,0,0, 1.f, cb2, p_x1, p_h2, p_cwgt, beta);

    // 11) h3 = LN3(x2)
    ln_kernel<<<NTOK, 256>>>(p_x2, p_h, ln3g, ln3b, nullptr, nullptr);

    // 12) ff1 = gelu(h3 @ fw1 + fb1)
    run_gemm<128,false,2>(p_h, p_fw1T, p_ff1, 0, 0, NTOK, FFN, DD, DD, DD, FFN,
                          1,1, 0,0,0,0,0,0, 1.f, fb1, 0,0,0,0);

    // 13) out = x2 + ff1 @ fw2 + fb2
    run_gemm<128,false,3>(p_ff1, p_fw2T, out_x, 0, 0, NTOK, DD, FFN, FFN, FFN, DD,
                          1,1, 0,0,0,0,0,0, 1.f, fb2, p_x2, 0,0,0);
}

// round 8
// speedup vs baseline: 3.6303x; 1.0628x over previous
#include <cuda_runtime.h>
#include <math.h>
#include <stdint.h>

// ---------------- problem constants ----------------
#define BB   4
#define SS   2048
#define DD   1024
#define HH   16
#define DKK  64
#define FFN  4096
#define NTOK (BB*SS)
#define NELT (NTOK*DD)
#define ASZ  ((long long)BB*HH*SS*SS)
#define NROWS (BB*HH*SS)

#define SPAD 20   // smem row stride (floats): conflict-free frags, rows 16B-aligned

// ---------------- scratch (device globals) ----------------
__device__ float g_h  [NELT];
__device__ float g_Q  [NELT];
__device__ float g_K  [NELT];
__device__ float g_V  [NELT];
__device__ float g_Qg [NELT];
__device__ float g_VT [NELT];
__device__ float g_ctx[NELT];
__device__ float g_x1 [NELT];
__device__ float g_h2 [NELT];
__device__ float g_x2 [NELT];
__device__ float g_t1 [NTOK*2*DD];
__device__ float g_ff1[NTOK*FFN];
__device__ float g_cwgt[NTOK];
__device__ float g_rowsum[NROWS];
__device__ float g_wqT [DD*DD];
__device__ float g_wkT [DD*DD];
__device__ float g_wvT [DD*DD];
__device__ float g_woT [DD*DD];
__device__ float g_cw1T[DD*2*DD];
__device__ float g_cw2T[2*DD*DD];
__device__ float g_fw1T[DD*FFN];
__device__ float g_fw2T[DD*FFN];
__device__ float g_attn_fb[(size_t)ASZ];   // unnormalized exp(scores)

// ---------------- helpers ----------------
__device__ __forceinline__ uint32_t smem_u32(const void* p) {
    uint32_t a;
    asm("{ .reg .u64 t; cvta.to.shared.u64 t, %1; cvt.u32.u64 %0, t; }"
        : "=r"(a) : "l"(p));
    return a;
}
__device__ __forceinline__ uint32_t f2tf32(float x) {
    uint32_t u;
    asm("cvt.rna.tf32.f32 %0, %1;" : "=r"(u) : "f"(x));
    return u;
}
__device__ __forceinline__ float geluf(float x) {
    return 0.5f * x * (1.0f + erff(x * 0.70710678118654752f));
}
__device__ __forceinline__ void mma_tf32(float* d, const uint32_t* a, const uint32_t* b) {
    asm volatile(
        "mma.sync.aligned.m16n8k8.row.col.f32.tf32.tf32.f32 "
        "{%0,%1,%2,%3}, {%4,%5,%6,%7}, {%8,%9}, {%0,%1,%2,%3};"
        : "+f"(d[0]), "+f"(d[1]), "+f"(d[2]), "+f"(d[3])
        : "r"(a[0]), "r"(a[1]), "r"(a[2]), "r"(a[3]), "r"(b[0]), "r"(b[1]));
}
__device__ __forceinline__ void cp16(uint32_t dst, const void* src) {
    asm volatile("cp.async.cg.shared.global [%0], [%1], 16;"
                 :: "r"(dst), "l"(src) : "memory");
}
#define CP_COMMIT() asm volatile("cp.async.commit_group;" ::: "memory")
#define CP_WAIT1()  asm volatile("cp.async.wait_group 1;" ::: "memory")

// ---------------- templated tensor-core tf32 GEMM ----------------
// C = A[M,K] @ B[N,K]^T; K-chunk 16, 3-stage cp.async pipeline; 8 warps, 256 thr.
// Warp grid: WN = BN/64 (each warp covers 64 N-cols), WM = BM/(MT*16).
// MODE: 1 = acc                    2 = gelu(acc+bias)
//       3 = res + acc (+bias)      4 = res + beta*h2 + cwgt[m]*(acc+bias)
//       5 = e=exp(acc*scale), write e, atomic row sums
//       6 = acc * inv_rowsum[m]  (ctx; ATTN=true also streams normalized attn)
template<int BM, int BN, int MT, bool ATTN, int MODE>
__global__ void __launch_bounds__(256) tc_gemm(
    const float* __restrict__ A, const float* __restrict__ B,
    float* __restrict__ C, float* __restrict__ Aout, float* __restrict__ rowsum,
    int M, int K, int lda, int ldb, int ldc,
    int batchH, long long sAb, long long sAh, long long sBb, long long sBh,
    long long sCb, long long sCh,
    float scale, const float* __restrict__ bias, const float* __restrict__ res,
    const float* __restrict__ h2p, const float* __restrict__ cwgt,
    const float* __restrict__ beta_ptr)
{
    constexpr int WN  = BN / 64;
    constexpr int AI  = BM / 64;            // A cp16s per thread per chunk
    constexpr int BI  = BN / 64;            // B cp16s per thread per chunk
    constexpr int STG = (BM + BN) * SPAD;   // uint32s per stage

    extern __shared__ uint32_t sm[];
    uint32_t sbase = smem_u32(sm);

    int z = blockIdx.z;
    int zb = z / batchH, zh = z - zb * batchH;
    A += (long long)zb * sAb + (long long)zh * sAh;
    B += (long long)zb * sBb + (long long)zh * sBh;
    C += (long long)zb * sCb + (long long)zh * sCh;

    int tid = threadIdx.x;
    int wid = tid >> 5, lane = tid & 31;
    int wm = wid / WN, wn = wid % WN;
    int g = lane >> 2, t = lane & 3;
    int m0 = blockIdx.y * BM, n0 = blockIdx.x * BN;

    float acc[MT][8][4];
    #pragma unroll
    for (int i = 0; i < MT; i++)
        #pragma unroll
        for (int j = 0; j < 8; j++)
            #pragma unroll
            for (int q = 0; q < 4; q++) acc[i][j][q] = 0.f;

    int lr0 = tid >> 2, lc0 = (tid & 3) * 4;
    const float* Ag = A + (long long)(m0 + lr0) * lda + lc0;
    const float* Bg = B + (long long)(n0 + lr0) * ldb + lc0;
    int NC = K >> 4;

    float invL[AI];
    float* AoutB = nullptr;
    if (ATTN) {
        const float* rs = rowsum + (long long)z * M;
        #pragma unroll
        for (int i = 0; i < AI; i++) invL[i] = 1.f / rs[m0 + lr0 + i * 64];
        AoutB = Aout + (long long)zb * sAb + (long long)zh * sAh;
    }

    auto issue = [&](int c) {
        int s = c % 3;
        uint32_t ab = sbase + (uint32_t)(s * STG) * 4u;
        uint32_t bb = ab + (uint32_t)(BM * SPAD) * 4u;
        const float* Ap = Ag + c * 16;
        #pragma unroll
        for (int i = 0; i < AI; i++)
            cp16(ab + (uint32_t)((lr0 + i * 64) * SPAD + lc0) * 4u,
                 Ap + (long long)(i * 64) * lda);
        const float* Bp = Bg + c * 16;
        #pragma unroll
        for (int i = 0; i < BI; i++)
            cp16(bb + (uint32_t)((lr0 + i * 64) * SPAD + lc0) * 4u,
                 Bp + (long long)(i * 64) * ldb);
    };

    issue(0); CP_COMMIT();
    issue(1); CP_COMMIT();

    for (int c = 0; c < NC; c++) {
        int s = c % 3;
        uint32_t* stA = sm + s * STG;
        uint32_t* stB = stA + BM * SPAD;

        CP_WAIT1();
        __syncthreads();

        if (ATTN) {   // stream normalized attention weights out of smem
            #pragma unroll
            for (int i = 0; i < AI; i++) {
                float4 e = *reinterpret_cast<float4*>(&stA[(lr0 + i * 64) * SPAD + lc0]);
                e.x *= invL[i]; e.y *= invL[i]; e.z *= invL[i]; e.w *= invL[i];
                *reinterpret_cast<float4*>(
                    AoutB + (long long)(m0 + lr0 + i * 64) * lda + c * 16 + lc0) = e;
            }
        }

        if (c + 2 < NC) issue(c + 2);
        CP_COMMIT();

        #pragma unroll
        for (int ks = 0; ks < 2; ks++) {
            int kk = ks * 8;
            uint32_t af[MT][4], bf[8][2];
            #pragma unroll
            for (int mt = 0; mt < MT; mt++) {
                int row = wm * (MT * 16) + mt * 16 + g;
                af[mt][0] = f2tf32(__uint_as_float(stA[row * SPAD + kk + t]));
                af[mt][1] = f2tf32(__uint_as_float(stA[(row + 8) * SPAD + kk + t]));
                af[mt][2] = f2tf32(__uint_as_float(stA[row * SPAD + kk + t + 4]));
                af[mt][3] = f2tf32(__uint_as_float(stA[(row + 8) * SPAD + kk + t + 4]));
            }
            #pragma unroll
            for (int nt = 0; nt < 8; nt++) {
                int col = wn * 64 + nt * 8 + g;
                bf[nt][0] = f2tf32(__uint_as_float(stB[col * SPAD + kk + t]));
                bf[nt][1] = f2tf32(__uint_as_float(stB[col * SPAD + kk + t + 4]));
            }
            #pragma unroll
            for (int mt = 0; mt < MT; mt++)
                #pragma unroll
                for (int nt = 0; nt < 8; nt++)
                    mma_tf32(acc[mt][nt], af[mt], bf[nt]);
        }
    }

    // ---------------- epilogue ----------------
    float betav = (MODE == 4) ? beta_ptr[0] : 0.f;
    const float* rsE = (MODE == 6) ? rowsum + (long long)z * M : nullptr;
    float* rsA = (MODE == 5) ? rowsum + (long long)z * M : nullptr;

    #pragma unroll
    for (int mt = 0; mt < MT; mt++) {
        int r0 = m0 + wm * (MT * 16) + mt * 16 + g;
        int r1 = r0 + 8;
        float cw0 = 0.f, cw1 = 0.f, inv0 = 0.f, inv1 = 0.f;
        if (MODE == 4) { cw0 = cwgt[r0]; cw1 = cwgt[r1]; }
        if (MODE == 6) { inv0 = 1.f / rsE[r0]; inv1 = 1.f / rsE[r1]; }
        float s0 = 0.f, s1 = 0.f;
        #pragma unroll
        for (int nt = 0; nt < 8; nt++) {
            int n = n0 + wn * 64 + nt * 8 + 2 * t;
            long long co0 = (long long)r0 * ldc + n;
            long long co1 = (long long)r1 * ldc + n;
            float v00 = acc[mt][nt][0], v01 = acc[mt][nt][1];
            float v10 = acc[mt][nt][2], v11 = acc[mt][nt][3];
            float2 o0, o1;
            if (MODE == 1) {
                o0 = make_float2(v00, v01);
                o1 = make_float2(v10, v11);
            } else if (MODE == 2) {
                float b0 = bias[n], b1 = bias[n + 1];
                o0 = make_float2(geluf(v00 + b0), geluf(v01 + b1));
                o1 = make_float2(geluf(v10 + b0), geluf(v11 + b1));
            } else if (MODE == 3) {
                float b0 = bias ? bias[n] : 0.f, b1 = bias ? bias[n + 1] : 0.f;
                float2 q0 = *reinterpret_cast<const float2*>(res + co0);
                float2 q1 = *reinterpret_cast<const float2*>(res + co1);
                o0 = make_float2(q0.x + v00 + b0, q0.y + v01 + b1);
                o1 = make_float2(q1.x + v10 + b0, q1.y + v11 + b1);
            } else if (MODE == 4) {
                float b0 = bias[n], b1 = bias[n + 1];
                float2 q0 = *reinterpret_cast<const float2*>(res + co0);
                float2 q1 = *reinterpret_cast<const float2*>(res + co1);
                float2 h0 = *reinterpret_cast<const float2*>(h2p + co0);
                float2 h1 = *reinterpret_cast<const float2*>(h2p + co1);
                o0 = make_float2(q0.x + betav * h0.x + cw0 * (v00 + b0),
                                 q0.y + betav * h0.y + cw0 * (v01 + b1));
                o1 = make_float2(q1.x + betav * h1.x + cw1 * (v10 + b0),
                                 q1.y + betav * h1.y + cw1 * (v11 + b1));
            } else if (MODE == 5) {
                float e00 = __expf(v00 * scale), e01 = __expf(v01 * scale);
                float e10 = __expf(v10 * scale), e11 = __expf(v11 * scale);
                o0 = make_float2(e00, e01);
                o1 = make_float2(e10, e11);
                s0 += e00 + e01; s1 += e10 + e11;
            } else { // MODE == 6
                o0 = make_float2(v00 * inv0, v01 * inv0);
                o1 = make_float2(v10 * inv1, v11 * inv1);
            }
            *reinterpret_cast<float2*>(C + co0) = o0;
            *reinterpret_cast<float2*>(C + co1) = o1;
        }
        if (MODE == 5) {
            s0 += __shfl_xor_sync(0xffffffffu, s0, 1);
            s0 += __shfl_xor_sync(0xffffffffu, s0, 2);
            s1 += __shfl_xor_sync(0xffffffffu, s1, 1);
            s1 += __shfl_xor_sync(0xffffffffu, s1, 2);
            if (t == 0) {
                atomicAdd(rsA + r0, s0);
                atomicAdd(rsA + r1, s1);
            }
        }
    }
}

// ---------------- zero kernel (row sums) ----------------
__global__ void __launch_bounds__(256) zero_kernel(float* p, int n) {
    int i = blockIdx.x * 256 + threadIdx.x;
    if (i < n) p[i] = 0.f;
}

// ---------------- transpose ----------------
__global__ void __launch_bounds__(256) transpose_kernel(
    const float* __restrict__ in, float* __restrict__ out,
    int R, int C, int ldi, int ldo,
    int batchH, long long sIb, long long sIh, long long sOb, long long sOh)
{
    __shared__ float tile[32][33];
    int z = blockIdx.z;
    int zb = z / batchH, zh = z - zb * batchH;
    in  += (long long)zb * sIb + (long long)zh * sIh;
    out += (long long)zb * sOb + (long long)zh * sOh;
    int r0 = blockIdx.y * 32, c0 = blockIdx.x * 32;
    int tx = threadIdx.x & 31, ty = threadIdx.x >> 5;
    #pragma unroll
    for (int i = 0; i < 4; i++) {
        int r = r0 + ty + i * 8, c = c0 + tx;
        if (r < R && c < C) tile[ty + i * 8][tx] = in[(long long)r * ldi + c];
    }
    __syncthreads();
    #pragma unroll
    for (int i = 0; i < 4; i++) {
        int c = c0 + ty + i * 8, r = r0 + tx;
        if (r < R && c < C) out[(long long)c * ldo + r] = tile[tx][ty + i * 8];
    }
}

// ---------------- layernorm ----------------
__device__ __forceinline__ float brsum(float v, float* sh) {
    int t = threadIdx.x;
    sh[t] = v; __syncthreads();
    #pragma unroll
    for (int s = 128; s > 0; s >>= 1) { if (t < s) sh[t] += sh[t + s]; __syncthreads(); }
    float r = sh[0]; __syncthreads();
    return r;
}

__global__ void __launch_bounds__(256) ln_kernel(
    const float* __restrict__ x, float* __restrict__ y,
    const float* __restrict__ g, const float* __restrict__ b,
    float* __restrict__ cwgt, const float* __restrict__ alpha_ptr)
{
    long long base = (long long)blockIdx.x * DD;
    int t = threadIdx.x;
    __shared__ float sh[256];
    float xv[4];
    float s = 0.f;
    #pragma unroll
    for (int i = 0; i < 4; i++) { xv[i] = x[base + t + i * 256]; s += xv[i]; }
    s = brsum(s, sh);
    float mu = s * (1.0f / DD);
    float vs = 0.f;
    #pragma unroll
    for (int i = 0; i < 4; i++) { float d = xv[i] - mu; vs += d * d; }
    vs = brsum(vs, sh);
    float inv = rsqrtf(vs * (1.0f / DD) + 1e-5f);
    float ss = 0.f;
    #pragma unroll
    for (int i = 0; i < 4; i++) {
        int c = t + i * 256;
        float yv = (xv[i] - mu) * inv * g[c] + b[c];
        y[base + c] = yv;
        ss += yv * yv;
    }
    if (cwgt) {
        ss = brsum(ss, sh);
        if (t == 0) cwgt[blockIdx.x] = expf(-alpha_ptr[0] * sqrtf(ss));
    }
}

// ---------------- Qg = Q*cos(ph[h]) - V*sin(ph[h]) ----------------
__global__ void __launch_bounds__(256) qg_kernel(
    const float* __restrict__ Q, const float* __restrict__ V,
    const float* __restrict__ phase, float* __restrict__ Qg)
{
    int i = blockIdx.x * 256 + threadIdx.x;
    if (i >= NELT) return;
    int h = (i & (DD - 1)) >> 6;
    float p = phase[h];
    Qg[i] = Q[i] * cosf(p) - V[i] * sinf(p);
}

// ---------------- host helpers ----------------
template<int BM, int BN, int MT, bool ATTN, int MODE>
static void run_gemm(const float* A, const float* B, float* C, float* Aout, float* rowsum,
    int M, int N, int K, int lda, int ldb, int ldc,
    int batch, int batchH,
    long long sAb, long long sAh, long long sBb, long long sBh,
    long long sCb, long long sCh,
    float scale, const float* bias, const float* res,
    const float* h2p, const float* cwgt, const float* betap)
{
    int smem = 3 * (BM + BN) * SPAD * 4;
    cudaFuncSetAttribute(tc_gemm<BM, BN, MT, ATTN, MODE>,
                         cudaFuncAttributeMaxDynamicSharedMemorySize, smem);
    dim3 grid(N / BN, M / BM, batch);
    tc_gemm<BM, BN, MT, ATTN, MODE><<<grid, 256, smem>>>(
        A, B, C, Aout, rowsum, M, K, lda, ldb, ldc,
        batchH, sAb, sAh, sBb, sBh, sCb, sCh,
        scale, bias, res, h2p, cwgt, betap);
}

static void launch_tr(const float* in, float* out, int R, int C, int ldi, int ldo,
    int batch, int batchH, long long sIb, long long sIh, long long sOb, long long sOh)
{
    dim3 grid((C + 31) / 32, (R + 31) / 32, batch);
    transpose_kernel<<<grid, 256>>>(in, out, R, C, ldi, ldo, batchH, sIb, sIh, sOb, sOh);
}

extern "C" void kernel_launch(void* const* d_in, const int* in_sizes, int n_in,
                              void* d_out, int out_size)
{
    const float* x     = (const float*)d_in[0];
    const float* wq    = (const float*)d_in[1];
    const float* wk    = (const float*)d_in[2];
    const float* wv    = (const float*)d_in[3];
    const float* wo    = (const float*)d_in[4];
    const float* phase = (const float*)d_in[5];
    const float* cw1   = (const float*)d_in[6];
    const float* cb1   = (const float*)d_in[7];
    const float* cw2   = (const float*)d_in[8];
    const float* cb2   = (const float*)d_in[9];
    const float* alpha = (const float*)d_in[10];
    const float* beta  = (const float*)d_in[11];
    const float* fw1   = (const float*)d_in[12];
    const float* fb1   = (const float*)d_in[13];
    const float* fw2   = (const float*)d_in[14];
    const float* fb2   = (const float*)d_in[15];
    const float* ln1g  = (const float*)d_in[16];
    const float* ln1b  = (const float*)d_in[17];
    const float* ln2g  = (const float*)d_in[18];
    const float* ln2b  = (const float*)d_in[19];
    const float* ln3g  = (const float*)d_in[20];
    const float* ln3b  = (const float*)d_in[21];

    static float *p_h=0,*p_Q=0,*p_K=0,*p_V=0,*p_Qg=0,*p_VT=0,*p_ctx=0,*p_x1=0,
                 *p_h2=0,*p_x2=0,*p_t1=0,*p_ff1=0,*p_cwgt=0,*p_rowsum=0,*p_attn_fb=0,
                 *p_wqT=0,*p_wkT=0,*p_wvT=0,*p_woT=0,*p_cw1T=0,*p_cw2T=0,
                 *p_fw1T=0,*p_fw2T=0;
    if (!p_h) {
        cudaGetSymbolAddress((void**)&p_h,    g_h);
        cudaGetSymbolAddress((void**)&p_Q,    g_Q);
        cudaGetSymbolAddress((void**)&p_K,    g_K);
        cudaGetSymbolAddress((void**)&p_V,    g_V);
        cudaGetSymbolAddress((void**)&p_Qg,   g_Qg);
        cudaGetSymbolAddress((void**)&p_VT,   g_VT);
        cudaGetSymbolAddress((void**)&p_ctx,  g_ctx);
        cudaGetSymbolAddress((void**)&p_x1,   g_x1);
        cudaGetSymbolAddress((void**)&p_h2,   g_h2);
        cudaGetSymbolAddress((void**)&p_x2,   g_x2);
        cudaGetSymbolAddress((void**)&p_t1,   g_t1);
        cudaGetSymbolAddress((void**)&p_ff1,  g_ff1);
        cudaGetSymbolAddress((void**)&p_cwgt, g_cwgt);
        cudaGetSymbolAddress((void**)&p_rowsum, g_rowsum);
        cudaGetSymbolAddress((void**)&p_attn_fb, g_attn_fb);
        cudaGetSymbolAddress((void**)&p_wqT,  g_wqT);
        cudaGetSymbolAddress((void**)&p_wkT,  g_wkT);
        cudaGetSymbolAddress((void**)&p_wvT,  g_wvT);
        cudaGetSymbolAddress((void**)&p_woT,  g_woT);
        cudaGetSymbolAddress((void**)&p_cw1T, g_cw1T);
        cudaGetSymbolAddress((void**)&p_cw2T, g_cw2T);
        cudaGetSymbolAddress((void**)&p_fw1T, g_fw1T);
        cudaGetSymbolAddress((void**)&p_fw2T, g_fw2T);
    }

    float* out_x = (float*)d_out;
    long long need = (long long)NELT + ASZ;
    float* attn = ((long long)out_size >= need) ? (out_x + NELT) : p_attn_fb;

    // weight transposes (W[K,N] -> WT[N,K])
    launch_tr(wq,  p_wqT,  DD,   DD,  DD,   DD,   1, 1, 0,0,0,0);
    launch_tr(wk,  p_wkT,  DD,   DD,  DD,   DD,   1, 1, 0,0,0,0);
    launch_tr(wv,  p_wvT,  DD,   DD,  DD,   DD,   1, 1, 0,0,0,0);
    launch_tr(wo,  p_woT,  DD,   DD,  DD,   DD,   1, 1, 0,0,0,0);
    launch_tr(cw1, p_cw1T, DD,   2*DD, 2*DD, DD,  1, 1, 0,0,0,0);
    launch_tr(cw2, p_cw2T, 2*DD, DD,  DD,   2*DD, 1, 1, 0,0,0,0);
    launch_tr(fw1, p_fw1T, DD,   FFN, FFN,  DD,   1, 1, 0,0,0,0);
    launch_tr(fw2, p_fw2T, FFN,  DD,  DD,   FFN,  1, 1, 0,0,0,0);

    // 0) zero row sums
    zero_kernel<<<(NROWS + 255) / 256, 256>>>(p_rowsum, NROWS);

    // 1) h = LN1(x)
    ln_kernel<<<NTOK, 256>>>(x, p_h, ln1g, ln1b, nullptr, nullptr);

    // 2) Q,K,V
    run_gemm<256,128,4,false,1>(p_h, p_wqT, p_Q, 0, 0, NTOK, DD, DD, DD, DD, DD,
                                1,1, 0,0,0,0,0,0, 1.f, 0,0,0,0,0);
    run_gemm<256,128,4,false,1>(p_h, p_wkT, p_K, 0, 0, NTOK, DD, DD, DD, DD, DD,
                                1,1, 0,0,0,0,0,0, 1.f, 0,0,0,0,0);
    run_gemm<256,128,4,false,1>(p_h, p_wvT, p_V, 0, 0, NTOK, DD, DD, DD, DD, DD,
                                1,1, 0,0,0,0,0,0, 1.f, 0,0,0,0,0);

    // 3) Qg
    qg_kernel<<<(NELT + 255) / 256, 256>>>(p_Q, p_V, phase, p_Qg);

    // 3b) VT[b,h,d,s] = V[b,s,h,d]
    launch_tr(p_V, p_VT, SS, DKK, DD, SS,
              BB * HH, HH,
              (long long)SS * DD, DKK,
              (long long)HH * DKK * SS, (long long)DKK * SS);

    // 4) e = exp(Qg @ K^T / 8)  + row sums (unnormalized, into scratch)
    run_gemm<256,128,4,false,5>(p_Qg, p_K, p_attn_fb, 0, p_rowsum,
                                SS, SS, DKK, DD, DD, SS,
                                BB * HH, HH,
                                (long long)SS * DD, DKK,
                                (long long)SS * DD, DKK,
                                (long long)HH * SS * SS, (long long)SS * SS,
                                0.125f, 0,0,0,0,0);

    // 5+6) ctx = (e/rowsum) @ V  — streams normalized attn_weights to output
    run_gemm<128,64,1,true,6>(p_attn_fb, p_VT, p_ctx, attn, p_rowsum,
                              SS, DKK, SS, SS, SS, DD,
                              BB * HH, HH,
                              (long long)HH * SS * SS, (long long)SS * SS,
                              (long long)HH * DKK * SS, (long long)DKK * SS,
                              (long long)SS * DD, DKK,
                              1.f, 0,0,0,0,0);

    // 7) x1 = x + ctx @ wo
    run_gemm<256,128,4,false,3>(p_ctx, p_woT, p_x1, 0, 0, NTOK, DD, DD, DD, DD, DD,
                                1,1, 0,0,0,0,0,0, 1.f, 0, x, 0,0,0);

    // 8) h2 = LN2(x1) + cwgt
    ln_kernel<<<NTOK, 256>>>(p_x1, p_h2, ln2g, ln2b, p_cwgt, alpha);

    // 9) t1 = gelu(h2 @ cw1 + cb1)
    run_gemm<256,128,4,false,2>(p_h2, p_cw1T, p_t1, 0, 0, NTOK, 2*DD, DD, DD, DD, 2*DD,
                                1,1, 0,0,0,0,0,0, 1.f, cb1, 0,0,0,0);

    // 10) x2 = x1 + beta*h2 + cwgt*(t1 @ cw2 + cb2)
    run_gemm<256,128,4,false,4>(p_t1, p_cw2T, p_x2, 0, 0, NTOK, DD, 2*DD, 2*DD, 2*DD, DD,
                                1,1, 0,0,0,0,0,0, 1.f, cb2, p_x1, p_h2, p_cwgt, beta);

    // 11) h3 = LN3(x2)
    ln_kernel<<<NTOK, 256>>>(p_x2, p_h, ln3g, ln3b, nullptr, nullptr);

    // 12) ff1 = gelu(h3 @ fw1 + fb1)
    run_gemm<256,128,4,false,2>(p_h, p_fw1T, p_ff1, 0, 0, NTOK, FFN, DD, DD, DD, FFN,
                                1,1, 0,0,0,0,0,0, 1.f, fb1, 0,0,0,0);

    // 13) out = x2 + ff1 @ fw2 + fb2
    run_gemm<256,128,4,false,3>(p_ff1, p_fw2T, out_x, 0, 0, NTOK, DD, FFN, FFN, FFN, DD,
                                1,1, 0,0,0,0,0,0, 1.f, fb2, p_x2, 0,0,0);
}

// round 9
// speedup vs baseline: 3.7035x; 1.0202x over previous
#include <cuda_runtime.h>
#include <math.h>
#include <stdint.h>

// ---------------- problem constants ----------------
#define BB   4
#define SS   2048
#define DD   1024
#define HH   16
#define DKK  64
#define FFN  4096
#define NTOK (BB*SS)
#define NELT (NTOK*DD)
#define ASZ  ((long long)BB*HH*SS*SS)
#define NROWS (BB*HH*SS)

#define KC    32   // K-chunk
#define SPAD  36   // smem row stride (floats): 32 data + 4 pad; banks g*36+t ≡ g*4+t (mod 32)

// ---------------- scratch (device globals) ----------------
__device__ float g_h  [NELT];
__device__ float g_QKV[NTOK*3*DD];
__device__ float g_Qg [NELT];
__device__ float g_VT [NELT];
__device__ float g_ctx[NELT];
__device__ float g_x1 [NELT];
__device__ float g_h2 [NELT];
__device__ float g_x2 [NELT];
__device__ float g_t1 [NTOK*2*DD];
__device__ float g_ff1[NTOK*FFN];
__device__ float g_cwgt[NTOK];
__device__ float g_rowsum[NROWS];
__device__ float g_wqkvT[3*DD*DD];
__device__ float g_woT [DD*DD];
__device__ float g_cw1T[DD*2*DD];
__device__ float g_cw2T[2*DD*DD];
__device__ float g_fw1T[DD*FFN];
__device__ float g_fw2T[DD*FFN];
__device__ float g_attn_fb[(size_t)ASZ];   // unnormalized exp(scores)

// ---------------- helpers ----------------
__device__ __forceinline__ uint32_t smem_u32(const void* p) {
    uint32_t a;
    asm("{ .reg .u64 t; cvta.to.shared.u64 t, %1; cvt.u32.u64 %0, t; }"
        : "=r"(a) : "l"(p));
    return a;
}
__device__ __forceinline__ uint32_t f2tf32(float x) {
    uint32_t u;
    asm("cvt.rna.tf32.f32 %0, %1;" : "=r"(u) : "f"(x));
    return u;
}
__device__ __forceinline__ float geluf(float x) {
    return 0.5f * x * (1.0f + erff(x * 0.70710678118654752f));
}
__device__ __forceinline__ void mma_tf32(float* d, const uint32_t* a, const uint32_t* b) {
    asm volatile(
        "mma.sync.aligned.m16n8k8.row.col.f32.tf32.tf32.f32 "
        "{%0,%1,%2,%3}, {%4,%5,%6,%7}, {%8,%9}, {%0,%1,%2,%3};"
        : "+f"(d[0]), "+f"(d[1]), "+f"(d[2]), "+f"(d[3])
        : "r"(a[0]), "r"(a[1]), "r"(a[2]), "r"(a[3]), "r"(b[0]), "r"(b[1]));
}
__device__ __forceinline__ void cp16(uint32_t dst, const void* src) {
    asm volatile("cp.async.cg.shared.global [%0], [%1], 16;"
                 :: "r"(dst), "l"(src) : "memory");
}
#define CP_COMMIT() asm volatile("cp.async.commit_group;" ::: "memory")
#define CP_WAIT1()  asm volatile("cp.async.wait_group 1;" ::: "memory")

// ---------------- templated tensor-core tf32 GEMM ----------------
// C = A[M,K] @ B[N,K]^T; K-chunk 32, 3-stage cp.async pipeline; 8 warps, 256 thr.
// MODE: 1 = acc                    2 = gelu(acc+bias)
//       3 = res + acc (+bias)      4 = res + beta*h2 + cwgt[m]*(acc+bias)
//       5 = e=exp(acc*scale), write e, atomic row sums
//       6 = acc * inv_rowsum[m]  (ctx; ATTN=true also streams normalized attn)
template<int BM, int BN, int MT, bool ATTN, int MODE>
__global__ void __launch_bounds__(256) tc_gemm(
    const float* __restrict__ A, const float* __restrict__ B,
    float* __restrict__ C, float* __restrict__ Aout, float* __restrict__ rowsum,
    int M, int K, int lda, int ldb, int ldc,
    int batchH, long long sAb, long long sAh, long long sBb, long long sBh,
    long long sCb, long long sCh,
    float scale, const float* __restrict__ bias, const float* __restrict__ res,
    const float* __restrict__ h2p, const float* __restrict__ cwgt,
    const float* __restrict__ beta_ptr)
{
    constexpr int WN  = BN / 64;
    constexpr int AI  = BM / 64;            // 64-row groups of A
    constexpr int BI  = BN / 64;            // 64-row groups of B
    constexpr int STG = (BM + BN) * SPAD;   // uint32s per stage

    extern __shared__ uint32_t sm[];
    uint32_t sbase = smem_u32(sm);

    int z = blockIdx.z;
    int zb = z / batchH, zh = z - zb * batchH;
    A += (long long)zb * sAb + (long long)zh * sAh;
    B += (long long)zb * sBb + (long long)zh * sBh;
    C += (long long)zb * sCb + (long long)zh * sCh;

    int tid = threadIdx.x;
    int wid = tid >> 5, lane = tid & 31;
    int wm = wid / WN, wn = wid % WN;
    int g = lane >> 2, t = lane & 3;
    int m0 = blockIdx.y * BM, n0 = blockIdx.x * BN;

    float acc[MT][8][4];
    #pragma unroll
    for (int i = 0; i < MT; i++)
        #pragma unroll
        for (int j = 0; j < 8; j++)
            #pragma unroll
            for (int q = 0; q < 4; q++) acc[i][j][q] = 0.f;

    int lr0 = tid >> 2, lc0 = (tid & 3) * 4;
    const float* Ag = A + (long long)(m0 + lr0) * lda + lc0;
    const float* Bg = B + (long long)(n0 + lr0) * ldb + lc0;
    int NC = K / KC;

    float invL[AI];
    float* AoutB = nullptr;
    if (ATTN) {
        const float* rs = rowsum + (long long)z * M;
        #pragma unroll
        for (int i = 0; i < AI; i++) invL[i] = 1.f / rs[m0 + lr0 + i * 64];
        AoutB = Aout + (long long)zb * sAb + (long long)zh * sAh;
    }

    auto issue = [&](int c) {
        int s = c % 3;
        uint32_t ab = sbase + (uint32_t)(s * STG) * 4u;
        uint32_t bb = ab + (uint32_t)(BM * SPAD) * 4u;
        const float* Ap = Ag + c * KC;
        #pragma unroll
        for (int i = 0; i < AI; i++) {
            cp16(ab + (uint32_t)((lr0 + i * 64) * SPAD + lc0) * 4u,
                 Ap + (long long)(i * 64) * lda);
            cp16(ab + (uint32_t)((lr0 + i * 64) * SPAD + lc0 + 16) * 4u,
                 Ap + (long long)(i * 64) * lda + 16);
        }
        const float* Bp = Bg + c * KC;
        #pragma unroll
        for (int i = 0; i < BI; i++) {
            cp16(bb + (uint32_t)((lr0 + i * 64) * SPAD + lc0) * 4u,
                 Bp + (long long)(i * 64) * ldb);
            cp16(bb + (uint32_t)((lr0 + i * 64) * SPAD + lc0 + 16) * 4u,
                 Bp + (long long)(i * 64) * ldb + 16);
        }
    };

    issue(0); CP_COMMIT();
    issue(1); CP_COMMIT();

    for (int c = 0; c < NC; c++) {
        int s = c % 3;
        uint32_t* stA = sm + s * STG;
        uint32_t* stB = stA + BM * SPAD;

        CP_WAIT1();
        __syncthreads();

        if (ATTN) {   // stream normalized attention weights out of smem
            #pragma unroll
            for (int i = 0; i < AI; i++) {
                #pragma unroll
                for (int jj = 0; jj < 2; jj++) {
                    float4 e = *reinterpret_cast<float4*>(
                        &stA[(lr0 + i * 64) * SPAD + lc0 + jj * 16]);
                    e.x *= invL[i]; e.y *= invL[i]; e.z *= invL[i]; e.w *= invL[i];
                    *reinterpret_cast<float4*>(
                        AoutB + (long long)(m0 + lr0 + i * 64) * lda
                        + c * KC + lc0 + jj * 16) = e;
                }
            }
        }

        if (c + 2 < NC) issue(c + 2);
        CP_COMMIT();

        #pragma unroll
        for (int ks = 0; ks < KC / 8; ks++) {
            int kk = ks * 8;
            uint32_t af[MT][4], bf[8][2];
            #pragma unroll
            for (int mt = 0; mt < MT; mt++) {
                int row = wm * (MT * 16) + mt * 16 + g;
                af[mt][0] = f2tf32(__uint_as_float(stA[row * SPAD + kk + t]));
                af[mt][1] = f2tf32(__uint_as_float(stA[(row + 8) * SPAD + kk + t]));
                af[mt][2] = f2tf32(__uint_as_float(stA[row * SPAD + kk + t + 4]));
                af[mt][3] = f2tf32(__uint_as_float(stA[(row + 8) * SPAD + kk + t + 4]));
            }
            #pragma unroll
            for (int nt = 0; nt < 8; nt++) {
                int col = wn * 64 + nt * 8 + g;
                bf[nt][0] = f2tf32(__uint_as_float(stB[col * SPAD + kk + t]));
                bf[nt][1] = f2tf32(__uint_as_float(stB[col * SPAD + kk + t + 4]));
            }
            #pragma unroll
            for (int mt = 0; mt < MT; mt++)
                #pragma unroll
                for (int nt = 0; nt < 8; nt++)
                    mma_tf32(acc[mt][nt], af[mt], bf[nt]);
        }
    }

    // ---------------- epilogue ----------------
    float betav = (MODE == 4) ? beta_ptr[0] : 0.f;
    const float* rsE = (MODE == 6) ? rowsum + (long long)z * M : nullptr;
    float* rsA = (MODE == 5) ? rowsum + (long long)z * M : nullptr;

    #pragma unroll
    for (int mt = 0; mt < MT; mt++) {
        int r0 = m0 + wm * (MT * 16) + mt * 16 + g;
        int r1 = r0 + 8;
        float cw0 = 0.f, cw1 = 0.f, inv0 = 0.f, inv1 = 0.f;
        if (MODE == 4) { cw0 = cwgt[r0]; cw1 = cwgt[r1]; }
        if (MODE == 6) { inv0 = 1.f / rsE[r0]; inv1 = 1.f / rsE[r1]; }
        float s0 = 0.f, s1 = 0.f;
        #pragma unroll
        for (int nt = 0; nt < 8; nt++) {
            int n = n0 + wn * 64 + nt * 8 + 2 * t;
            long long co0 = (long long)r0 * ldc + n;
            long long co1 = (long long)r1 * ldc + n;
            float v00 = acc[mt][nt][0], v01 = acc[mt][nt][1];
            float v10 = acc[mt][nt][2], v11 = acc[mt][nt][3];
            float2 o0, o1;
            if (MODE == 1) {
                o0 = make_float2(v00, v01);
                o1 = make_float2(v10, v11);
            } else if (MODE == 2) {
                float b0 = bias[n], b1 = bias[n + 1];
                o0 = make_float2(geluf(v00 + b0), geluf(v01 + b1));
                o1 = make_float2(geluf(v10 + b0), geluf(v11 + b1));
            } else if (MODE == 3) {
                float b0 = bias ? bias[n] : 0.f, b1 = bias ? bias[n + 1] : 0.f;
                float2 q0 = *reinterpret_cast<const float2*>(res + co0);
                float2 q1 = *reinterpret_cast<const float2*>(res + co1);
                o0 = make_float2(q0.x + v00 + b0, q0.y + v01 + b1);
                o1 = make_float2(q1.x + v10 + b0, q1.y + v11 + b1);
            } else if (MODE == 4) {
                float b0 = bias[n], b1 = bias[n + 1];
                float2 q0 = *reinterpret_cast<const float2*>(res + co0);
                float2 q1 = *reinterpret_cast<const float2*>(res + co1);
                float2 h0 = *reinterpret_cast<const float2*>(h2p + co0);
                float2 h1 = *reinterpret_cast<const float2*>(h2p + co1);
                o0 = make_float2(q0.x + betav * h0.x + cw0 * (v00 + b0),
                                 q0.y + betav * h0.y + cw0 * (v01 + b1));
                o1 = make_float2(q1.x + betav * h1.x + cw1 * (v10 + b0),
                                 q1.y + betav * h1.y + cw1 * (v11 + b1));
            } else if (MODE == 5) {
                float e00 = __expf(v00 * scale), e01 = __expf(v01 * scale);
                float e10 = __expf(v10 * scale), e11 = __expf(v11 * scale);
                o0 = make_float2(e00, e01);
                o1 = make_float2(e10, e11);
                s0 += e00 + e01; s1 += e10 + e11;
            } else { // MODE == 6
                o0 = make_float2(v00 * inv0, v01 * inv0);
                o1 = make_float2(v10 * inv1, v11 * inv1);
            }
            *reinterpret_cast<float2*>(C + co0) = o0;
            *reinterpret_cast<float2*>(C + co1) = o1;
        }
        if (MODE == 5) {
            s0 += __shfl_xor_sync(0xffffffffu, s0, 1);
            s0 += __shfl_xor_sync(0xffffffffu, s0, 2);
            s1 += __shfl_xor_sync(0xffffffffu, s1, 1);
            s1 += __shfl_xor_sync(0xffffffffu, s1, 2);
            if (t == 0) {
                atomicAdd(rsA + r0, s0);
                atomicAdd(rsA + r1, s1);
            }
        }
    }
}

// ---------------- zero kernel (row sums) ----------------
__global__ void __launch_bounds__(256) zero_kernel(float* p, int n) {
    int i = blockIdx.x * 256 + threadIdx.x;
    if (i < n) p[i] = 0.f;
}

// ---------------- transpose ----------------
__global__ void __launch_bounds__(256) transpose_kernel(
    const float* __restrict__ in, float* __restrict__ out,
    int R, int C, int ldi, int ldo,
    int batchH, long long sIb, long long sIh, long long sOb, long long sOh)
{
    __shared__ float tile[32][33];
    int z = blockIdx.z;
    int zb = z / batchH, zh = z - zb * batchH;
    in  += (long long)zb * sIb + (long long)zh * sIh;
    out += (long long)zb * sOb + (long long)zh * sOh;
    int r0 = blockIdx.y * 32, c0 = blockIdx.x * 32;
    int tx = threadIdx.x & 31, ty = threadIdx.x >> 5;
    #pragma unroll
    for (int i = 0; i < 4; i++) {
        int r = r0 + ty + i * 8, c = c0 + tx;
        if (r < R && c < C) tile[ty + i * 8][tx] = in[(long long)r * ldi + c];
    }
    __syncthreads();
    #pragma unroll
    for (int i = 0; i < 4; i++) {
        int c = c0 + ty + i * 8, r = r0 + tx;
        if (r < R && c < C) out[(long long)c * ldo + r] = tile[tx][ty + i * 8];
    }
}

// ---------------- layernorm ----------------
__device__ __forceinline__ float brsum(float v, float* sh) {
    int t = threadIdx.x;
    sh[t] = v; __syncthreads();
    #pragma unroll
    for (int s = 128; s > 0; s >>= 1) { if (t < s) sh[t] += sh[t + s]; __syncthreads(); }
    float r = sh[0]; __syncthreads();
    return r;
}

__global__ void __launch_bounds__(256) ln_kernel(
    const float* __restrict__ x, float* __restrict__ y,
    const float* __restrict__ g, const float* __restrict__ b,
    float* __restrict__ cwgt, const float* __restrict__ alpha_ptr)
{
    long long base = (long long)blockIdx.x * DD;
    int t = threadIdx.x;
    __shared__ float sh[256];
    float xv[4];
    float s = 0.f;
    #pragma unroll
    for (int i = 0; i < 4; i++) { xv[i] = x[base + t + i * 256]; s += xv[i]; }
    s = brsum(s, sh);
    float mu = s * (1.0f / DD);
    float vs = 0.f;
    #pragma unroll
    for (int i = 0; i < 4; i++) { float d = xv[i] - mu; vs += d * d; }
    vs = brsum(vs, sh);
    float inv = rsqrtf(vs * (1.0f / DD) + 1e-5f);
    float ss = 0.f;
    #pragma unroll
    for (int i = 0; i < 4; i++) {
        int c = t + i * 256;
        float yv = (xv[i] - mu) * inv * g[c] + b[c];
        y[base + c] = yv;
        ss += yv * yv;
    }
    if (cwgt) {
        ss = brsum(ss, sh);
        if (t == 0) cwgt[blockIdx.x] = expf(-alpha_ptr[0] * sqrtf(ss));
    }
}

// ---------------- Qg = Q*cos(ph[h]) - V*sin(ph[h])  (from packed QKV) ----------------
__global__ void __launch_bounds__(256) qg_kernel(
    const float* __restrict__ QKV, const float* __restrict__ phase,
    float* __restrict__ Qg)
{
    int i = blockIdx.x * 256 + threadIdx.x;
    if (i >= NELT) return;
    int tok = i >> 10, col = i & (DD - 1);
    int h = col >> 6;
    float p = phase[h];
    long long base = (long long)tok * (3 * DD) + col;
    Qg[i] = QKV[base] * cosf(p) - QKV[base + 2 * DD] * sinf(p);
}

// ---------------- host helpers ----------------
template<int BM, int BN, int MT, bool ATTN, int MODE>
static void run_gemm(const float* A, const float* B, float* C, float* Aout, float* rowsum,
    int M, int N, int K, int lda, int ldb, int ldc,
    int batch, int batchH,
    long long sAb, long long sAh, long long sBb, long long sBh,
    long long sCb, long long sCh,
    float scale, const float* bias, const float* res,
    const float* h2p, const float* cwgt, const float* betap)
{
    int smem = 3 * (BM + BN) * SPAD * 4;
    cudaFuncSetAttribute(tc_gemm<BM, BN, MT, ATTN, MODE>,
                         cudaFuncAttributeMaxDynamicSharedMemorySize, smem);
    dim3 grid(N / BN, M / BM, batch);
    tc_gemm<BM, BN, MT, ATTN, MODE><<<grid, 256, smem>>>(
        A, B, C, Aout, rowsum, M, K, lda, ldb, ldc,
        batchH, sAb, sAh, sBb, sBh, sCb, sCh,
        scale, bias, res, h2p, cwgt, betap);
}

static void launch_tr(const float* in, float* out, int R, int C, int ldi, int ldo,
    int batch, int batchH, long long sIb, long long sIh, long long sOb, long long sOh)
{
    dim3 grid((C + 31) / 32, (R + 31) / 32, batch);
    transpose_kernel<<<grid, 256>>>(in, out, R, C, ldi, ldo, batchH, sIb, sIh, sOb, sOh);
}

extern "C" void kernel_launch(void* const* d_in, const int* in_sizes, int n_in,
                              void* d_out, int out_size)
{
    const float* x     = (const float*)d_in[0];
    const float* wq    = (const float*)d_in[1];
    const float* wk    = (const float*)d_in[2];
    const float* wv    = (const float*)d_in[3];
    const float* wo    = (const float*)d_in[4];
    const float* phase = (const float*)d_in[5];
    const float* cw1   = (const float*)d_in[6];
    const float* cb1   = (const float*)d_in[7];
    const float* cw2   = (const float*)d_in[8];
    const float* cb2   = (const float*)d_in[9];
    const float* alpha = (const float*)d_in[10];
    const float* beta  = (const float*)d_in[11];
    const float* fw1   = (const float*)d_in[12];
    const float* fb1   = (const float*)d_in[13];
    const float* fw2   = (const float*)d_in[14];
    const float* fb2   = (const float*)d_in[15];
    const float* ln1g  = (const float*)d_in[16];
    const float* ln1b  = (const float*)d_in[17];
    const float* ln2g  = (const float*)d_in[18];
    const float* ln2b  = (const float*)d_in[19];
    const float* ln3g  = (const float*)d_in[20];
    const float* ln3b  = (const float*)d_in[21];

    static float *p_h=0,*p_QKV=0,*p_Qg=0,*p_VT=0,*p_ctx=0,*p_x1=0,
                 *p_h2=0,*p_x2=0,*p_t1=0,*p_ff1=0,*p_cwgt=0,*p_rowsum=0,*p_attn_fb=0,
                 *p_wqkvT=0,*p_woT=0,*p_cw1T=0,*p_cw2T=0,*p_fw1T=0,*p_fw2T=0;
    if (!p_h) {
        cudaGetSymbolAddress((void**)&p_h,    g_h);
        cudaGetSymbolAddress((void**)&p_QKV,  g_QKV);
        cudaGetSymbolAddress((void**)&p_Qg,   g_Qg);
        cudaGetSymbolAddress((void**)&p_VT,   g_VT);
        cudaGetSymbolAddress((void**)&p_ctx,  g_ctx);
        cudaGetSymbolAddress((void**)&p_x1,   g_x1);
        cudaGetSymbolAddress((void**)&p_h2,   g_h2);
        cudaGetSymbolAddress((void**)&p_x2,   g_x2);
        cudaGetSymbolAddress((void**)&p_t1,   g_t1);
        cudaGetSymbolAddress((void**)&p_ff1,  g_ff1);
        cudaGetSymbolAddress((void**)&p_cwgt, g_cwgt);
        cudaGetSymbolAddress((void**)&p_rowsum, g_rowsum);
        cudaGetSymbolAddress((void**)&p_attn_fb, g_attn_fb);
        cudaGetSymbolAddress((void**)&p_wqkvT, g_wqkvT);
        cudaGetSymbolAddress((void**)&p_woT,  g_woT);
        cudaGetSymbolAddress((void**)&p_cw1T, g_cw1T);
        cudaGetSymbolAddress((void**)&p_cw2T, g_cw2T);
        cudaGetSymbolAddress((void**)&p_fw1T, g_fw1T);
        cudaGetSymbolAddress((void**)&p_fw2T, g_fw2T);
    }

    float* out_x = (float*)d_out;
    long long need = (long long)NELT + ASZ;
    float* attn = ((long long)out_size >= need) ? (out_x + NELT) : p_attn_fb;

    // weight transposes (W[K,N] -> WT[N,K]); wq/wk/wv packed into one [3072,1024]
    launch_tr(wq,  p_wqkvT,             DD,   DD,  DD,   DD,   1, 1, 0,0,0,0);
    launch_tr(wk,  p_wqkvT + DD*DD,     DD,   DD,  DD,   DD,   1, 1, 0,0,0,0);
    launch_tr(wv,  p_wqkvT + 2*DD*DD,   DD,   DD,  DD,   DD,   1, 1, 0,0,0,0);
    launch_tr(wo,  p_woT,  DD,   DD,  DD,   DD,   1, 1, 0,0,0,0);
    launch_tr(cw1, p_cw1T, DD,   2*DD, 2*DD, DD,  1, 1, 0,0,0,0);
    launch_tr(cw2, p_cw2T, 2*DD, DD,  DD,   2*DD, 1, 1, 0,0,0,0);
    launch_tr(fw1, p_fw1T, DD,   FFN, FFN,  DD,   1, 1, 0,0,0,0);
    launch_tr(fw2, p_fw2T, FFN,  DD,  DD,   FFN,  1, 1, 0,0,0,0);

    // 0) zero row sums
    zero_kernel<<<(NROWS + 255) / 256, 256>>>(p_rowsum, NROWS);

    // 1) h = LN1(x)
    ln_kernel<<<NTOK, 256>>>(x, p_h, ln1g, ln1b, nullptr, nullptr);

    // 2) QKV = h @ [wq|wk|wv]   (one GEMM, N=3072)
    run_gemm<256,128,4,false,1>(p_h, p_wqkvT, p_QKV, 0, 0, NTOK, 3*DD, DD,
                                DD, DD, 3*DD,
                                1,1, 0,0,0,0,0,0, 1.f, 0,0,0,0,0);

    // 3) Qg (from packed QKV)
    qg_kernel<<<(NELT + 255) / 256, 256>>>(p_QKV, phase, p_Qg);

    // 3b) VT[b,h,d,s] = V[b,s,h,d]
    launch_tr(p_QKV + 2*DD, p_VT, SS, DKK, 3*DD, SS,
              BB * HH, HH,
              (long long)SS * 3*DD, DKK,
              (long long)HH * DKK * SS, (long long)DKK * SS);

    // 4) e = exp(Qg @ K^T / 8)  + row sums (unnormalized, into scratch)
    run_gemm<256,128,4,false,5>(p_Qg, p_QKV + DD, p_attn_fb, 0, p_rowsum,
                                SS, SS, DKK, DD, 3*DD, SS,
                                BB * HH, HH,
                                (long long)SS * DD, DKK,
                                (long long)SS * 3*DD, DKK,
                                (long long)HH * SS * SS, (long long)SS * SS,
                                0.125f, 0,0,0,0,0);

    // 5+6) ctx = (e/rowsum) @ V  — streams normalized attn_weights to output
    run_gemm<128,64,1,true,6>(p_attn_fb, p_VT, p_ctx, attn, p_rowsum,
                              SS, DKK, SS, SS, SS, DD,
                              BB * HH, HH,
                              (long long)HH * SS * SS, (long long)SS * SS,
                              (long long)HH * DKK * SS, (long long)DKK * SS,
                              (long long)SS * DD, DKK,
                              1.f, 0,0,0,0,0);

    // 7) x1 = x + ctx @ wo
    run_gemm<256,128,4,false,3>(p_ctx, p_woT, p_x1, 0, 0, NTOK, DD, DD, DD, DD, DD,
                                1,1, 0,0,0,0,0,0, 1.f, 0, x, 0,0,0);

    // 8) h2 = LN2(x1) + cwgt
    ln_kernel<<<NTOK, 256>>>(p_x1, p_h2, ln2g, ln2b, p_cwgt, alpha);

    // 9) t1 = gelu(h2 @ cw1 + cb1)
    run_gemm<256,128,4,false,2>(p_h2, p_cw1T, p_t1, 0, 0, NTOK, 2*DD, DD, DD, DD, 2*DD,
                                1,1, 0,0,0,0,0,0, 1.f, cb1, 0,0,0,0);

    // 10) x2 = x1 + beta*h2 + cwgt*(t1 @ cw2 + cb2)
    run_gemm<256,128,4,false,4>(p_t1, p_cw2T, p_x2, 0, 0, NTOK, DD, 2*DD, 2*DD, 2*DD, DD,
                                1,1, 0,0,0,0,0,0, 1.f, cb2, p_x1, p_h2, p_cwgt, beta);

    // 11) h3 = LN3(x2)
    ln_kernel<<<NTOK, 256>>>(p_x2, p_h, ln3g, ln3b, nullptr, nullptr);

    // 12) ff1 = gelu(h3 @ fw1 + fb1)
    run_gemm<256,128,4,false,2>(p_h, p_fw1T, p_ff1, 0, 0, NTOK, FFN, DD, DD, DD, FFN,
                                1,1, 0,0,0,0,0,0, 1.f, fb1, 0,0,0,0);

    // 13) out = x2 + ff1 @ fw2 + fb2
    run_gemm<256,128,4,false,3>(p_ff1, p_fw2T, out_x, 0, 0, NTOK, DD, FFN, FFN, FFN, DD,
                                1,1, 0,0,0,0,0,0, 1.f, fb2, p_x2, 0,0,0);
}

// round 11
// speedup vs baseline: 3.9144x; 1.0570x over previous
#include <cuda_runtime.h>
#include <math.h>
#include <stdint.h>

// ---------------- problem constants ----------------
#define BB   4
#define SS   2048
#define DD   1024
#define HH   16
#define DKK  64
#define FFN  4096
#define NTOK (BB*SS)
#define NELT (NTOK*DD)
#define ASZ  ((long long)BB*HH*SS*SS)
#define NROWS (BB*HH*SS)

#define KC    32   // K-chunk
#define SPAD  36   // smem row stride (floats)

// ---------------- scratch (device globals) ----------------
__device__ float g_h  [NELT];
__device__ float g_QKV[NTOK*3*DD];
__device__ float g_Qg [NELT];
__device__ float g_VT [NELT];
__device__ float g_ctx[NELT];
__device__ float g_x1 [NELT];
__device__ float g_h2 [NELT];
__device__ float g_x2 [NELT];
__device__ float g_t1 [NTOK*2*DD];
__device__ float g_ff1[NTOK*FFN];
__device__ float g_cwgt[NTOK];
__device__ float g_rowsum[NROWS];
__device__ float g_wqkvT[3*DD*DD];
__device__ float g_woT [DD*DD];
__device__ float g_cw1T[DD*2*DD];
__device__ float g_cw2T[2*DD*DD];
__device__ float g_fw1T[DD*FFN];
__device__ float g_fw2T[DD*FFN];
__device__ float g_attn_fb[(size_t)ASZ];   // unnormalized exp(scores), tf32-rounded

// ---------------- helpers ----------------
__device__ __forceinline__ uint32_t smem_u32(const void* p) {
    uint32_t a;
    asm("{ .reg .u64 t; cvta.to.shared.u64 t, %1; cvt.u32.u64 %0, t; }"
        : "=r"(a) : "l"(p));
    return a;
}
// round fp32 -> tf32-representable fp32 (rna); stored values feed mma directly
__device__ __forceinline__ float rndtf(float x) {
    uint32_t u;
    asm("cvt.rna.tf32.f32 %0, %1;" : "=r"(u) : "f"(x));
    return __uint_as_float(u);
}
__device__ __forceinline__ float geluf(float x) {
    return 0.5f * x * (1.0f + erff(x * 0.70710678118654752f));
}
__device__ __forceinline__ void mma_tf32(float* d, const uint32_t* a, const uint32_t* b) {
    asm volatile(
        "mma.sync.aligned.m16n8k8.row.col.f32.tf32.tf32.f32 "
        "{%0,%1,%2,%3}, {%4,%5,%6,%7}, {%8,%9}, {%0,%1,%2,%3};"
        : "+f"(d[0]), "+f"(d[1]), "+f"(d[2]), "+f"(d[3])
        : "r"(a[0]), "r"(a[1]), "r"(a[2]), "r"(a[3]), "r"(b[0]), "r"(b[1]));
}
__device__ __forceinline__ void cp16(uint32_t dst, const void* src) {
    asm volatile("cp.async.cg.shared.global [%0], [%1], 16;"
                 :: "r"(dst), "l"(src) : "memory");
}
#define CP_COMMIT() asm volatile("cp.async.commit_group;" ::: "memory")
#define CP_WAIT1()  asm volatile("cp.async.wait_group 1;" ::: "memory")

// ---------------- templated tensor-core tf32 GEMM ----------------
// C = A[M,K] @ B[N,K]^T. All A/B inputs are PRE-ROUNDED to tf32 in gmem,
// so fragments go smem -> mma with no cvt.
// MODE: 1 = acc (rounded out)       2 = gelu(acc+bias) (rounded out)
//       3 = res + acc (+bias)       4 = res + beta*h2 + cwgt[m]*(acc+bias)
//       5 = e=rnd(exp(acc*scale)), write e, atomic row sums of rounded e
//       6 = rnd(acc * inv_rowsum[m])  (ctx; ATTN streams normalized attn)
template<int BM, int BN, int MT, bool ATTN, int MODE>
__global__ void __launch_bounds__(256) tc_gemm(
    const float* __restrict__ A, const float* __restrict__ B,
    float* __restrict__ C, float* __restrict__ Aout, float* __restrict__ rowsum,
    int M, int K, int lda, int ldb, int ldc,
    int batchH, long long sAb, long long sAh, long long sBb, long long sBh,
    long long sCb, long long sCh,
    float scale, const float* __restrict__ bias, const float* __restrict__ res,
    const float* __restrict__ h2p, const float* __restrict__ cwgt,
    const float* __restrict__ beta_ptr)
{
    constexpr int WN  = BN / 64;
    constexpr int AI  = BM / 64;
    constexpr int BI  = BN / 64;
    constexpr int STG = (BM + BN) * SPAD;

    extern __shared__ uint32_t sm[];
    uint32_t sbase = smem_u32(sm);

    int z = blockIdx.z;
    int zb = z / batchH, zh = z - zb * batchH;
    A += (long long)zb * sAb + (long long)zh * sAh;
    B += (long long)zb * sBb + (long long)zh * sBh;
    C += (long long)zb * sCb + (long long)zh * sCh;

    int tid = threadIdx.x;
    int wid = tid >> 5, lane = tid & 31;
    int wm = wid / WN, wn = wid % WN;
    int g = lane >> 2, t = lane & 3;
    int m0 = blockIdx.y * BM, n0 = blockIdx.x * BN;

    float acc[MT][8][4];
    #pragma unroll
    for (int i = 0; i < MT; i++)
        #pragma unroll
        for (int j = 0; j < 8; j++)
            #pragma unroll
            for (int q = 0; q < 4; q++) acc[i][j][q] = 0.f;

    int lr0 = tid >> 2, lc0 = (tid & 3) * 4;
    const float* Ag = A + (long long)(m0 + lr0) * lda + lc0;
    const float* Bg = B + (long long)(n0 + lr0) * ldb + lc0;
    int NC = K / KC;

    float invL[AI];
    float* AoutB = nullptr;
    if (ATTN) {
        const float* rs = rowsum + (long long)z * M;
        #pragma unroll
        for (int i = 0; i < AI; i++) invL[i] = 1.f / rs[m0 + lr0 + i * 64];
        AoutB = Aout + (long long)zb * sAb + (long long)zh * sAh;
    }

    auto issue = [&](int c) {
        int s = c % 3;
        uint32_t ab = sbase + (uint32_t)(s * STG) * 4u;
        uint32_t bb = ab + (uint32_t)(BM * SPAD) * 4u;
        const float* Ap = Ag + c * KC;
        #pragma unroll
        for (int i = 0; i < AI; i++) {
            cp16(ab + (uint32_t)((lr0 + i * 64) * SPAD + lc0) * 4u,
                 Ap + (long long)(i * 64) * lda);
            cp16(ab + (uint32_t)((lr0 + i * 64) * SPAD + lc0 + 16) * 4u,
                 Ap + (long long)(i * 64) * lda + 16);
        }
        const float* Bp = Bg + c * KC;
        #pragma unroll
        for (int i = 0; i < BI; i++) {
            cp16(bb + (uint32_t)((lr0 + i * 64) * SPAD + lc0) * 4u,
                 Bp + (long long)(i * 64) * ldb);
            cp16(bb + (uint32_t)((lr0 + i * 64) * SPAD + lc0 + 16) * 4u,
                 Bp + (long long)(i * 64) * ldb + 16);
        }
    };

    issue(0); CP_COMMIT();
    issue(1); CP_COMMIT();

    for (int c = 0; c < NC; c++) {
        int s = c % 3;
        uint32_t* stA = sm + s * STG;
        uint32_t* stB = stA + BM * SPAD;

        CP_WAIT1();
        __syncthreads();

        if (ATTN) {   // stream normalized attention weights out of smem
            #pragma unroll
            for (int i = 0; i < AI; i++) {
                #pragma unroll
                for (int jj = 0; jj < 2; jj++) {
                    float4 e = *reinterpret_cast<float4*>(
                        &stA[(lr0 + i * 64) * SPAD + lc0 + jj * 16]);
                    e.x *= invL[i]; e.y *= invL[i]; e.z *= invL[i]; e.w *= invL[i];
                    *reinterpret_cast<float4*>(
                        AoutB + (long long)(m0 + lr0 + i * 64) * lda
                        + c * KC + lc0 + jj * 16) = e;
                }
            }
        }

        if (c + 2 < NC) issue(c + 2);
        CP_COMMIT();

        #pragma unroll
        for (int ks = 0; ks < KC / 8; ks++) {
            int kk = ks * 8;
            uint32_t af[MT][4], bf[8][2];
            #pragma unroll
            for (int mt = 0; mt < MT; mt++) {
                int row = wm * (MT * 16) + mt * 16 + g;
                af[mt][0] = stA[row * SPAD + kk + t];
                af[mt][1] = stA[(row + 8) * SPAD + kk + t];
                af[mt][2] = stA[row * SPAD + kk + t + 4];
                af[mt][3] = stA[(row + 8) * SPAD + kk + t + 4];
            }
            #pragma unroll
            for (int nt = 0; nt < 8; nt++) {
                int col = wn * 64 + nt * 8 + g;
                bf[nt][0] = stB[col * SPAD + kk + t];
                bf[nt][1] = stB[col * SPAD + kk + t + 4];
            }
            #pragma unroll
            for (int mt = 0; mt < MT; mt++)
                #pragma unroll
                for (int nt = 0; nt < 8; nt++)
                    mma_tf32(acc[mt][nt], af[mt], bf[nt]);
        }
    }

    // ---------------- epilogue ----------------
    float betav = (MODE == 4) ? beta_ptr[0] : 0.f;
    const float* rsE = (MODE == 6) ? rowsum + (long long)z * M : nullptr;
    float* rsA = (MODE == 5) ? rowsum + (long long)z * M : nullptr;

    #pragma unroll
    for (int mt = 0; mt < MT; mt++) {
        int r0 = m0 + wm * (MT * 16) + mt * 16 + g;
        int r1 = r0 + 8;
        float cw0 = 0.f, cw1 = 0.f, inv0 = 0.f, inv1 = 0.f;
        if (MODE == 4) { cw0 = cwgt[r0]; cw1 = cwgt[r1]; }
        if (MODE == 6) { inv0 = 1.f / rsE[r0]; inv1 = 1.f / rsE[r1]; }
        float s0 = 0.f, s1 = 0.f;
        #pragma unroll
        for (int nt = 0; nt < 8; nt++) {
            int n = n0 + wn * 64 + nt * 8 + 2 * t;
            long long co0 = (long long)r0 * ldc + n;
            long long co1 = (long long)r1 * ldc + n;
            float v00 = acc[mt][nt][0], v01 = acc[mt][nt][1];
            float v10 = acc[mt][nt][2], v11 = acc[mt][nt][3];
            float2 o0, o1;
            if (MODE == 1) {
                o0 = make_float2(rndtf(v00), rndtf(v01));
                o1 = make_float2(rndtf(v10), rndtf(v11));
            } else if (MODE == 2) {
                float b0 = bias[n], b1 = bias[n + 1];
                o0 = make_float2(rndtf(geluf(v00 + b0)), rndtf(geluf(v01 + b1)));
                o1 = make_float2(rndtf(geluf(v10 + b0)), rndtf(geluf(v11 + b1)));
            } else if (MODE == 3) {
                float b0 = bias ? bias[n] : 0.f, b1 = bias ? bias[n + 1] : 0.f;
                float2 q0 = *reinterpret_cast<const float2*>(res + co0);
                float2 q1 = *reinterpret_cast<const float2*>(res + co1);
                o0 = make_float2(q0.x + v00 + b0, q0.y + v01 + b1);
                o1 = make_float2(q1.x + v10 + b0, q1.y + v11 + b1);
            } else if (MODE == 4) {
                float b0 = bias[n], b1 = bias[n + 1];
                float2 q0 = *reinterpret_cast<const float2*>(res + co0);
                float2 q1 = *reinterpret_cast<const float2*>(res + co1);
                float2 h0 = *reinterpret_cast<const float2*>(h2p + co0);
                float2 h1 = *reinterpret_cast<const float2*>(h2p + co1);
                o0 = make_float2(q0.x + betav * h0.x + cw0 * (v00 + b0),
                                 q0.y + betav * h0.y + cw0 * (v01 + b1));
                o1 = make_float2(q1.x + betav * h1.x + cw1 * (v10 + b0),
                                 q1.y + betav * h1.y + cw1 * (v11 + b1));
            } else if (MODE == 5) {
                float e00 = rndtf(__expf(v00 * scale));
                float e01 = rndtf(__expf(v01 * scale));
                float e10 = rndtf(__expf(v10 * scale));
                float e11 = rndtf(__expf(v11 * scale));
                o0 = make_float2(e00, e01);
                o1 = make_float2(e10, e11);
                s0 += e00 + e01; s1 += e10 + e11;
            } else { // MODE == 6
                o0 = make_float2(rndtf(v00 * inv0), rndtf(v01 * inv0));
                o1 = make_float2(rndtf(v10 * inv1), rndtf(v11 * inv1));
            }
            *reinterpret_cast<float2*>(C + co0) = o0;
            *reinterpret_cast<float2*>(C + co1) = o1;
        }
        if (MODE == 5) {
            s0 += __shfl_xor_sync(0xffffffffu, s0, 1);
            s0 += __shfl_xor_sync(0xffffffffu, s0, 2);
            s1 += __shfl_xor_sync(0xffffffffu, s1, 1);
            s1 += __shfl_xor_sync(0xffffffffu, s1, 2);
            if (t == 0) {
                atomicAdd(rsA + r0, s0);
                atomicAdd(rsA + r1, s1);
            }
        }
    }
}

// ---------------- zero kernel (row sums) ----------------
__global__ void __launch_bounds__(256) zero_kernel(float* p, int n) {
    int i = blockIdx.x * 256 + threadIdx.x;
    if (i < n) p[i] = 0.f;
}

// ---------------- transpose (rounds output to tf32: outputs are GEMM-B) ----------------
__global__ void __launch_bounds__(256) transpose_kernel(
    const float* __restrict__ in, float* __restrict__ out,
    int R, int C, int ldi, int ldo,
    int batchH, long long sIb, long long sIh, long long sOb, long long sOh)
{
    __shared__ float tile[32][33];
    int z = blockIdx.z;
    int zb = z / batchH, zh = z - zb * batchH;
    in  += (long long)zb * sIb + (long long)zh * sIh;
    out += (long long)zb * sOb + (long long)zh * sOh;
    int r0 = blockIdx.y * 32, c0 = blockIdx.x * 32;
    int tx = threadIdx.x & 31, ty = threadIdx.x >> 5;
    #pragma unroll
    for (int i = 0; i < 4; i++) {
        int r = r0 + ty + i * 8, c = c0 + tx;
        if (r < R && c < C) tile[ty + i * 8][tx] = in[(long long)r * ldi + c];
    }
    __syncthreads();
    #pragma unroll
    for (int i = 0; i < 4; i++) {
        int c = c0 + ty + i * 8, r = r0 + tx;
        if (r < R && c < C) out[(long long)c * ldo + r] = rndtf(tile[tx][ty + i * 8]);
    }
}

// ---------------- layernorm (rounds y to tf32: all LN outputs feed GEMMs) ----------------
__device__ __forceinline__ float brsum(float v, float* sh) {
    int t = threadIdx.x;
    sh[t] = v; __syncthreads();
    #pragma unroll
    for (int s = 128; s > 0; s >>= 1) { if (t < s) sh[t] += sh[t + s]; __syncthreads(); }
    float r = sh[0]; __syncthreads();
    return r;
}

__global__ void __launch_bounds__(256) ln_kernel(
    const float* __restrict__ x, float* __restrict__ y,
    const float* __restrict__ g, const float* __restrict__ b,
    float* __restrict__ cwgt, const float* __restrict__ alpha_ptr)
{
    long long base = (long long)blockIdx.x * DD;
    int t = threadIdx.x;
    __shared__ float sh[256];
    float xv[4];
    float s = 0.f;
    #pragma unroll
    for (int i = 0; i < 4; i++) { xv[i] = x[base + t + i * 256]; s += xv[i]; }
    s = brsum(s, sh);
    float mu = s * (1.0f / DD);
    float vs = 0.f;
    #pragma unroll
    for (int i = 0; i < 4; i++) { float d = xv[i] - mu; vs += d * d; }
    vs = brsum(vs, sh);
    float inv = rsqrtf(vs * (1.0f / DD) + 1e-5f);
    float ss = 0.f;
    #pragma unroll
    for (int i = 0; i < 4; i++) {
        int c = t + i * 256;
        float yv = (xv[i] - mu) * inv * g[c] + b[c];
        y[base + c] = rndtf(yv);
        ss += yv * yv;
    }
    if (cwgt) {
        ss = brsum(ss, sh);
        if (t == 0) cwgt[blockIdx.x] = expf(-alpha_ptr[0] * sqrtf(ss));
    }
}

// ---------------- Qg = Q*cos(ph[h]) - V*sin(ph[h]) (rounded; from packed QKV) ----------------
__global__ void __launch_bounds__(256) qg_kernel(
    const float* __restrict__ QKV, const float* __restrict__ phase,
    float* __restrict__ Qg)
{
    int i = blockIdx.x * 256 + threadIdx.x;
    if (i >= NELT) return;
    int tok = i >> 10, col = i & (DD - 1);
    int h = col >> 6;
    float p = phase[h];
    long long base = (long long)tok * (3 * DD) + col;
    Qg[i] = rndtf(QKV[base] * cosf(p) - QKV[base + 2 * DD] * sinf(p));
}

// ---------------- host helpers ----------------
template<int BM, int BN, int MT, bool ATTN, int MODE>
static void run_gemm(const float* A, const float* B, float* C, float* Aout, float* rowsum,
    int M, int N, int K, int lda, int ldb, int ldc,
    int batch, int batchH,
    long long sAb, long long sAh, long long sBb, long long sBh,
    long long sCb, long long sCh,
    float scale, const float* bias, const float* res,
    const float* h2p, const float* cwgt, const float* betap)
{
    int smem = 3 * (BM + BN) * SPAD * 4;
    cudaFuncSetAttribute(tc_gemm<BM, BN, MT, ATTN, MODE>,
                         cudaFuncAttributeMaxDynamicSharedMemorySize, smem);
    dim3 grid(N / BN, M / BM, batch);
    tc_gemm<BM, BN, MT, ATTN, MODE><<<grid, 256, smem>>>(
        A, B, C, Aout, rowsum, M, K, lda, ldb, ldc,
        batchH, sAb, sAh, sBb, sBh, sCb, sCh,
        scale, bias, res, h2p, cwgt, betap);
}

static void launch_tr(const float* in, float* out, int R, int C, int ldi, int ldo,
    int batch, int batchH, long long sIb, long long sIh, long long sOb, long long sOh)
{
    dim3 grid((C + 31) / 32, (R + 31) / 32, batch);
    transpose_kernel<<<grid, 256>>>(in, out, R, C, ldi, ldo, batchH, sIb, sIh, sOb, sOh);
}

extern "C" void kernel_launch(void* const* d_in, const int* in_sizes, int n_in,
                              void* d_out, int out_size)
{
    const float* x     = (const float*)d_in[0];
    const float* wq    = (const float*)d_in[1];
    const float* wk    = (const float*)d_in[2];
    const float* wv    = (const float*)d_in[3];
    const float* wo    = (const float*)d_in[4];
    const float* phase = (const float*)d_in[5];
    const float* cw1   = (const float*)d_in[6];
    const float* cb1   = (const float*)d_in[7];
    const float* cw2   = (const float*)d_in[8];
    const float* cb2   = (const float*)d_in[9];
    const float* alpha = (const float*)d_in[10];
    const float* beta  = (const float*)d_in[11];
    const float* fw1   = (const float*)d_in[12];
    const float* fb1   = (const float*)d_in[13];
    const float* fw2   = (const float*)d_in[14];
    const float* fb2   = (const float*)d_in[15];
    const float* ln1g  = (const float*)d_in[16];
    const float* ln1b  = (const float*)d_in[17];
    const float* ln2g  = (const float*)d_in[18];
    const float* ln2b  = (const float*)d_in[19];
    const float* ln3g  = (const float*)d_in[20];
    const float* ln3b  = (const float*)d_in[21];

    static float *p_h=0,*p_QKV=0,*p_Qg=0,*p_VT=0,*p_ctx=0,*p_x1=0,
                 *p_h2=0,*p_x2=0,*p_t1=0,*p_ff1=0,*p_cwgt=0,*p_rowsum=0,*p_attn_fb=0,
                 *p_wqkvT=0,*p_woT=0,*p_cw1T=0,*p_cw2T=0,*p_fw1T=0,*p_fw2T=0;
    if (!p_h) {
        cudaGetSymbolAddress((void**)&p_h,    g_h);
        cudaGetSymbolAddress((void**)&p_QKV,  g_QKV);
        cudaGetSymbolAddress((void**)&p_Qg,   g_Qg);
        cudaGetSymbolAddress((void**)&p_VT,   g_VT);
        cudaGetSymbolAddress((void**)&p_ctx,  g_ctx);
        cudaGetSymbolAddress((void**)&p_x1,   g_x1);
        cudaGetSymbolAddress((void**)&p_h2,   g_h2);
        cudaGetSymbolAddress((void**)&p_x2,   g_x2);
        cudaGetSymbolAddress((void**)&p_t1,   g_t1);
        cudaGetSymbolAddress((void**)&p_ff1,  g_ff1);
        cudaGetSymbolAddress((void**)&p_cwgt, g_cwgt);
        cudaGetSymbolAddress((void**)&p_rowsum, g_rowsum);
        cudaGetSymbolAddress((void**)&p_attn_fb, g_attn_fb);
        cudaGetSymbolAddress((void**)&p_wqkvT, g_wqkvT);
        cudaGetSymbolAddress((void**)&p_woT,  g_woT);
        cudaGetSymbolAddress((void**)&p_cw1T, g_cw1T);
        cudaGetSymbolAddress((void**)&p_cw2T, g_cw2T);
        cudaGetSymbolAddress((void**)&p_fw1T, g_fw1T);
        cudaGetSymbolAddress((void**)&p_fw2T, g_fw2T);
    }

    float* out_x = (float*)d_out;
    long long need = (long long)NELT + ASZ;
    float* attn = ((long long)out_size >= need) ? (out_x + NELT) : p_attn_fb;

    // weight transposes (rounded to tf32); wq/wk/wv packed into one [3072,1024]
    launch_tr(wq,  p_wqkvT,             DD,   DD,  DD,   DD,   1, 1, 0,0,0,0);
    launch_tr(wk,  p_wqkvT + DD*DD,     DD,   DD,  DD,   DD,   1, 1, 0,0,0,0);
    launch_tr(wv,  p_wqkvT + 2*DD*DD,   DD,   DD,  DD,   DD,   1, 1, 0,0,0,0);
    launch_tr(wo,  p_woT,  DD,   DD,  DD,   DD,   1, 1, 0,0,0,0);
    launch_tr(cw1, p_cw1T, DD,   2*DD, 2*DD, DD,  1, 1, 0,0,0,0);
    launch_tr(cw2, p_cw2T, 2*DD, DD,  DD,   2*DD, 1, 1, 0,0,0,0);
    launch_tr(fw1, p_fw1T, DD,   FFN, FFN,  DD,   1, 1, 0,0,0,0);
    launch_tr(fw2, p_fw2T, FFN,  DD,  DD,   FFN,  1, 1, 0,0,0,0);

    // 0) zero row sums
    zero_kernel<<<(NROWS + 255) / 256, 256>>>(p_rowsum, NROWS);

    // 1) h = LN1(x)  (tf32-rounded)
    ln_kernel<<<NTOK, 256>>>(x, p_h, ln1g, ln1b, nullptr, nullptr);

    // 2) QKV = h @ [wq|wk|wv]  (one GEMM, N=3072, rounded out)
    run_gemm<256,128,4,false,1>(p_h, p_wqkvT, p_QKV, 0, 0, NTOK, 3*DD, DD,
                                DD, DD, 3*DD,
                                1,1, 0,0,0,0,0,0, 1.f, 0,0,0,0,0);

    // 3) Qg (rounded)
    qg_kernel<<<(NELT + 255) / 256, 256>>>(p_QKV, phase, p_Qg);

    // 3b) VT[b,h,d,s] = V[b,s,h,d] (already tf32; transpose round is identity)
    launch_tr(p_QKV + 2*DD, p_VT, SS, DKK, 3*DD, SS,
              BB * HH, HH,
              (long long)SS * 3*DD, DKK,
              (long long)HH * DKK * SS, (long long)DKK * SS);

    // 4) e = rnd(exp(Qg @ K^T / 8)) + row sums of rounded e
    run_gemm<256,128,4,false,5>(p_Qg, p_QKV + DD, p_attn_fb, 0, p_rowsum,
                                SS, SS, DKK, DD, 3*DD, SS,
                                BB * HH, HH,
                                (long long)SS * DD, DKK,
                                (long long)SS * 3*DD, DKK,
                                (long long)HH * SS * SS, (long long)SS * SS,
                                0.125f, 0,0,0,0,0);

    // 5+6) ctx = (e/rowsum) @ V  — streams normalized attn_weights to output
    run_gemm<128,64,1,true,6>(p_attn_fb, p_VT, p_ctx, attn, p_rowsum,
                              SS, DKK, SS, SS, SS, DD,
                              BB * HH, HH,
                              (long long)HH * SS * SS, (long long)SS * SS,
                              (long long)HH * DKK * SS, (long long)DKK * SS,
                              (long long)SS * DD, DKK,
                              1.f, 0,0,0,0,0);

    // 7) x1 = x + ctx @ wo  (full precision out)
    run_gemm<256,128,4,false,3>(p_ctx, p_woT, p_x1, 0, 0, NTOK, DD, DD, DD, DD, DD,
                                1,1, 0,0,0,0,0,0, 1.f, 0, x, 0,0,0);

    // 8) h2 = LN2(x1) + cwgt  (h2 tf32-rounded)
    ln_kernel<<<NTOK, 256>>>(p_x1, p_h2, ln2g, ln2b, p_cwgt, alpha);

    // 9) t1 = gelu(h2 @ cw1 + cb1)  (rounded out)
    run_gemm<256,128,4,false,2>(p_h2, p_cw1T, p_t1, 0, 0, NTOK, 2*DD, DD, DD, DD, 2*DD,
                                1,1, 0,0,0,0,0,0, 1.f, cb1, 0,0,0,0);

    // 10) x2 = x1 + beta*h2 + cwgt*(t1 @ cw2 + cb2)  (full precision out)
    run_gemm<256,128,4,false,4>(p_t1, p_cw2T, p_x2, 0, 0, NTOK, DD, 2*DD, 2*DD, 2*DD, DD,
                                1,1, 0,0,0,0,0,0, 1.f, cb2, p_x1, p_h2, p_cwgt, beta);

    // 11) h3 = LN3(x2)  (rounded)
    ln_kernel<<<NTOK, 256>>>(p_x2, p_h, ln3g, ln3b, nullptr, nullptr);

    // 12) ff1 = gelu(h3 @ fw1 + fb1)  (rounded out)
    run_gemm<256,128,4,false,2>(p_h, p_fw1T, p_ff1, 0, 0, NTOK, FFN, DD, DD, DD, FFN,
                                1,1, 0,0,0,0,0,0, 1.f, fb1, 0,0,0,0);

    // 13) out = x2 + ff1 @ fw2 + fb2  (full precision out)
    run_gemm<256,128,4,false,3>(p_ff1, p_fw2T, out_x, 0, 0, NTOK, DD, FFN, FFN, FFN, DD,
                                1,1, 0,0,0,0,0,0, 1.f, fb2, p_x2, 0,0,0);
}

// round 12
// speedup vs baseline: 6.3133x; 1.6128x over previous
#include <cuda_runtime.h>
#include <cuda_fp16.h>
#include <math.h>
#include <stdint.h>

// ---------------- problem constants ----------------
#define BB   4
#define SS   2048
#define DD   1024
#define HH   16
#define DKK  64
#define FFN  4096
#define NTOK (BB*SS)
#define NELT (NTOK*DD)
#define ASZ  ((long long)BB*HH*SS*SS)
#define NROWS (BB*HH*SS)

#define KC    64   // K-chunk in fp16 elements (= 32 words = 128B per row)
#define SPAD  36   // smem row stride in 32-bit words (32 data + 4 pad)

// ---------------- scratch (device globals) ----------------
__device__ __half g_h  [NELT];
__device__ __half g_QKV[NTOK*3*DD];
__device__ __half g_Qg [NELT];
__device__ __half g_VT [NELT];
__device__ __half g_ctx[NELT];
__device__ float  g_x1 [NELT];
__device__ __half g_h2 [NELT];
__device__ float  g_x2 [NELT];
__device__ __half g_t1 [NTOK*2*DD];
__device__ __half g_ff1[NTOK*FFN];
__device__ float  g_cwgt[NTOK];
__device__ float  g_rowsum[NROWS];
__device__ __half g_wqkvT[3*DD*DD];
__device__ __half g_woT [DD*DD];
__device__ __half g_cw1T[DD*2*DD];
__device__ __half g_cw2T[2*DD*DD];
__device__ __half g_fw1T[DD*FFN];
__device__ __half g_fw2T[DD*FFN];
__device__ __half g_e   [(size_t)ASZ];   // unnormalized exp(scores), fp16
__device__ float  g_attn_fb[(size_t)ASZ];// fallback fp32 attn output

// ---------------- helpers ----------------
__device__ __forceinline__ uint32_t smem_u32(const void* p) {
    uint32_t a;
    asm("{ .reg .u64 t; cvta.to.shared.u64 t, %1; cvt.u32.u64 %0, t; }"
        : "=r"(a) : "l"(p));
    return a;
}
__device__ __forceinline__ float geluf(float x) {
    return 0.5f * x * (1.0f + erff(x * 0.70710678118654752f));
}
__device__ __forceinline__ void mma_f16(float* d, const uint32_t* a, const uint32_t* b) {
    asm volatile(
        "mma.sync.aligned.m16n8k16.row.col.f32.f16.f16.f32 "
        "{%0,%1,%2,%3}, {%4,%5,%6,%7}, {%8,%9}, {%0,%1,%2,%3};"
        : "+f"(d[0]), "+f"(d[1]), "+f"(d[2]), "+f"(d[3])
        : "r"(a[0]), "r"(a[1]), "r"(a[2]), "r"(a[3]), "r"(b[0]), "r"(b[1]));
}
__device__ __forceinline__ void cp16(uint32_t dst, const void* src) {
    asm volatile("cp.async.cg.shared.global [%0], [%1], 16;"
                 :: "r"(dst), "l"(src) : "memory");
}
#define CP_COMMIT() asm volatile("cp.async.commit_group;" ::: "memory")
#define CP_WAIT1()  asm volatile("cp.async.wait_group 1;" ::: "memory")

// ---------------- templated fp16 tensor-core GEMM ----------------
// C = A[M,K] @ B[N,K]^T, A/B fp16 (pre-rounded at producers), fp32 accumulate.
// K-chunk 64 elements, 3-stage cp.async pipeline; 8 warps, 256 thr.
// MODE: 1 = acc -> half             2 = gelu(acc+bias) -> half
//       3 = res + acc (+bias) -> float
//       4 = res + beta*h2 + cwgt[m]*(acc+bias) -> float
//       5 = e=h(exp(acc*scale)) -> half, atomic row sums of rounded e
//       6 = h(acc * inv_rowsum[m]) -> half (ctx; ATTN streams fp32 attn)
template<int BM, int BN, int MT, bool ATTN, int MODE>
__global__ void __launch_bounds__(256) tc_gemm(
    const __half* __restrict__ A, const __half* __restrict__ B,
    void* __restrict__ Cv, float* __restrict__ Aout, float* __restrict__ rowsum,
    int M, int K, int lda, int ldb, int ldc,
    int batchH, long long sAb, long long sAh, long long sBb, long long sBh,
    long long sCb, long long sCh,
    float scale, const float* __restrict__ bias, const float* __restrict__ res,
    const __half* __restrict__ h2p, const float* __restrict__ cwgt,
    const float* __restrict__ beta_ptr)
{
    constexpr int WN  = BN / 64;
    constexpr int AI  = BM / 64;
    constexpr int BI  = BN / 64;
    constexpr int STG = (BM + BN) * SPAD;   // 32-bit words per stage
    constexpr bool OUTH = (MODE == 1 || MODE == 2 || MODE == 5 || MODE == 6);

    extern __shared__ uint32_t sm[];
    uint32_t sbase = smem_u32(sm);

    int z = blockIdx.z;
    int zb = z / batchH, zh = z - zb * batchH;
    A += (long long)zb * sAb + (long long)zh * sAh;
    B += (long long)zb * sBb + (long long)zh * sBh;
    float*  Cf = (float*)Cv  + (OUTH ? 0 : ((long long)zb * sCb + (long long)zh * sCh));
    __half* Ch = (__half*)Cv + (OUTH ? ((long long)zb * sCb + (long long)zh * sCh) : 0);

    int tid = threadIdx.x;
    int wid = tid >> 5, lane = tid & 31;
    int wm = wid / WN, wn = wid % WN;
    int g = lane >> 2, t = lane & 3;
    int m0 = blockIdx.y * BM, n0 = blockIdx.x * BN;

    float acc[MT][8][4];
    #pragma unroll
    for (int i = 0; i < MT; i++)
        #pragma unroll
        for (int j = 0; j < 8; j++)
            #pragma unroll
            for (int q = 0; q < 4; q++) acc[i][j][q] = 0.f;

    int lr0 = tid >> 2;
    int lw0 = (tid & 3) * 4;       // word offset in smem row
    int hc0 = (tid & 3) * 8;       // half offset in gmem row
    const __half* Ag = A + (long long)(m0 + lr0) * lda + hc0;
    const __half* Bg = B + (long long)(n0 + lr0) * ldb + hc0;
    int NC = K / KC;

    float invL[AI];
    float* AoutB = nullptr;
    if (ATTN) {
        const float* rs = rowsum + (long long)z * M;
        #pragma unroll
        for (int i = 0; i < AI; i++) invL[i] = 1.f / rs[m0 + lr0 + i * 64];
        AoutB = Aout + (long long)zb * sAb + (long long)zh * sAh;
    }

    auto issue = [&](int c) {
        int s = c % 3;
        uint32_t ab = sbase + (uint32_t)(s * STG) * 4u;
        uint32_t bb = ab + (uint32_t)(BM * SPAD) * 4u;
        const __half* Ap = Ag + c * KC;
        #pragma unroll
        for (int i = 0; i < AI; i++) {
            cp16(ab + (uint32_t)((lr0 + i * 64) * SPAD + lw0) * 4u,
                 Ap + (long long)(i * 64) * lda);
            cp16(ab + (uint32_t)((lr0 + i * 64) * SPAD + lw0 + 16) * 4u,
                 Ap + (long long)(i * 64) * lda + 32);
        }
        const __half* Bp = Bg + c * KC;
        #pragma unroll
        for (int i = 0; i < BI; i++) {
            cp16(bb + (uint32_t)((lr0 + i * 64) * SPAD + lw0) * 4u,
                 Bp + (long long)(i * 64) * ldb);
            cp16(bb + (uint32_t)((lr0 + i * 64) * SPAD + lw0 + 16) * 4u,
                 Bp + (long long)(i * 64) * ldb + 32);
        }
    };

    issue(0); CP_COMMIT();
    if (NC > 1) issue(1);
    CP_COMMIT();

    for (int c = 0; c < NC; c++) {
        int s = c % 3;
        uint32_t* stA = sm + s * STG;
        uint32_t* stB = stA + BM * SPAD;

        CP_WAIT1();
        __syncthreads();

        if (ATTN) {   // stream normalized fp32 attention weights out of smem
            #pragma unroll
            for (int i = 0; i < AI; i++) {
                #pragma unroll
                for (int jj = 0; jj < 2; jj++) {
                    uint4 w = *reinterpret_cast<uint4*>(
                        &stA[(lr0 + i * 64) * SPAD + lw0 + jj * 16]);
                    __half2 p0 = *reinterpret_cast<__half2*>(&w.x);
                    __half2 p1 = *reinterpret_cast<__half2*>(&w.y);
                    __half2 p2 = *reinterpret_cast<__half2*>(&w.z);
                    __half2 p3 = *reinterpret_cast<__half2*>(&w.w);
                    float iv = invL[i];
                    float4 o0 = make_float4(__low2float(p0) * iv, __high2float(p0) * iv,
                                            __low2float(p1) * iv, __high2float(p1) * iv);
                    float4 o1 = make_float4(__low2float(p2) * iv, __high2float(p2) * iv,
                                            __low2float(p3) * iv, __high2float(p3) * iv);
                    float* dst = AoutB + (long long)(m0 + lr0 + i * 64) * lda
                                 + c * KC + hc0 + jj * 32;
                    *reinterpret_cast<float4*>(dst)     = o0;
                    *reinterpret_cast<float4*>(dst + 4) = o1;
                }
            }
        }

        if (c + 2 < NC) issue(c + 2);
        CP_COMMIT();

        #pragma unroll
        for (int ks = 0; ks < 4; ks++) {           // 4 x k16 per 64-chunk
            int kk = ks * 8;                        // word offset
            uint32_t af[MT][4], bf[8][2];
            #pragma unroll
            for (int mt = 0; mt < MT; mt++) {
                int row = wm * (MT * 16) + mt * 16 + g;
                af[mt][0] = stA[row * SPAD + kk + t];
                af[mt][1] = stA[(row + 8) * SPAD + kk + t];
                af[mt][2] = stA[row * SPAD + kk + t + 4];
                af[mt][3] = stA[(row + 8) * SPAD + kk + t + 4];
            }
            #pragma unroll
            for (int nt = 0; nt < 8; nt++) {
                int col = wn * 64 + nt * 8 + g;
                bf[nt][0] = stB[col * SPAD + kk + t];
                bf[nt][1] = stB[col * SPAD + kk + t + 4];
            }
            #pragma unroll
            for (int mt = 0; mt < MT; mt++)
                #pragma unroll
                for (int nt = 0; nt < 8; nt++)
                    mma_f16(acc[mt][nt], af[mt], bf[nt]);
        }
    }

    // ---------------- epilogue ----------------
    float betav = (MODE == 4) ? beta_ptr[0] : 0.f;
    const float* rsE = (MODE == 6) ? rowsum + (long long)z * M : nullptr;
    float* rsA = (MODE == 5) ? rowsum + (long long)z * M : nullptr;

    #pragma unroll
    for (int mt = 0; mt < MT; mt++) {
        int r0 = m0 + wm * (MT * 16) + mt * 16 + g;
        int r1 = r0 + 8;
        float cw0 = 0.f, cw1 = 0.f, inv0 = 0.f, inv1 = 0.f;
        if (MODE == 4) { cw0 = cwgt[r0]; cw1 = cwgt[r1]; }
        if (MODE == 6) { inv0 = 1.f / rsE[r0]; inv1 = 1.f / rsE[r1]; }
        float s0 = 0.f, s1 = 0.f;
        #pragma unroll
        for (int nt = 0; nt < 8; nt++) {
            int n = n0 + wn * 64 + nt * 8 + 2 * t;
            long long co0 = (long long)r0 * ldc + n;
            long long co1 = (long long)r1 * ldc + n;
            float v00 = acc[mt][nt][0], v01 = acc[mt][nt][1];
            float v10 = acc[mt][nt][2], v11 = acc[mt][nt][3];
            if (MODE == 1) {
                *reinterpret_cast<__half2*>(Ch + co0) = __floats2half2_rn(v00, v01);
                *reinterpret_cast<__half2*>(Ch + co1) = __floats2half2_rn(v10, v11);
            } else if (MODE == 2) {
                float b0 = bias[n], b1 = bias[n + 1];
                *reinterpret_cast<__half2*>(Ch + co0) =
                    __floats2half2_rn(geluf(v00 + b0), geluf(v01 + b1));
                *reinterpret_cast<__half2*>(Ch + co1) =
                    __floats2half2_rn(geluf(v10 + b0), geluf(v11 + b1));
            } else if (MODE == 3) {
                float b0 = bias ? bias[n] : 0.f, b1 = bias ? bias[n + 1] : 0.f;
                float2 q0 = *reinterpret_cast<const float2*>(res + co0);
                float2 q1 = *reinterpret_cast<const float2*>(res + co1);
                *reinterpret_cast<float2*>(Cf + co0) =
                    make_float2(q0.x + v00 + b0, q0.y + v01 + b1);
                *reinterpret_cast<float2*>(Cf + co1) =
                    make_float2(q1.x + v10 + b0, q1.y + v11 + b1);
            } else if (MODE == 4) {
                float b0 = bias[n], b1 = bias[n + 1];
                float2 q0 = *reinterpret_cast<const float2*>(res + co0);
                float2 q1 = *reinterpret_cast<const float2*>(res + co1);
                __half2 hh0 = *reinterpret_cast<const __half2*>(h2p + co0);
                __half2 hh1 = *reinterpret_cast<const __half2*>(h2p + co1);
                *reinterpret_cast<float2*>(Cf + co0) = make_float2(
                    q0.x + betav * __low2float(hh0) + cw0 * (v00 + b0),
                    q0.y + betav * __high2float(hh0) + cw0 * (v01 + b1));
                *reinterpret_cast<float2*>(Cf + co1) = make_float2(
                    q1.x + betav * __low2float(hh1) + cw1 * (v10 + b0),
                    q1.y + betav * __high2float(hh1) + cw1 * (v11 + b1));
            } else if (MODE == 5) {
                __half2 e0 = __floats2half2_rn(__expf(v00 * scale), __expf(v01 * scale));
                __half2 e1 = __floats2half2_rn(__expf(v10 * scale), __expf(v11 * scale));
                *reinterpret_cast<__half2*>(Ch + co0) = e0;
                *reinterpret_cast<__half2*>(Ch + co1) = e1;
                s0 += __low2float(e0) + __high2float(e0);
                s1 += __low2float(e1) + __high2float(e1);
            } else { // MODE == 6
                *reinterpret_cast<__half2*>(Ch + co0) =
                    __floats2half2_rn(v00 * inv0, v01 * inv0);
                *reinterpret_cast<__half2*>(Ch + co1) =
                    __floats2half2_rn(v10 * inv1, v11 * inv1);
            }
        }
        if (MODE == 5) {
            s0 += __shfl_xor_sync(0xffffffffu, s0, 1);
            s0 += __shfl_xor_sync(0xffffffffu, s0, 2);
            s1 += __shfl_xor_sync(0xffffffffu, s1, 1);
            s1 += __shfl_xor_sync(0xffffffffu, s1, 2);
            if (t == 0) {
                atomicAdd(rsA + r0, s0);
                atomicAdd(rsA + r1, s1);
            }
        }
    }
}

// ---------------- zero kernel ----------------
__global__ void __launch_bounds__(256) zero_kernel(float* p, int n) {
    int i = blockIdx.x * 256 + threadIdx.x;
    if (i < n) p[i] = 0.f;
}

// ---------------- transpose (templated in/out types; out = fp16) ----------------
template<typename TI>
__global__ void __launch_bounds__(256) transpose_kernel(
    const TI* __restrict__ in, __half* __restrict__ out,
    int R, int C, int ldi, int ldo,
    int batchH, long long sIb, long long sIh, long long sOb, long long sOh)
{
    __shared__ float tile[32][33];
    int z = blockIdx.z;
    int zb = z / batchH, zh = z - zb * batchH;
    in  += (long long)zb * sIb + (long long)zh * sIh;
    out += (long long)zb * sOb + (long long)zh * sOh;
    int r0 = blockIdx.y * 32, c0 = blockIdx.x * 32;
    int tx = threadIdx.x & 31, ty = threadIdx.x >> 5;
    #pragma unroll
    for (int i = 0; i < 4; i++) {
        int r = r0 + ty + i * 8, c = c0 + tx;
        if (r < R && c < C) tile[ty + i * 8][tx] = (float)in[(long long)r * ldi + c];
    }
    __syncthreads();
    #pragma unroll
    for (int i = 0; i < 4; i++) {
        int c = c0 + ty + i * 8, r = r0 + tx;
        if (r < R && c < C)
            out[(long long)c * ldo + r] = __float2half_rn(tile[tx][ty + i * 8]);
    }
}

// ---------------- layernorm: fp32 in, fp16 out ----------------
__device__ __forceinline__ float brsum(float v, float* sh) {
    int t = threadIdx.x;
    sh[t] = v; __syncthreads();
    #pragma unroll
    for (int s = 128; s > 0; s >>= 1) { if (t < s) sh[t] += sh[t + s]; __syncthreads(); }
    float r = sh[0]; __syncthreads();
    return r;
}

__global__ void __launch_bounds__(256) ln_kernel(
    const float* __restrict__ x, __half* __restrict__ y,
    const float* __restrict__ g, const float* __restrict__ b,
    float* __restrict__ cwgt, const float* __restrict__ alpha_ptr)
{
    long long base = (long long)blockIdx.x * DD;
    int t = threadIdx.x;
    __shared__ float sh[256];
    float xv[4];
    float s = 0.f;
    #pragma unroll
    for (int i = 0; i < 4; i++) { xv[i] = x[base + t + i * 256]; s += xv[i]; }
    s = brsum(s, sh);
    float mu = s * (1.0f / DD);
    float vs = 0.f;
    #pragma unroll
    for (int i = 0; i < 4; i++) { float d = xv[i] - mu; vs += d * d; }
    vs = brsum(vs, sh);
    float inv = rsqrtf(vs * (1.0f / DD) + 1e-5f);
    float ss = 0.f;
    #pragma unroll
    for (int i = 0; i < 4; i++) {
        int c = t + i * 256;
        float yv = (xv[i] - mu) * inv * g[c] + b[c];
        y[base + c] = __float2half_rn(yv);
        ss += yv * yv;
    }
    if (cwgt) {
        ss = brsum(ss, sh);
        if (t == 0) cwgt[blockIdx.x] = expf(-alpha_ptr[0] * sqrtf(ss));
    }
}

// ---------------- Qg = Q*cos(ph[h]) - V*sin(ph[h]) (fp16, packed QKV) ----------------
__global__ void __launch_bounds__(256) qg_kernel(
    const __half* __restrict__ QKV, const float* __restrict__ phase,
    __half* __restrict__ Qg)
{
    int i = blockIdx.x * 256 + threadIdx.x;
    if (i >= NELT) return;
    int tok = i >> 10, col = i & (DD - 1);
    int h = col >> 6;
    float p = phase[h];
    long long base = (long long)tok * (3 * DD) + col;
    Qg[i] = __float2half_rn(__half2float(QKV[base]) * cosf(p)
                            - __half2float(QKV[base + 2 * DD]) * sinf(p));
}

// ---------------- host helpers ----------------
template<int BM, int BN, int MT, bool ATTN, int MODE>
static void run_gemm(const __half* A, const __half* B, void* C, float* Aout, float* rowsum,
    int M, int N, int K, int lda, int ldb, int ldc,
    int batch, int batchH,
    long long sAb, long long sAh, long long sBb, long long sBh,
    long long sCb, long long sCh,
    float scale, const float* bias, const float* res,
    const __half* h2p, const float* cwgt, const float* betap)
{
    int smem = 3 * (BM + BN) * SPAD * 4;
    cudaFuncSetAttribute(tc_gemm<BM, BN, MT, ATTN, MODE>,
                         cudaFuncAttributeMaxDynamicSharedMemorySize, smem);
    dim3 grid(N / BN, M / BM, batch);
    tc_gemm<BM, BN, MT, ATTN, MODE><<<grid, 256, smem>>>(
        A, B, C, Aout, rowsum, M, K, lda, ldb, ldc,
        batchH, sAb, sAh, sBb, sBh, sCb, sCh,
        scale, bias, res, h2p, cwgt, betap);
}

template<typename TI>
static void launch_tr(const TI* in, __half* out, int R, int C, int ldi, int ldo,
    int batch, int batchH, long long sIb, long long sIh, long long sOb, long long sOh)
{
    dim3 grid((C + 31) / 32, (R + 31) / 32, batch);
    transpose_kernel<TI><<<grid, 256>>>(in, out, R, C, ldi, ldo,
                                        batchH, sIb, sIh, sOb, sOh);
}

extern "C" void kernel_launch(void* const* d_in, const int* in_sizes, int n_in,
                              void* d_out, int out_size)
{
    const float* x     = (const float*)d_in[0];
    const float* wq    = (const float*)d_in[1];
    const float* wk    = (const float*)d_in[2];
    const float* wv    = (const float*)d_in[3];
    const float* wo    = (const float*)d_in[4];
    const float* phase = (const float*)d_in[5];
    const float* cw1   = (const float*)d_in[6];
    const float* cb1   = (const float*)d_in[7];
    const float* cw2   = (const float*)d_in[8];
    const float* cb2   = (const float*)d_in[9];
    const float* alpha = (const float*)d_in[10];
    const float* beta  = (const float*)d_in[11];
    const float* fw1   = (const float*)d_in[12];
    const float* fb1   = (const float*)d_in[13];
    const float* fw2   = (const float*)d_in[14];
    const float* fb2   = (const float*)d_in[15];
    const float* ln1g  = (const float*)d_in[16];
    const float* ln1b  = (const float*)d_in[17];
    const float* ln2g  = (const float*)d_in[18];
    const float* ln2b  = (const float*)d_in[19];
    const float* ln3g  = (const float*)d_in[20];
    const float* ln3b  = (const float*)d_in[21];

    static __half *p_h=0,*p_QKV=0,*p_Qg=0,*p_VT=0,*p_ctx=0,*p_h2=0,*p_t1=0,*p_ff1=0,
                  *p_wqkvT=0,*p_woT=0,*p_cw1T=0,*p_cw2T=0,*p_fw1T=0,*p_fw2T=0,*p_e=0;
    static float *p_x1=0,*p_x2=0,*p_cwgt=0,*p_rowsum=0,*p_attn_fb=0;
    if (!p_h) {
        cudaGetSymbolAddress((void**)&p_h,    g_h);
        cudaGetSymbolAddress((void**)&p_QKV,  g_QKV);
        cudaGetSymbolAddress((void**)&p_Qg,   g_Qg);
        cudaGetSymbolAddress((void**)&p_VT,   g_VT);
        cudaGetSymbolAddress((void**)&p_ctx,  g_ctx);
        cudaGetSymbolAddress((void**)&p_x1,   g_x1);
        cudaGetSymbolAddress((void**)&p_h2,   g_h2);
        cudaGetSymbolAddress((void**)&p_x2,   g_x2);
        cudaGetSymbolAddress((void**)&p_t1,   g_t1);
        cudaGetSymbolAddress((void**)&p_ff1,  g_ff1);
        cudaGetSymbolAddress((void**)&p_cwgt, g_cwgt);
        cudaGetSymbolAddress((void**)&p_rowsum, g_rowsum);
        cudaGetSymbolAddress((void**)&p_e,    g_e);
        cudaGetSymbolAddress((void**)&p_attn_fb, g_attn_fb);
        cudaGetSymbolAddress((void**)&p_wqkvT, g_wqkvT);
        cudaGetSymbolAddress((void**)&p_woT,  g_woT);
        cudaGetSymbolAddress((void**)&p_cw1T, g_cw1T);
        cudaGetSymbolAddress((void**)&p_cw2T, g_cw2T);
        cudaGetSymbolAddress((void**)&p_fw1T, g_fw1T);
        cudaGetSymbolAddress((void**)&p_fw2T, g_fw2T);
    }

    float* out_x = (float*)d_out;
    long long need = (long long)NELT + ASZ;
    float* attn = ((long long)out_size >= need) ? (out_x + NELT) : p_attn_fb;

    // weight transposes (fp32 -> fp16, W[K,N] -> WT[N,K]); qkv packed [3072,1024]
    launch_tr(wq,  p_wqkvT,             DD,   DD,  DD,   DD,   1, 1, 0,0,0,0);
    launch_tr(wk,  p_wqkvT + DD*DD,     DD,   DD,  DD,   DD,   1, 1, 0,0,0,0);
    launch_tr(wv,  p_wqkvT + 2*DD*DD,   DD,   DD,  DD,   DD,   1, 1, 0,0,0,0);
    launch_tr(wo,  p_woT,  DD,   DD,  DD,   DD,   1, 1, 0,0,0,0);
    launch_tr(cw1, p_cw1T, DD,   2*DD, 2*DD, DD,  1, 1, 0,0,0,0);
    launch_tr(cw2, p_cw2T, 2*DD, DD,  DD,   2*DD, 1, 1, 0,0,0,0);
    launch_tr(fw1, p_fw1T, DD,   FFN, FFN,  DD,   1, 1, 0,0,0,0);
    launch_tr(fw2, p_fw2T, FFN,  DD,  DD,   FFN,  1, 1, 0,0,0,0);

    // 0) zero row sums
    zero_kernel<<<(NROWS + 255) / 256, 256>>>(p_rowsum, NROWS);

    // 1) h = LN1(x)  (fp16)
    ln_kernel<<<NTOK, 256>>>(x, p_h, ln1g, ln1b, nullptr, nullptr);

    // 2) QKV = h @ [wq|wk|wv]  (one GEMM, N=3072, fp16 out)
    run_gemm<256,128,4,false,1>(p_h, p_wqkvT, p_QKV, 0, 0, NTOK, 3*DD, DD,
                                DD, DD, 3*DD,
                                1,1, 0,0,0,0,0,0, 1.f, 0,0,0,0,0);

    // 3) Qg (fp16)
    qg_kernel<<<(NELT + 255) / 256, 256>>>(p_QKV, phase, p_Qg);

    // 3b) VT[b,h,d,s] = V[b,s,h,d]  (fp16 -> fp16)
    launch_tr(p_QKV + 2*DD, p_VT, SS, DKK, 3*DD, SS,
              BB * HH, HH,
              (long long)SS * 3*DD, DKK,
              (long long)HH * DKK * SS, (long long)DKK * SS);

    // 4) e = h(exp(Qg @ K^T / 8)) + row sums of rounded e
    run_gemm<256,128,4,false,5>(p_Qg, p_QKV + DD, p_e, 0, p_rowsum,
                                SS, SS, DKK, DD, 3*DD, SS,
                                BB * HH, HH,
                                (long long)SS * DD, DKK,
                                (long long)SS * 3*DD, DKK,
                                (long long)HH * SS * SS, (long long)SS * SS,
                                0.125f, 0,0,0,0,0);

    // 5+6) ctx = (e/rowsum) @ V  — streams normalized fp32 attn_weights
    run_gemm<128,64,1,true,6>(p_e, p_VT, p_ctx, attn, p_rowsum,
                              SS, DKK, SS, SS, SS, DD,
                              BB * HH, HH,
                              (long long)HH * SS * SS, (long long)SS * SS,
                              (long long)HH * DKK * SS, (long long)DKK * SS,
                              (long long)SS * DD, DKK,
                              1.f, 0,0,0,0,0);

    // 7) x1 = x + ctx @ wo  (fp32 out)
    run_gemm<256,128,4,false,3>(p_ctx, p_woT, p_x1, 0, 0, NTOK, DD, DD, DD, DD, DD,
                                1,1, 0,0,0,0,0,0, 1.f, 0, x, 0,0,0);

    // 8) h2 = LN2(x1) + cwgt  (fp16)
    ln_kernel<<<NTOK, 256>>>(p_x1, p_h2, ln2g, ln2b, p_cwgt, alpha);

    // 9) t1 = gelu(h2 @ cw1 + cb1)  (fp16 out)
    run_gemm<256,128,4,false,2>(p_h2, p_cw1T, p_t1, 0, 0, NTOK, 2*DD, DD, DD, DD, 2*DD,
                                1,1, 0,0,0,0,0,0, 1.f, cb1, 0,0,0,0);

    // 10) x2 = x1 + beta*h2 + cwgt*(t1 @ cw2 + cb2)  (fp32 out)
    run_gemm<256,128,4,false,4>(p_t1, p_cw2T, p_x2, 0, 0, NTOK, DD, 2*DD, 2*DD, 2*DD, DD,
                                1,1, 0,0,0,0,0,0, 1.f, cb2, p_x1, p_h2, p_cwgt, beta);

    // 11) h3 = LN3(x2)  (fp16)
    ln_kernel<<<NTOK, 256>>>(p_x2, p_h, ln3g, ln3b, nullptr, nullptr);

    // 12) ff1 = gelu(h3 @ fw1 + fb1)  (fp16 out)
    run_gemm<256,128,4,false,2>(p_h, p_fw1T, p_ff1, 0, 0, NTOK, FFN, DD, DD, DD, FFN,
                                1,1, 0,0,0,0,0,0, 1.f, fb1, 0,0,0,0);

    // 13) out = x2 + ff1 @ fw2 + fb2  (fp32 out)
    run_gemm<256,128,4,false,3>(p_ff1, p_fw2T, out_x, 0, 0, NTOK, DD, FFN, FFN, FFN, DD,
                                1,1, 0,0,0,0,0,0, 1.f, fb2, p_x2, 0,0,0);
}

// round 13
// speedup vs baseline: 6.3337x; 1.0032x over previous
#include <cuda_runtime.h>
#include <cuda_fp16.h>
#include <math.h>
#include <stdint.h>

// ---------------- problem constants ----------------
#define BB   4
#define SS   2048
#define DD   1024
#define HH   16
#define DKK  64
#define FFN  4096
#define NTOK (BB*SS)
#define NELT (NTOK*DD)
#define ASZ  ((long long)BB*HH*SS*SS)
#define NROWS (BB*HH*SS)

#define KC    64   // K-chunk in fp16 elements (= 32 words = 128B per row)
#define SPAD  36   // smem row stride in 32-bit words (32 data + 4 pad)

// ---------------- scratch (device globals) ----------------
__device__ __half g_h  [NELT];
__device__ __half g_QKV[NTOK*3*DD];
__device__ __half g_Qg [NELT];
__device__ __half g_VT [NELT];
__device__ __half g_ctx[NELT];
__device__ float  g_x1 [NELT];
__device__ __half g_h2 [NELT];
__device__ float  g_x2 [NELT];
__device__ __half g_t1 [NTOK*2*DD];
__device__ __half g_ff1[NTOK*FFN];
__device__ float  g_cwgt[NTOK];
__device__ float  g_rowsum[NROWS];
__device__ __half g_wqkvT[3*DD*DD];
__device__ __half g_woT [DD*DD];
__device__ __half g_cw1T[DD*2*DD];
__device__ __half g_cw2T[2*DD*DD];
__device__ __half g_fw1T[DD*FFN];
__device__ __half g_fw2T[DD*FFN];
__device__ __half g_e   [(size_t)ASZ];   // unnormalized exp(scores), fp16
__device__ float  g_attn_fb[(size_t)ASZ];// fallback fp32 attn output

// ---------------- helpers ----------------
__device__ __forceinline__ uint32_t smem_u32(const void* p) {
    uint32_t a;
    asm("{ .reg .u64 t; cvta.to.shared.u64 t, %1; cvt.u32.u64 %0, t; }"
        : "=r"(a) : "l"(p));
    return a;
}
__device__ __forceinline__ float geluf(float x) {
    return 0.5f * x * (1.0f + erff(x * 0.70710678118654752f));
}
__device__ __forceinline__ void mma_f16(float* d, const uint32_t* a, const uint32_t* b) {
    asm volatile(
        "mma.sync.aligned.m16n8k16.row.col.f32.f16.f16.f32 "
        "{%0,%1,%2,%3}, {%4,%5,%6,%7}, {%8,%9}, {%0,%1,%2,%3};"
        : "+f"(d[0]), "+f"(d[1]), "+f"(d[2]), "+f"(d[3])
        : "r"(a[0]), "r"(a[1]), "r"(a[2]), "r"(a[3]), "r"(b[0]), "r"(b[1]));
}
__device__ __forceinline__ void cp16(uint32_t dst, const void* src) {
    asm volatile("cp.async.cg.shared.global [%0], [%1], 16;"
                 :: "r"(dst), "l"(src) : "memory");
}
#define CP_COMMIT() asm volatile("cp.async.commit_group;" ::: "memory")
#define CP_WAIT1()  asm volatile("cp.async.wait_group 1;" ::: "memory")

// ---------------- templated fp16 tensor-core GEMM ----------------
// C = A[M,K] @ B[N,K]^T, A/B fp16 (pre-rounded at producers), fp32 accumulate.
// K-chunk 64 elements, 3-stage cp.async pipeline; 8 warps, 256 thr.
// MODE: 1 = acc -> half             2 = gelu(acc+bias) -> half
//       3 = res + acc (+bias) -> float
//       4 = res + beta*h2 + cwgt[m]*(acc+bias) -> float
//       5 = e=h(exp(acc*scale)) -> half, atomic row sums of rounded e
//       6 = h(acc * inv_rowsum[m]) -> half (ctx; ATTN streams fp32 attn)
template<int BM, int BN, int MT, bool ATTN, int MODE>
__global__ void __launch_bounds__(256) tc_gemm(
    const __half* __restrict__ A, const __half* __restrict__ B,
    void* __restrict__ Cv, float* __restrict__ Aout, float* __restrict__ rowsum,
    int M, int K, int lda, int ldb, int ldc,
    int batchH, long long sAb, long long sAh, long long sBb, long long sBh,
    long long sCb, long long sCh,
    float scale, const float* __restrict__ bias, const float* __restrict__ res,
    const __half* __restrict__ h2p, const float* __restrict__ cwgt,
    const float* __restrict__ beta_ptr)
{
    constexpr int WN  = BN / 64;
    constexpr int AI  = BM / 64;
    constexpr int BI  = BN / 64;
    constexpr int STG = (BM + BN) * SPAD;   // 32-bit words per stage
    constexpr bool OUTH = (MODE == 1 || MODE == 2 || MODE == 5 || MODE == 6);

    extern __shared__ uint32_t sm[];
    uint32_t sbase = smem_u32(sm);

    int z = blockIdx.z;
    int zb = z / batchH, zh = z - zb * batchH;
    A += (long long)zb * sAb + (long long)zh * sAh;
    B += (long long)zb * sBb + (long long)zh * sBh;
    float*  Cf = (float*)Cv  + (OUTH ? 0 : ((long long)zb * sCb + (long long)zh * sCh));
    __half* Ch = (__half*)Cv + (OUTH ? ((long long)zb * sCb + (long long)zh * sCh) : 0);

    int tid = threadIdx.x;
    int wid = tid >> 5, lane = tid & 31;
    int wm = wid / WN, wn = wid % WN;
    int g = lane >> 2, t = lane & 3;
    int m0 = blockIdx.y * BM, n0 = blockIdx.x * BN;

    float acc[MT][8][4];
    #pragma unroll
    for (int i = 0; i < MT; i++)
        #pragma unroll
        for (int j = 0; j < 8; j++)
            #pragma unroll
            for (int q = 0; q < 4; q++) acc[i][j][q] = 0.f;

    int lr0 = tid >> 2;
    int lw0 = (tid & 3) * 4;       // word offset in smem row
    int hc0 = (tid & 3) * 8;       // half offset in gmem row
    const __half* Ag = A + (long long)(m0 + lr0) * lda + hc0;
    const __half* Bg = B + (long long)(n0 + lr0) * ldb + hc0;
    int NC = K / KC;

    float invL[AI];
    float* AoutB = nullptr;
    if (ATTN) {
        const float* rs = rowsum + (long long)z * M;
        #pragma unroll
        for (int i = 0; i < AI; i++) invL[i] = 1.f / rs[m0 + lr0 + i * 64];
        AoutB = Aout + (long long)zb * sAb + (long long)zh * sAh;
    }

    auto issue = [&](int c) {
        int s = c % 3;
        uint32_t ab = sbase + (uint32_t)(s * STG) * 4u;
        uint32_t bb = ab + (uint32_t)(BM * SPAD) * 4u;
        const __half* Ap = Ag + c * KC;
        #pragma unroll
        for (int i = 0; i < AI; i++) {
            cp16(ab + (uint32_t)((lr0 + i * 64) * SPAD + lw0) * 4u,
                 Ap + (long long)(i * 64) * lda);
            cp16(ab + (uint32_t)((lr0 + i * 64) * SPAD + lw0 + 16) * 4u,
                 Ap + (long long)(i * 64) * lda + 32);
        }
        const __half* Bp = Bg + c * KC;
        #pragma unroll
        for (int i = 0; i < BI; i++) {
            cp16(bb + (uint32_t)((lr0 + i * 64) * SPAD + lw0) * 4u,
                 Bp + (long long)(i * 64) * ldb);
            cp16(bb + (uint32_t)((lr0 + i * 64) * SPAD + lw0 + 16) * 4u,
                 Bp + (long long)(i * 64) * ldb + 32);
        }
    };

    issue(0); CP_COMMIT();
    if (NC > 1) issue(1);
    CP_COMMIT();

    for (int c = 0; c < NC; c++) {
        int s = c % 3;
        uint32_t* stA = sm + s * STG;
        uint32_t* stB = stA + BM * SPAD;

        CP_WAIT1();
        __syncthreads();

        if (ATTN) {   // stream normalized fp32 attention weights out of smem
            #pragma unroll
            for (int i = 0; i < AI; i++) {
                #pragma unroll
                for (int jj = 0; jj < 2; jj++) {
                    uint4 w = *reinterpret_cast<uint4*>(
                        &stA[(lr0 + i * 64) * SPAD + lw0 + jj * 16]);
                    __half2 p0 = *reinterpret_cast<__half2*>(&w.x);
                    __half2 p1 = *reinterpret_cast<__half2*>(&w.y);
                    __half2 p2 = *reinterpret_cast<__half2*>(&w.z);
                    __half2 p3 = *reinterpret_cast<__half2*>(&w.w);
                    float iv = invL[i];
                    float4 o0 = make_float4(__low2float(p0) * iv, __high2float(p0) * iv,
                                            __low2float(p1) * iv, __high2float(p1) * iv);
                    float4 o1 = make_float4(__low2float(p2) * iv, __high2float(p2) * iv,
                                            __low2float(p3) * iv, __high2float(p3) * iv);
                    float* dst = AoutB + (long long)(m0 + lr0 + i * 64) * lda
                                 + c * KC + hc0 + jj * 32;
                    *reinterpret_cast<float4*>(dst)     = o0;
                    *reinterpret_cast<float4*>(dst + 4) = o1;
                }
            }
        }

        if (c + 2 < NC) issue(c + 2);
        CP_COMMIT();

        #pragma unroll
        for (int ks = 0; ks < 4; ks++) {           // 4 x k16 per 64-chunk
            int kk = ks * 8;                        // word offset
            uint32_t af[MT][4], bf[8][2];
            #pragma unroll
            for (int mt = 0; mt < MT; mt++) {
                int row = wm * (MT * 16) + mt * 16 + g;
                af[mt][0] = stA[row * SPAD + kk + t];
                af[mt][1] = stA[(row + 8) * SPAD + kk + t];
                af[mt][2] = stA[row * SPAD + kk + t + 4];
                af[mt][3] = stA[(row + 8) * SPAD + kk + t + 4];
            }
            #pragma unroll
            for (int nt = 0; nt < 8; nt++) {
                int col = wn * 64 + nt * 8 + g;
                bf[nt][0] = stB[col * SPAD + kk + t];
                bf[nt][1] = stB[col * SPAD + kk + t + 4];
            }
            #pragma unroll
            for (int mt = 0; mt < MT; mt++)
                #pragma unroll
                for (int nt = 0; nt < 8; nt++)
                    mma_f16(acc[mt][nt], af[mt], bf[nt]);
        }
    }

    // ---------------- epilogue ----------------
    float betav = (MODE == 4) ? beta_ptr[0] : 0.f;
    const float* rsE = (MODE == 6) ? rowsum + (long long)z * M : nullptr;
    float* rsA = (MODE == 5) ? rowsum + (long long)z * M : nullptr;

    #pragma unroll
    for (int mt = 0; mt < MT; mt++) {
        int r0 = m0 + wm * (MT * 16) + mt * 16 + g;
        int r1 = r0 + 8;
        float cw0 = 0.f, cw1 = 0.f, inv0 = 0.f, inv1 = 0.f;
        if (MODE == 4) { cw0 = cwgt[r0]; cw1 = cwgt[r1]; }
        if (MODE == 6) { inv0 = 1.f / rsE[r0]; inv1 = 1.f / rsE[r1]; }
        float s0 = 0.f, s1 = 0.f;
        #pragma unroll
        for (int nt = 0; nt < 8; nt++) {
            int n = n0 + wn * 64 + nt * 8 + 2 * t;
            long long co0 = (long long)r0 * ldc + n;
            long long co1 = (long long)r1 * ldc + n;
            float v00 = acc[mt][nt][0], v01 = acc[mt][nt][1];
            float v10 = acc[mt][nt][2], v11 = acc[mt][nt][3];
            if (MODE == 1) {
                *reinterpret_cast<__half2*>(Ch + co0) = __floats2half2_rn(v00, v01);
                *reinterpret_cast<__half2*>(Ch + co1) = __floats2half2_rn(v10, v11);
            } else if (MODE == 2) {
                float b0 = bias[n], b1 = bias[n + 1];
                *reinterpret_cast<__half2*>(Ch + co0) =
                    __floats2half2_rn(geluf(v00 + b0), geluf(v01 + b1));
                *reinterpret_cast<__half2*>(Ch + co1) =
                    __floats2half2_rn(geluf(v10 + b0), geluf(v11 + b1));
            } else if (MODE == 3) {
                float b0 = bias ? bias[n] : 0.f, b1 = bias ? bias[n + 1] : 0.f;
                float2 q0 = *reinterpret_cast<const float2*>(res + co0);
                float2 q1 = *reinterpret_cast<const float2*>(res + co1);
                *reinterpret_cast<float2*>(Cf + co0) =
                    make_float2(q0.x + v00 + b0, q0.y + v01 + b1);
                *reinterpret_cast<float2*>(Cf + co1) =
                    make_float2(q1.x + v10 + b0, q1.y + v11 + b1);
            } else if (MODE == 4) {
                float b0 = bias[n], b1 = bias[n + 1];
                float2 q0 = *reinterpret_cast<const float2*>(res + co0);
                float2 q1 = *reinterpret_cast<const float2*>(res + co1);
                __half2 hh0 = *reinterpret_cast<const __half2*>(h2p + co0);
                __half2 hh1 = *reinterpret_cast<const __half2*>(h2p + co1);
                *reinterpret_cast<float2*>(Cf + co0) = make_float2(
                    q0.x + betav * __low2float(hh0) + cw0 * (v00 + b0),
                    q0.y + betav * __high2float(hh0) + cw0 * (v01 + b1));
                *reinterpret_cast<float2*>(Cf + co1) = make_float2(
                    q1.x + betav * __low2float(hh1) + cw1 * (v10 + b0),
                    q1.y + betav * __high2float(hh1) + cw1 * (v11 + b1));
            } else if (MODE == 5) {
                __half2 e0 = __floats2half2_rn(__expf(v00 * scale), __expf(v01 * scale));
                __half2 e1 = __floats2half2_rn(__expf(v10 * scale), __expf(v11 * scale));
                *reinterpret_cast<__half2*>(Ch + co0) = e0;
                *reinterpret_cast<__half2*>(Ch + co1) = e1;
                s0 += __low2float(e0) + __high2float(e0);
                s1 += __low2float(e1) + __high2float(e1);
            } else { // MODE == 6
                *reinterpret_cast<__half2*>(Ch + co0) =
                    __floats2half2_rn(v00 * inv0, v01 * inv0);
                *reinterpret_cast<__half2*>(Ch + co1) =
                    __floats2half2_rn(v10 * inv1, v11 * inv1);
            }
        }
        if (MODE == 5) {
            s0 += __shfl_xor_sync(0xffffffffu, s0, 1);
            s0 += __shfl_xor_sync(0xffffffffu, s0, 2);
            s1 += __shfl_xor_sync(0xffffffffu, s1, 1);
            s1 += __shfl_xor_sync(0xffffffffu, s1, 2);
            if (t == 0) {
                atomicAdd(rsA + r0, s0);
                atomicAdd(rsA + r1, s1);
            }
        }
    }
}

// ---------------- zero kernel ----------------
__global__ void __launch_bounds__(256) zero_kernel(float* p, int n) {
    int i = blockIdx.x * 256 + threadIdx.x;
    if (i < n) p[i] = 0.f;
}

// ---------------- transpose (templated in/out types; out = fp16) ----------------
template<typename TI>
__global__ void __launch_bounds__(256) transpose_kernel(
    const TI* __restrict__ in, __half* __restrict__ out,
    int R, int C, int ldi, int ldo,
    int batchH, long long sIb, long long sIh, long long sOb, long long sOh)
{
    __shared__ float tile[32][33];
    int z = blockIdx.z;
    int zb = z / batchH, zh = z - zb * batchH;
    in  += (long long)zb * sIb + (long long)zh * sIh;
    out += (long long)zb * sOb + (long long)zh * sOh;
    int r0 = blockIdx.y * 32, c0 = blockIdx.x * 32;
    int tx = threadIdx.x & 31, ty = threadIdx.x >> 5;
    #pragma unroll
    for (int i = 0; i < 4; i++) {
        int r = r0 + ty + i * 8, c = c0 + tx;
        if (r < R && c < C) tile[ty + i * 8][tx] = (float)in[(long long)r * ldi + c];
    }
    __syncthreads();
    #pragma unroll
    for (int i = 0; i < 4; i++) {
        int c = c0 + ty + i * 8, r = r0 + tx;
        if (r < R && c < C)
            out[(long long)c * ldo + r] = __float2half_rn(tile[tx][ty + i * 8]);
    }
}

// ---------------- layernorm: fp32 in, fp16 out ----------------
__device__ __forceinline__ float brsum(float v, float* sh) {
    int t = threadIdx.x;
    sh[t] = v; __syncthreads();
    #pragma unroll
    for (int s = 128; s > 0; s >>= 1) { if (t < s) sh[t] += sh[t + s]; __syncthreads(); }
    float r = sh[0]; __syncthreads();
    return r;
}

__global__ void __launch_bounds__(256) ln_kernel(
    const float* __restrict__ x, __half* __restrict__ y,
    const float* __restrict__ g, const float* __restrict__ b,
    float* __restrict__ cwgt, const float* __restrict__ alpha_ptr)
{
    long long base = (long long)blockIdx.x * DD;
    int t = threadIdx.x;
    __shared__ float sh[256];
    float xv[4];
    float s = 0.f;
    #pragma unroll
    for (int i = 0; i < 4; i++) { xv[i] = x[base + t + i * 256]; s += xv[i]; }
    s = brsum(s, sh);
    float mu = s * (1.0f / DD);
    float vs = 0.f;
    #pragma unroll
    for (int i = 0; i < 4; i++) { float d = xv[i] - mu; vs += d * d; }
    vs = brsum(vs, sh);
    float inv = rsqrtf(vs * (1.0f / DD) + 1e-5f);
    float ss = 0.f;
    #pragma unroll
    for (int i = 0; i < 4; i++) {
        int c = t + i * 256;
        float yv = (xv[i] - mu) * inv * g[c] + b[c];
        y[base + c] = __float2half_rn(yv);
        ss += yv * yv;
    }
    if (cwgt) {
        ss = brsum(ss, sh);
        if (t == 0) cwgt[blockIdx.x] = expf(-alpha_ptr[0] * sqrtf(ss));
    }
}

// ---------------- Qg = Q*cos(ph[h]) - V*sin(ph[h]) (fp16, packed QKV) ----------------
__global__ void __launch_bounds__(256) qg_kernel(
    const __half* __restrict__ QKV, const float* __restrict__ phase,
    __half* __restrict__ Qg)
{
    int i = blockIdx.x * 256 + threadIdx.x;
    if (i >= NELT) return;
    int tok = i >> 10, col = i & (DD - 1);
    int h = col >> 6;
    float p = phase[h];
    long long base = (long long)tok * (3 * DD) + col;
    Qg[i] = __float2half_rn(__half2float(QKV[base]) * cosf(p)
                            - __half2float(QKV[base + 2 * DD]) * sinf(p));
}

// ---------------- host helpers ----------------
template<int BM, int BN, int MT, bool ATTN, int MODE>
static void run_gemm(const __half* A, const __half* B, void* C, float* Aout, float* rowsum,
    int M, int N, int K, int lda, int ldb, int ldc,
    int batch, int batchH,
    long long sAb, long long sAh, long long sBb, long long sBh,
    long long sCb, long long sCh,
    float scale, const float* bias, const float* res,
    const __half* h2p, const float* cwgt, const float* betap)
{
    int smem = 3 * (BM + BN) * SPAD * 4;
    cudaFuncSetAttribute(tc_gemm<BM, BN, MT, ATTN, MODE>,
                         cudaFuncAttributeMaxDynamicSharedMemorySize, smem);
    dim3 grid(N / BN, M / BM, batch);
    tc_gemm<BM, BN, MT, ATTN, MODE><<<grid, 256, smem>>>(
        A, B, C, Aout, rowsum, M, K, lda, ldb, ldc,
        batchH, sAb, sAh, sBb, sBh, sCb, sCh,
        scale, bias, res, h2p, cwgt, betap);
}

template<typename TI>
static void launch_tr(const TI* in, __half* out, int R, int C, int ldi, int ldo,
    int batch, int batchH, long long sIb, long long sIh, long long sOb, long long sOh)
{
    dim3 grid((C + 31) / 32, (R + 31) / 32, batch);
    transpose_kernel<TI><<<grid, 256>>>(in, out, R, C, ldi, ldo,
                                        batchH, sIb, sIh, sOb, sOh);
}

extern "C" void kernel_launch(void* const* d_in, const int* in_sizes, int n_in,
                              void* d_out, int out_size)
{
    const float* x     = (const float*)d_in[0];
    const float* wq    = (const float*)d_in[1];
    const float* wk    = (const float*)d_in[2];
    const float* wv    = (const float*)d_in[3];
    const float* wo    = (const float*)d_in[4];
    const float* phase = (const float*)d_in[5];
    const float* cw1   = (const float*)d_in[6];
    const float* cb1   = (const float*)d_in[7];
    const float* cw2   = (const float*)d_in[8];
    const float* cb2   = (const float*)d_in[9];
    const float* alpha = (const float*)d_in[10];
    const float* beta  = (const float*)d_in[11];
    const float* fw1   = (const float*)d_in[12];
    const float* fb1   = (const float*)d_in[13];
    const float* fw2   = (const float*)d_in[14];
    const float* fb2   = (const float*)d_in[15];
    const float* ln1g  = (const float*)d_in[16];
    const float* ln1b  = (const float*)d_in[17];
    const float* ln2g  = (const float*)d_in[18];
    const float* ln2b  = (const float*)d_in[19];
    const float* ln3g  = (const float*)d_in[20];
    const float* ln3b  = (const float*)d_in[21];

    static __half *p_h=0,*p_QKV=0,*p_Qg=0,*p_VT=0,*p_ctx=0,*p_h2=0,*p_t1=0,*p_ff1=0,
                  *p_wqkvT=0,*p_woT=0,*p_cw1T=0,*p_cw2T=0,*p_fw1T=0,*p_fw2T=0,*p_e=0;
    static float *p_x1=0,*p_x2=0,*p_cwgt=0,*p_rowsum=0,*p_attn_fb=0;
    if (!p_h) {
        cudaGetSymbolAddress((void**)&p_h,    g_h);
        cudaGetSymbolAddress((void**)&p_QKV,  g_QKV);
        cudaGetSymbolAddress((void**)&p_Qg,   g_Qg);
        cudaGetSymbolAddress((void**)&p_VT,   g_VT);
        cudaGetSymbolAddress((void**)&p_ctx,  g_ctx);
        cudaGetSymbolAddress((void**)&p_x1,   g_x1);
        cudaGetSymbolAddress((void**)&p_h2,   g_h2);
        cudaGetSymbolAddress((void**)&p_x2,   g_x2);
        cudaGetSymbolAddress((void**)&p_t1,   g_t1);
        cudaGetSymbolAddress((void**)&p_ff1,  g_ff1);
        cudaGetSymbolAddress((void**)&p_cwgt, g_cwgt);
        cudaGetSymbolAddress((void**)&p_rowsum, g_rowsum);
        cudaGetSymbolAddress((void**)&p_e,    g_e);
        cudaGetSymbolAddress((void**)&p_attn_fb, g_attn_fb);
        cudaGetSymbolAddress((void**)&p_wqkvT, g_wqkvT);
        cudaGetSymbolAddress((void**)&p_woT,  g_woT);
        cudaGetSymbolAddress((void**)&p_cw1T, g_cw1T);
        cudaGetSymbolAddress((void**)&p_cw2T, g_cw2T);
        cudaGetSymbolAddress((void**)&p_fw1T, g_fw1T);
        cudaGetSymbolAddress((void**)&p_fw2T, g_fw2T);
    }

    float* out_x = (float*)d_out;
    long long need = (long long)NELT + ASZ;
    float* attn = ((long long)out_size >= need) ? (out_x + NELT) : p_attn_fb;

    // weight transposes (fp32 -> fp16, W[K,N] -> WT[N,K]); qkv packed [3072,1024]
    launch_tr(wq,  p_wqkvT,             DD,   DD,  DD,   DD,   1, 1, 0,0,0,0);
    launch_tr(wk,  p_wqkvT + DD*DD,     DD,   DD,  DD,   DD,   1, 1, 0,0,0,0);
    launch_tr(wv,  p_wqkvT + 2*DD*DD,   DD,   DD,  DD,   DD,   1, 1, 0,0,0,0);
    launch_tr(wo,  p_woT,  DD,   DD,  DD,   DD,   1, 1, 0,0,0,0);
    launch_tr(cw1, p_cw1T, DD,   2*DD, 2*DD, DD,  1, 1, 0,0,0,0);
    launch_tr(cw2, p_cw2T, 2*DD, DD,  DD,   2*DD, 1, 1, 0,0,0,0);
    launch_tr(fw1, p_fw1T, DD,   FFN, FFN,  DD,   1, 1, 0,0,0,0);
    launch_tr(fw2, p_fw2T, FFN,  DD,  DD,   FFN,  1, 1, 0,0,0,0);

    // 0) zero row sums
    zero_kernel<<<(NROWS + 255) / 256, 256>>>(p_rowsum, NROWS);

    // 1) h = LN1(x)  (fp16)
    ln_kernel<<<NTOK, 256>>>(x, p_h, ln1g, ln1b, nullptr, nullptr);

    // 2) QKV = h @ [wq|wk|wv]  (one GEMM, N=3072, fp16 out)
    run_gemm<256,128,4,false,1>(p_h, p_wqkvT, p_QKV, 0, 0, NTOK, 3*DD, DD,
                                DD, DD, 3*DD,
                                1,1, 0,0,0,0,0,0, 1.f, 0,0,0,0,0);

    // 3) Qg (fp16)
    qg_kernel<<<(NELT + 255) / 256, 256>>>(p_QKV, phase, p_Qg);

    // 3b) VT[b,h,d,s] = V[b,s,h,d]  (fp16 -> fp16)
    launch_tr(p_QKV + 2*DD, p_VT, SS, DKK, 3*DD, SS,
              BB * HH, HH,
              (long long)SS * 3*DD, DKK,
              (long long)HH * DKK * SS, (long long)DKK * SS);

    // 4) e = h(exp(Qg @ K^T / 8)) + row sums of rounded e
    run_gemm<256,128,4,false,5>(p_Qg, p_QKV + DD, p_e, 0, p_rowsum,
                                SS, SS, DKK, DD, 3*DD, SS,
                                BB * HH, HH,
                                (long long)SS * DD, DKK,
                                (long long)SS * 3*DD, DKK,
                                (long long)HH * SS * SS, (long long)SS * SS,
                                0.125f, 0,0,0,0,0);

    // 5+6) ctx = (e/rowsum) @ V  — streams normalized fp32 attn_weights
    run_gemm<128,64,1,true,6>(p_e, p_VT, p_ctx, attn, p_rowsum,
                              SS, DKK, SS, SS, SS, DD,
                              BB * HH, HH,
                              (long long)HH * SS * SS, (long long)SS * SS,
                              (long long)HH * DKK * SS, (long long)DKK * SS,
                              (long long)SS * DD, DKK,
                              1.f, 0,0,0,0,0);

    // 7) x1 = x + ctx @ wo  (fp32 out)
    run_gemm<256,128,4,false,3>(p_ctx, p_woT, p_x1, 0, 0, NTOK, DD, DD, DD, DD, DD,
                                1,1, 0,0,0,0,0,0, 1.f, 0, x, 0,0,0);

    // 8) h2 = LN2(x1) + cwgt  (fp16)
    ln_kernel<<<NTOK, 256>>>(p_x1, p_h2, ln2g, ln2b, p_cwgt, alpha);

    // 9) t1 = gelu(h2 @ cw1 + cb1)  (fp16 out)
    run_gemm<256,128,4,false,2>(p_h2, p_cw1T, p_t1, 0, 0, NTOK, 2*DD, DD, DD, DD, 2*DD,
                                1,1, 0,0,0,0,0,0, 1.f, cb1, 0,0,0,0);

    // 10) x2 = x1 + beta*h2 + cwgt*(t1 @ cw2 + cb2)  (fp32 out)
    run_gemm<256,128,4,false,4>(p_t1, p_cw2T, p_x2, 0, 0, NTOK, DD, 2*DD, 2*DD, 2*DD, DD,
                                1,1, 0,0,0,0,0,0, 1.f, cb2, p_x1, p_h2, p_cwgt, beta);

    // 11) h3 = LN3(x2)  (fp16)
    ln_kernel<<<NTOK, 256>>>(p_x2, p_h, ln3g, ln3b, nullptr, nullptr);

    // 12) ff1 = gelu(h3 @ fw1 + fb1)  (fp16 out)
    run_gemm<256,128,4,false,2>(p_h, p_fw1T, p_ff1, 0, 0, NTOK, FFN, DD, DD, DD, FFN,
                                1,1, 0,0,0,0,0,0, 1.f, fb1, 0,0,0,0);

    // 13) out = x2 + ff1 @ fw2 + fb2  (fp32 out)
    run_gemm<256,128,4,false,3>(p_ff1, p_fw2T, out_x, 0, 0, NTOK, DD, FFN, FFN, FFN, DD,
                                1,1, 0,0,0,0,0,0, 1.f, fb2, p_x2, 0,0,0);
}